// round 1
// baseline (speedup 1.0000x reference)
#include <cuda_runtime.h>
#include <math.h>

// ---------------- problem constants ----------------
#define XDIM    1024
#define D_STATE 64
#define D_CONV  4
#define HEADDIM 128
#define D_INNER 2048
#define NHEADS  16
#define CONVDIM 2176              // D_INNER + 2*64
#define DPROJ   4240              // 2*2048 + 2*64 + 16
#define CHUNK   256
#define NBATCH  2
#define SEQLEN  4096
#define NCPB    16                // chunks per batch
#define NBC     32                // total chunks
#define R_TOT   8192              // total tokens

// ---------------- device scratch (no allocations allowed) ----------------
__device__ float g_ln  [(size_t)R_TOT * XDIM];
__device__ float g_Win [(size_t)DPROJ * XDIM];
__device__ float g_Wout[(size_t)XDIM * D_INNER];
__device__ float g_zx  [(size_t)R_TOT * DPROJ];
__device__ float g_xBC [(size_t)R_TOT * CONVDIM];
__device__ float g_dt  [(size_t)R_TOT * NHEADS];
__device__ float g_cum [(size_t)NBC * NHEADS * CHUNK];
__device__ float g_cdec[(size_t)NBC * NHEADS];
__device__ float g_S   [(size_t)NBC * CHUNK * CHUNK];
__device__ float g_y   [(size_t)R_TOT * D_INNER];
__device__ float g_st  [(size_t)NBC * NHEADS * HEADDIM * D_STATE];
__device__ float g_ps  [(size_t)NBC * NHEADS * HEADDIM * D_STATE];
__device__ float g_g   [(size_t)R_TOT * D_INNER];

// ---------------- helpers ----------------
__device__ __forceinline__ float blockReduceSum256(float v) {
    __shared__ float red[8];
    __shared__ float tot;
    int lane = threadIdx.x & 31, wid = threadIdx.x >> 5;
    #pragma unroll
    for (int o = 16; o; o >>= 1) v += __shfl_down_sync(0xffffffffu, v, o);
    if (lane == 0) red[wid] = v;
    __syncthreads();
    if (wid == 0) {
        float w = (lane < 8) ? red[lane] : 0.f;
        #pragma unroll
        for (int o = 4; o; o >>= 1) w += __shfl_down_sync(0xffffffffu, w, o);
        if (lane == 0) tot = w;
    }
    __syncthreads();
    return tot;
}

// ---------------- K1: l2-normalize weight rows (+ optional extra scale) ----------------
__global__ __launch_bounds__(256) void k_normw(const float* __restrict__ W,
                                               float* __restrict__ Wo,
                                               int K, float extra) {
    int r = blockIdx.x;
    const float* wr = W + (size_t)r * K;
    float s2 = 0.f;
    for (int i = threadIdx.x; i < K; i += 256) { float v = wr[i]; s2 += v * v; }
    float totv = blockReduceSum256(s2);
    float sc = extra / fmaxf(sqrtf(totv), 1e-6f);
    for (int i = threadIdx.x; i < K; i += 256) Wo[(size_t)r * K + i] = wr[i] * sc;
}

// ---------------- K2: layernorm over DIM ----------------
__global__ __launch_bounds__(256) void k_layernorm(const float* __restrict__ u,
                                                   const float* __restrict__ w,
                                                   const float* __restrict__ b) {
    int row = blockIdx.x;
    const float* ur = u + (size_t)row * XDIM;
    float v[4]; float s = 0.f, s2 = 0.f;
    #pragma unroll
    for (int k = 0; k < 4; k++) {
        v[k] = ur[threadIdx.x + 256 * k];
        s += v[k]; s2 += v[k] * v[k];
    }
    float sum = blockReduceSum256(s);
    float sumsq = blockReduceSum256(s2);
    float mu = sum * (1.f / XDIM);
    float var = sumsq * (1.f / XDIM) - mu * mu;
    float inv = rsqrtf(var + 1e-5f);
    #pragma unroll
    for (int k = 0; k < 4; k++) {
        int d = threadIdx.x + 256 * k;
        g_ln[(size_t)row * XDIM + d] = (v[k] - mu) * inv * w[d] + b[d];
    }
}

// ---------------- K3/K11: SGEMM NT: C[M,N] = A[M,K] * W[N,K]^T ----------------
__global__ __launch_bounds__(256) void sgemm_nt(const float* __restrict__ A,
                                                const float* __restrict__ W,
                                                float* __restrict__ C,
                                                int M, int N, int K) {
    const int BM = 128, BN = 128, BK = 16;
    __shared__ float As[BK][BM];
    __shared__ float Ws[BK][BN];
    int tid = threadIdx.x;
    int m0 = blockIdx.y * BM;
    int n0 = blockIdx.x * BN;
    int ty = tid >> 4, tx = tid & 15;
    float acc[8][8];
    #pragma unroll
    for (int i = 0; i < 8; i++)
        #pragma unroll
        for (int j = 0; j < 8; j++) acc[i][j] = 0.f;

    for (int k0 = 0; k0 < K; k0 += BK) {
        #pragma unroll
        for (int pass = 0; pass < 2; ++pass) {
            int r = (tid >> 2) + pass * 64;
            int c4 = (tid & 3) * 4;
            float4 av = make_float4(0.f, 0.f, 0.f, 0.f);
            int gm = m0 + r;
            if (gm < M) av = *(const float4*)(A + (size_t)gm * K + k0 + c4);
            As[c4 + 0][r] = av.x; As[c4 + 1][r] = av.y;
            As[c4 + 2][r] = av.z; As[c4 + 3][r] = av.w;
            float4 wv = make_float4(0.f, 0.f, 0.f, 0.f);
            int gn = n0 + r;
            if (gn < N) wv = *(const float4*)(W + (size_t)gn * K + k0 + c4);
            Ws[c4 + 0][r] = wv.x; Ws[c4 + 1][r] = wv.y;
            Ws[c4 + 2][r] = wv.z; Ws[c4 + 3][r] = wv.w;
        }
        __syncthreads();
        #pragma unroll
        for (int k = 0; k < BK; ++k) {
            float ar[8], br[8];
            float4 a0 = *(float4*)&As[k][ty * 8];
            float4 a1 = *(float4*)&As[k][ty * 8 + 4];
            ar[0]=a0.x; ar[1]=a0.y; ar[2]=a0.z; ar[3]=a0.w;
            ar[4]=a1.x; ar[5]=a1.y; ar[6]=a1.z; ar[7]=a1.w;
            float4 b0 = *(float4*)&Ws[k][tx * 8];
            float4 b1 = *(float4*)&Ws[k][tx * 8 + 4];
            br[0]=b0.x; br[1]=b0.y; br[2]=b0.z; br[3]=b0.w;
            br[4]=b1.x; br[5]=b1.y; br[6]=b1.z; br[7]=b1.w;
            #pragma unroll
            for (int i = 0; i < 8; i++)
                #pragma unroll
                for (int j = 0; j < 8; j++) acc[i][j] += ar[i] * br[j];
        }
        __syncthreads();
    }
    #pragma unroll
    for (int i = 0; i < 8; i++) {
        int gm = m0 + ty * 8 + i;
        if (gm >= M) continue;
        #pragma unroll
        for (int j = 0; j < 8; j += 4) {
            int gn = n0 + tx * 8 + j;
            if (gn < N) {
                float4 v = make_float4(acc[i][j], acc[i][j+1], acc[i][j+2], acc[i][j+3]);
                *(float4*)(C + (size_t)gm * N + gn) = v;
            }
        }
    }
}

// ---------------- K4: depthwise causal conv (4 taps) + bias + silu ----------------
__global__ __launch_bounds__(256) void k_conv(const float* __restrict__ cw,
                                              const float* __restrict__ cb) {
    int gi = blockIdx.x * 256 + threadIdx.x;
    if (gi >= R_TOT * CONVDIM) return;
    int ch = gi % CONVDIM;
    int row = gi / CONVDIM;
    int l = row & (SEQLEN - 1);
    float acc = cb[ch];
    #pragma unroll
    for (int d = 0; d < 4; d++) {
        int ll = l - 3 + d;
        if (ll >= 0)
            acc += cw[ch * 4 + d] * g_zx[(size_t)(row - 3 + d) * DPROJ + D_INNER + ch];
    }
    g_xBC[(size_t)row * CONVDIM + ch] = acc / (1.f + __expf(-acc));
}

// ---------------- K5: dt softplus + per-chunk cumulative dA scan ----------------
__global__ __launch_bounds__(256) void k_dtcum(const float* __restrict__ dt_bias,
                                               const float* __restrict__ A_log) {
    int bch = blockIdx.x;           // bc*16 + h
    int h = bch & 15, bc = bch >> 4;
    int t = threadIdx.x;
    int row = bc * CHUNK + t;
    float x = g_zx[(size_t)row * DPROJ + (D_INNER + CONVDIM) + h] + dt_bias[h];
    float dtv = (x > 20.f) ? x : log1pf(expf(x));
    g_dt[(size_t)row * NHEADS + h] = dtv;
    float dA = dtv * (-expf(A_log[h]));
    __shared__ float s[256];
    s[t] = dA;
    __syncthreads();
    #pragma unroll
    for (int off = 1; off < 256; off <<= 1) {
        float pv = (t >= off) ? s[t - off] : 0.f;
        __syncthreads();
        s[t] += pv;
        __syncthreads();
    }
    g_cum[(size_t)bch * CHUNK + t] = s[t];
    if (t == 255) g_cdec[bch] = __expf(s[255]);
}

// ---------------- K6a: scores S = C @ B^T per chunk (256x256, K=64) ----------------
__global__ __launch_bounds__(256) void k_scores() {
    if (blockIdx.z > blockIdx.y) return;  // upper triangle tiles never read
    int bc = blockIdx.x, i0 = blockIdx.y * 64, j0 = blockIdx.z * 64;
    __shared__ float Ct[64][65];
    __shared__ float Bt[64][65];
    int row0 = bc * CHUNK;
    for (int idx = threadIdx.x; idx < 4096; idx += 256) {
        int n = idx & 63, r = idx >> 6;
        Ct[n][r] = g_xBC[(size_t)(row0 + i0 + r) * CONVDIM + D_INNER + 64 + n];
        Bt[n][r] = g_xBC[(size_t)(row0 + j0 + r) * CONVDIM + D_INNER + n];
    }
    __syncthreads();
    int ty = threadIdx.x >> 4, tx = threadIdx.x & 15;
    float acc[4][4];
    #pragma unroll
    for (int i = 0; i < 4; i++)
        #pragma unroll
        for (int j = 0; j < 4; j++) acc[i][j] = 0.f;
    #pragma unroll 4
    for (int n = 0; n < 64; n++) {
        float a[4], b[4];
        #pragma unroll
        for (int i = 0; i < 4; i++) a[i] = Ct[n][ty * 4 + i];
        #pragma unroll
        for (int j = 0; j < 4; j++) b[j] = Bt[n][tx * 4 + j];
        #pragma unroll
        for (int i = 0; i < 4; i++)
            #pragma unroll
            for (int j = 0; j < 4; j++) acc[i][j] += a[i] * b[j];
    }
    #pragma unroll
    for (int i = 0; i < 4; i++) {
        float4 v = make_float4(acc[i][0], acc[i][1], acc[i][2], acc[i][3]);
        *(float4*)(g_S + ((size_t)bc * CHUNK + i0 + ty * 4 + i) * CHUNK + j0 + tx * 4) = v;
    }
}

// ---------------- K6b: y_intra = att @ x per (chunk, head) ----------------
__global__ __launch_bounds__(256) void k_yintra() {
    int bc = blockIdx.x, h = blockIdx.y, i0 = blockIdx.z * 64;
    __shared__ float4 xs4[16][32];
    __shared__ float att[64][17];
    __shared__ float cum_i[64], cum_j[16], dtj[16];
    int row0 = bc * CHUNK;
    int cb = (bc * NHEADS + h) * CHUNK;
    int tid = threadIdx.x;
    if (tid < 64) cum_i[tid] = g_cum[cb + i0 + tid];
    int il = tid >> 2, fq = tid & 3;
    int i = i0 + il;
    float4 acc[8];
    #pragma unroll
    for (int k = 0; k < 8; k++) acc[k] = make_float4(0.f, 0.f, 0.f, 0.f);
    int nt = (i0 >> 4) + 4;
    for (int jt = 0; jt < nt; jt++) {
        int j0 = jt * 16;
        __syncthreads();
        #pragma unroll
        for (int p = 0; p < 2; p++) {
            int idx = tid + p * 256;
            int jr = idx >> 5, c = idx & 31;
            xs4[jr][c] = ((const float4*)(g_xBC + (size_t)(row0 + j0 + jr) * CONVDIM + h * HEADDIM))[c];
        }
        if (tid < 16) {
            cum_j[tid] = g_cum[cb + j0 + tid];
            dtj[tid]   = g_dt[(size_t)(row0 + j0 + tid) * NHEADS + h];
        }
        __syncthreads();
        #pragma unroll
        for (int q = 0; q < 4; q++) {
            int idx = tid + q * 256;
            int ii = idx >> 4, jj = idx & 15;
            int gi = i0 + ii, gj = j0 + jj;
            float a = 0.f;
            if (gj <= gi)
                a = g_S[((size_t)bc * CHUNK + gi) * CHUNK + gj] *
                    __expf(cum_i[ii] - cum_j[jj]) * dtj[jj];
            att[ii][jj] = a;
        }
        __syncthreads();
        #pragma unroll
        for (int j = 0; j < 16; j++) {
            float a = att[il][j];
            #pragma unroll
            for (int k = 0; k < 8; k++) {
                float4 xv = xs4[j][fq + 4 * k];
                acc[k].x += a * xv.x; acc[k].y += a * xv.y;
                acc[k].z += a * xv.z; acc[k].w += a * xv.w;
            }
        }
    }
    float4* yp = (float4*)(g_y + (size_t)(row0 + i) * D_INNER + h * HEADDIM);
    #pragma unroll
    for (int k = 0; k < 8; k++) yp[fq + 4 * k] = acc[k];
}

// ---------------- K7: per-chunk states = sum_t B ⊗ (dt*decay2end*x) ----------------
__global__ __launch_bounds__(256) void k_states() {
    int bc = blockIdx.x, h = blockIdx.y;
    __shared__ __align__(16) float xs[16][128];
    __shared__ float4 Bs4[16][16];
    __shared__ float wsh[16];
    int row0 = bc * CHUNK;
    int cb = (bc * NHEADS + h) * CHUNK;
    int tid = threadIdx.x;
    float cum_last = g_cum[cb + 255];
    int p = tid >> 1, nq = tid & 1;
    float4 acc[8];
    #pragma unroll
    for (int k = 0; k < 8; k++) acc[k] = make_float4(0.f, 0.f, 0.f, 0.f);
    for (int tt = 0; tt < 16; tt++) {
        int t0 = tt * 16;
        __syncthreads();
        #pragma unroll
        for (int ps = 0; ps < 2; ps++) {
            int idx = tid + ps * 256;
            int jr = idx >> 5, c = idx & 31;
            ((float4*)xs[jr])[c] = ((const float4*)(g_xBC + (size_t)(row0 + t0 + jr) * CONVDIM + h * HEADDIM))[c];
        }
        {
            int jr = tid >> 4, c = tid & 15;
            Bs4[jr][c] = ((const float4*)(g_xBC + (size_t)(row0 + t0 + jr) * CONVDIM + D_INNER))[c];
        }
        if (tid < 16) {
            int t = t0 + tid;
            wsh[tid] = g_dt[(size_t)(row0 + t) * NHEADS + h] * __expf(cum_last - g_cum[cb + t]);
        }
        __syncthreads();
        #pragma unroll
        for (int t = 0; t < 16; t++) {
            float xv = xs[t][p] * wsh[t];
            #pragma unroll
            for (int k = 0; k < 8; k++) {
                float4 b = Bs4[t][nq + 2 * k];
                acc[k].x += xv * b.x; acc[k].y += xv * b.y;
                acc[k].z += xv * b.z; acc[k].w += xv * b.w;
            }
        }
    }
    float4* sp = (float4*)(g_st + ((size_t)(bc * NHEADS + h) * HEADDIM + p) * D_STATE);
    #pragma unroll
    for (int k = 0; k < 8; k++) sp[nq + 2 * k] = acc[k];
}

// ---------------- K8: serial inter-chunk scan ----------------
__global__ __launch_bounds__(256) void k_scan() {
    int b = blockIdx.x, h = blockIdx.y;
    int tid = threadIdx.x;
    float carry[32];
    #pragma unroll
    for (int k = 0; k < 32; k++) carry[k] = 0.f;
    for (int c = 0; c < NCPB; c++) {
        int bch = (b * NCPB + c) * NHEADS + h;
        float dec = g_cdec[bch];
        size_t base = (size_t)bch * HEADDIM * D_STATE;
        #pragma unroll
        for (int k = 0; k < 32; k++) {
            int e = tid + 256 * k;
            g_ps[base + e] = carry[k];
            carry[k] = carry[k] * dec + g_st[base + e];
        }
    }
}

// ---------------- K9: y_inter += (C*exp(cum)) @ prev_states^T ----------------
__global__ __launch_bounds__(256) void k_yinter() {
    int bch = blockIdx.x;
    int h = bch & 15, bc = bch >> 4;
    int i0 = blockIdx.y * 64, p0 = blockIdx.z * 64;
    __shared__ float Ct[64][65];
    __shared__ float Pt[64][65];
    __shared__ float es[64];
    int row0 = bc * CHUNK;
    int cb = bch * CHUNK;
    size_t psb = (size_t)bch * HEADDIM * D_STATE;
    for (int idx = threadIdx.x; idx < 4096; idx += 256) {
        int n = idx & 63, r = idx >> 6;
        Ct[n][r] = g_xBC[(size_t)(row0 + i0 + r) * CONVDIM + D_INNER + D_STATE + n];
        Pt[n][r] = g_ps[psb + (size_t)(p0 + r) * D_STATE + n];
    }
    if (threadIdx.x < 64) es[threadIdx.x] = __expf(g_cum[cb + i0 + threadIdx.x]);
    __syncthreads();
    int ty = threadIdx.x >> 4, tx = threadIdx.x & 15;
    float acc[4][4];
    #pragma unroll
    for (int i = 0; i < 4; i++)
        #pragma unroll
        for (int j = 0; j < 4; j++) acc[i][j] = 0.f;
    #pragma unroll 4
    for (int n = 0; n < 64; n++) {
        float a[4], b[4];
        #pragma unroll
        for (int i = 0; i < 4; i++) a[i] = Ct[n][ty * 4 + i];
        #pragma unroll
        for (int j = 0; j < 4; j++) b[j] = Pt[n][tx * 4 + j];
        #pragma unroll
        for (int i = 0; i < 4; i++)
            #pragma unroll
            for (int j = 0; j < 4; j++) acc[i][j] += a[i] * b[j];
    }
    #pragma unroll
    for (int i = 0; i < 4; i++) {
        int gi = i0 + ty * 4 + i;
        float e = es[ty * 4 + i];
        float4* yp = (float4*)(g_y + (size_t)(row0 + gi) * D_INNER + h * HEADDIM + p0 + tx * 4);
        float4 v = *yp;
        v.x += e * acc[i][0]; v.y += e * acc[i][1];
        v.z += e * acc[i][2]; v.w += e * acc[i][3];
        *yp = v;
    }
}

// ---------------- K10: y += D*x, gate with silu(z), RMS norm ----------------
__global__ __launch_bounds__(256) void k_gate(const float* __restrict__ Dp,
                                              const float* __restrict__ rms_w) {
    int row = blockIdx.x;
    int tid = threadIdx.x;
    float gg[8];
    float s2 = 0.f;
    #pragma unroll
    for (int k = 0; k < 8; k++) {
        int d = tid + 256 * k;
        float xv = g_xBC[(size_t)row * CONVDIM + d];
        float v = g_y[(size_t)row * D_INNER + d] + Dp[d >> 7] * xv;
        float z = g_zx[(size_t)row * DPROJ + d];
        float sil = z / (1.f + __expf(-z));
        float g = v * sil;
        gg[k] = g;
        s2 += g * g;
    }
    float tot = blockReduceSum256(s2);
    float sc = rsqrtf(tot * (1.f / D_INNER) + 1e-5f);
    #pragma unroll
    for (int k = 0; k < 8; k++) {
        int d = tid + 256 * k;
        g_g[(size_t)row * D_INNER + d] = gg[k] * sc * rms_w[d];
    }
}

// ---------------- host launcher ----------------
extern "C" void kernel_launch(void* const* d_in, const int* in_sizes, int n_in,
                              void* d_out, int out_size) {
    const float* u          = (const float*)d_in[0];
    const float* in_proj_w  = (const float*)d_in[1];
    const float* conv_w     = (const float*)d_in[2];
    const float* conv_b     = (const float*)d_in[3];
    const float* dt_bias    = (const float*)d_in[4];
    const float* A_log      = (const float*)d_in[5];
    const float* Dp         = (const float*)d_in[6];
    const float* xnw        = (const float*)d_in[7];
    const float* xnb        = (const float*)d_in[8];
    const float* rms_w      = (const float*)d_in[9];
    const float* out_proj_w = (const float*)d_in[10];
    float* out = (float*)d_out;

    float *pWin, *pWout, *pLn, *pZx, *pG;
    cudaGetSymbolAddress((void**)&pWin,  g_Win);
    cudaGetSymbolAddress((void**)&pWout, g_Wout);
    cudaGetSymbolAddress((void**)&pLn,   g_ln);
    cudaGetSymbolAddress((void**)&pZx,   g_zx);
    cudaGetSymbolAddress((void**)&pG,    g_g);

    // weights: l2norm rows; fold DIM^-0.5 into in_proj
    k_normw<<<DPROJ, 256>>>(in_proj_w, pWin, XDIM, 0.03125f);
    k_normw<<<XDIM, 256>>>(out_proj_w, pWout, D_INNER, 1.0f);

    // layernorm input
    k_layernorm<<<R_TOT, 256>>>(u, xnw, xnb);

    // in_proj GEMM: (8192 x 1024) @ (4240 x 1024)^T
    sgemm_nt<<<dim3((DPROJ + 127) / 128, R_TOT / 128), 256>>>(pLn, pWin, pZx, R_TOT, DPROJ, XDIM);

    // depthwise conv + silu
    k_conv<<<(R_TOT * CONVDIM + 255) / 256, 256>>>(conv_w, conv_b);

    // dt softplus + cumulative decay per chunk/head
    k_dtcum<<<NBC * NHEADS, 256>>>(dt_bias, A_log);

    // SSD
    k_scores<<<dim3(NBC, 4, 4), 256>>>();
    k_yintra<<<dim3(NBC, NHEADS, 4), 256>>>();
    k_states<<<dim3(NBC, NHEADS), 256>>>();
    k_scan<<<dim3(NBATCH, NHEADS), 256>>>();
    k_yinter<<<dim3(NBC * NHEADS, 4, 2), 256>>>();

    // gate + RMS norm
    k_gate<<<R_TOT, 256>>>(Dp, rms_w);

    // out_proj GEMM: (8192 x 2048) @ (1024 x 2048)^T
    sgemm_nt<<<dim3(XDIM / 128, R_TOT / 128), 256>>>(pG, pWout, out, R_TOT, XDIM, D_INNER);
}

// round 3
// speedup vs baseline: 2.4477x; 2.4477x over previous
#include <cuda_runtime.h>
#include <math.h>
#include <stdint.h>

// ---------------- problem constants ----------------
#define XDIM    1024
#define D_STATE 64
#define HEADDIM 128
#define D_INNER 2048
#define NHEADS  16
#define CONVDIM 2176              // D_INNER + 2*64
#define DPROJ   4240              // 2*2048 + 2*64 + 16
#define DPROJP  4352              // padded to 128-multiple for GEMM tiles
#define CHUNK   256
#define NBATCH  2
#define SEQLEN  4096
#define NCPB    16
#define NBC     32
#define R_TOT   8192

// ---------------- device scratch ----------------
__device__ float g_ln  [(size_t)R_TOT * XDIM];
__device__ float g_Win [(size_t)DPROJP * XDIM];      // rows >= DPROJ stay zero (.bss)
__device__ float g_Wout[(size_t)XDIM * D_INNER];
__device__ float g_zx  [(size_t)R_TOT * DPROJP];
__device__ float g_xBC [(size_t)R_TOT * CONVDIM];
__device__ float g_dt  [(size_t)R_TOT * NHEADS];
__device__ float g_cum [(size_t)NBC * NHEADS * CHUNK];
__device__ float g_cdec[(size_t)NBC * NHEADS];
__device__ float g_S   [(size_t)NBC * CHUNK * CHUNK];
__device__ float g_y   [(size_t)R_TOT * D_INNER];
__device__ float g_st  [(size_t)NBC * NHEADS * HEADDIM * D_STATE];
__device__ float g_ps  [(size_t)NBC * NHEADS * HEADDIM * D_STATE];
__device__ float g_g   [(size_t)R_TOT * D_INNER];

// ---------------- PTX helpers (baseline PTX only, no sm_103a-specific ops) ----------------
__device__ __forceinline__ uint32_t smem_u32(const void* p) {
    uint32_t a;
    asm("{ .reg .u64 t; cvta.to.shared.u64 t, %1; cvt.u32.u64 %0, t; }" : "=r"(a) : "l"(p));
    return a;
}
__device__ __forceinline__ float to_tf32(float x) {
    uint32_t r;
    asm("cvt.rna.tf32.f32 %0, %1;" : "=r"(r) : "f"(x));
    return __uint_as_float(r);
}
#define CP_ASYNC16(s, g) \
    asm volatile("cp.async.cg.shared.global [%0], [%1], 16;" :: "r"(s), "l"(g))
#define CP_COMMIT() asm volatile("cp.async.commit_group;" ::: "memory")
#define CP_WAIT(n)  asm volatile("cp.async.wait_group %0;" :: "n"(n) : "memory")

__device__ __forceinline__ void ldsm_x4(uint32_t* r, uint32_t addr) {
    asm volatile("ldmatrix.sync.aligned.m8n8.x4.shared.b16 {%0,%1,%2,%3}, [%4];"
        : "=r"(r[0]), "=r"(r[1]), "=r"(r[2]), "=r"(r[3]) : "r"(addr));
}
__device__ __forceinline__ void mma_tf32(float* d, const uint32_t* a, const uint32_t* b) {
    asm volatile("mma.sync.aligned.m16n8k8.row.col.f32.tf32.tf32.f32 "
        "{%0,%1,%2,%3},{%4,%5,%6,%7},{%8,%9},{%0,%1,%2,%3};"
        : "+f"(d[0]), "+f"(d[1]), "+f"(d[2]), "+f"(d[3])
        : "r"(a[0]), "r"(a[1]), "r"(a[2]), "r"(a[3]), "r"(b[0]), "r"(b[1]));
}

// ================= tensor-core tf32 GEMM: C[M,N] = A[M,K] * B[N,K]^T =================
// BM=128, BN=128, BK=32, 3-stage cp.async pipeline, 8 warps (warp tile 64x32).
#define GBM 128
#define GBN 128
#define GBK 32
#define GSTG 3
#define TB_A (GBM * GBK * 4)            // 16384 bytes per A tile (128 rows x 128B)
#define TB_B (GBN * GBK * 4)
#define STAGE_B (TB_A + TB_B)           // 32768
#define GEMM_SMEM (GSTG * STAGE_B)      // 98304

// XOR swizzle within a 128B row: col ^= (row%8)<<4 (on byte offsets, 16B granules)
__device__ __forceinline__ void gemm_load_tile(const float* Ab, const float* Bb,
                                               int K, int t, uint32_t sb, int tid) {
    const float* Ap = Ab + (size_t)t * GBK;
    const float* Bp = Bb + (size_t)t * GBK;
    #pragma unroll
    for (int j = 0; j < 4; j++) {
        int c = tid + 256 * j;
        int row = c >> 3;
        uint32_t cc = (uint32_t)(c & 7) * 16;
        uint32_t off = (uint32_t)row * 128 + (cc ^ (((uint32_t)row & 7) << 4));
        CP_ASYNC16(sb + off, Ap + (size_t)row * K + (cc >> 2));
    }
    uint32_t sb2 = sb + TB_A;
    #pragma unroll
    for (int j = 0; j < 4; j++) {
        int c = tid + 256 * j;
        int row = c >> 3;
        uint32_t cc = (uint32_t)(c & 7) * 16;
        uint32_t off = (uint32_t)row * 128 + (cc ^ (((uint32_t)row & 7) << 4));
        CP_ASYNC16(sb2 + off, Bp + (size_t)row * K + (cc >> 2));
    }
    CP_COMMIT();
}

__global__ __launch_bounds__(256, 1) void gemm_tc(const float* __restrict__ A,
                                                  const float* __restrict__ B,
                                                  float* __restrict__ C,
                                                  int K, int ldc) {
    extern __shared__ char sm[];
    uint32_t sbase = smem_u32(sm);
    int tid = threadIdx.x, lane = tid & 31, wid = tid >> 5;
    int wm = (wid & 1) * 64;            // warp m offset in tile
    int wn = (wid >> 1) * 32;           // warp n offset
    int m0 = blockIdx.y * GBM;
    int n0 = blockIdx.x * GBN;
    const float* Ab = A + (size_t)m0 * K;
    const float* Bb = B + (size_t)n0 * K;

    // per-lane ldmatrix row/col-half components
    int a_row = wm + (lane & 15);
    uint32_t a_kb = (uint32_t)(lane >> 4) * 16;           // k-half byte offset
    int b_row = wn + (lane & 7) + ((lane & 16) ? 8 : 0);
    uint32_t b_kb = (lane & 8) ? 16u : 0u;

    float acc[4][4][4];
    #pragma unroll
    for (int mt = 0; mt < 4; mt++)
        #pragma unroll
        for (int nt = 0; nt < 4; nt++)
            #pragma unroll
            for (int q = 0; q < 4; q++) acc[mt][nt][q] = 0.f;

    int T = K / GBK;
    gemm_load_tile(Ab, Bb, K, 0, sbase, tid);
    gemm_load_tile(Ab, Bb, K, 1, sbase + STAGE_B, tid);

    for (int t = 0; t < T; t++) {
        CP_WAIT(1);
        __syncthreads();
        if (t + 2 < T)
            gemm_load_tile(Ab, Bb, K, t + 2, sbase + ((t + 2) % GSTG) * STAGE_B, tid);
        uint32_t sa = sbase + (t % GSTG) * STAGE_B;
        uint32_t sb = sa + TB_A;

        #pragma unroll
        for (int ks = 0; ks < 4; ks++) {
            uint32_t afr[4][4];
            #pragma unroll
            for (int mt = 0; mt < 4; mt++) {
                uint32_t row = (uint32_t)(a_row + mt * 16);
                uint32_t c = (uint32_t)ks * 32 + a_kb;
                ldsm_x4(afr[mt], sa + row * 128 + (c ^ ((row & 7) << 4)));
            }
            uint32_t bfr[2][4];
            #pragma unroll
            for (int nh = 0; nh < 2; nh++) {
                uint32_t row = (uint32_t)(b_row + nh * 16);
                uint32_t c = (uint32_t)ks * 32 + b_kb;
                ldsm_x4(bfr[nh], sb + row * 128 + (c ^ ((row & 7) << 4)));
            }
            #pragma unroll
            for (int mt = 0; mt < 4; mt++)
                #pragma unroll
                for (int nt = 0; nt < 4; nt++)
                    mma_tf32(acc[mt][nt], afr[mt], &bfr[nt >> 1][(nt & 1) * 2]);
        }
    }

    // epilogue: c0,c1 at (g, 2*tg), c2,c3 at (g+8, 2*tg)
    int g = lane >> 2, tg = lane & 3;
    #pragma unroll
    for (int mt = 0; mt < 4; mt++) {
        int rowa = m0 + wm + mt * 16 + g;
        #pragma unroll
        for (int nt = 0; nt < 4; nt++) {
            int col = n0 + wn + nt * 8 + tg * 2;
            *(float2*)(C + (size_t)rowa * ldc + col) =
                make_float2(acc[mt][nt][0], acc[mt][nt][1]);
            *(float2*)(C + (size_t)(rowa + 8) * ldc + col) =
                make_float2(acc[mt][nt][2], acc[mt][nt][3]);
        }
    }
}

// ---------------- reductions ----------------
__device__ __forceinline__ float blockReduceSum256(float v) {
    __shared__ float red[8];
    __shared__ float tot;
    int lane = threadIdx.x & 31, wid = threadIdx.x >> 5;
    #pragma unroll
    for (int o = 16; o; o >>= 1) v += __shfl_down_sync(0xffffffffu, v, o);
    if (lane == 0) red[wid] = v;
    __syncthreads();
    if (wid == 0) {
        float w = (lane < 8) ? red[lane] : 0.f;
        #pragma unroll
        for (int o = 4; o; o >>= 1) w += __shfl_down_sync(0xffffffffu, w, o);
        if (lane == 0) tot = w;
    }
    __syncthreads();
    return tot;
}

// ---------------- K1: l2-normalize weight rows (tf32-rounded output) ----------------
__global__ __launch_bounds__(256) void k_normw(const float* __restrict__ W,
                                               float* __restrict__ Wo, int K, float extra) {
    int r = blockIdx.x;
    const float* wr = W + (size_t)r * K;
    float s2 = 0.f;
    for (int i = threadIdx.x; i < K; i += 256) { float v = wr[i]; s2 += v * v; }
    float totv = blockReduceSum256(s2);
    float sc = extra / fmaxf(sqrtf(totv), 1e-6f);
    for (int i = threadIdx.x; i < K; i += 256) Wo[(size_t)r * K + i] = to_tf32(wr[i] * sc);
}

// ---------------- K2: layernorm (tf32-rounded output) ----------------
__global__ __launch_bounds__(256) void k_layernorm(const float* __restrict__ u,
                                                   const float* __restrict__ w,
                                                   const float* __restrict__ b) {
    int row = blockIdx.x;
    const float* ur = u + (size_t)row * XDIM;
    float v[4]; float s = 0.f, s2 = 0.f;
    #pragma unroll
    for (int k = 0; k < 4; k++) {
        v[k] = ur[threadIdx.x + 256 * k];
        s += v[k]; s2 += v[k] * v[k];
    }
    float sum = blockReduceSum256(s);
    float sumsq = blockReduceSum256(s2);
    float mu = sum * (1.f / XDIM);
    float var = sumsq * (1.f / XDIM) - mu * mu;
    float inv = rsqrtf(var + 1e-5f);
    #pragma unroll
    for (int k = 0; k < 4; k++) {
        int d = threadIdx.x + 256 * k;
        g_ln[(size_t)row * XDIM + d] = to_tf32((v[k] - mu) * inv * w[d] + b[d]);
    }
}

// ---------------- K4: depthwise causal conv + bias + silu ----------------
__global__ __launch_bounds__(256) void k_conv(const float* __restrict__ cw,
                                              const float* __restrict__ cb) {
    int gi = blockIdx.x * 256 + threadIdx.x;
    if (gi >= R_TOT * CONVDIM) return;
    int ch = gi % CONVDIM;
    int row = gi / CONVDIM;
    int l = row & (SEQLEN - 1);
    float acc = cb[ch];
    #pragma unroll
    for (int d = 0; d < 4; d++) {
        int ll = l - 3 + d;
        if (ll >= 0)
            acc += cw[ch * 4 + d] * g_zx[(size_t)(row - 3 + d) * DPROJP + D_INNER + ch];
    }
    g_xBC[(size_t)row * CONVDIM + ch] = acc / (1.f + __expf(-acc));
}

// ---------------- K5: dt softplus + per-chunk cumulative dA ----------------
__global__ __launch_bounds__(256) void k_dtcum(const float* __restrict__ dt_bias,
                                               const float* __restrict__ A_log) {
    int bch = blockIdx.x;
    int h = bch & 15, bc = bch >> 4;
    int t = threadIdx.x;
    int row = bc * CHUNK + t;
    float x = g_zx[(size_t)row * DPROJP + (D_INNER + CONVDIM) + h] + dt_bias[h];
    float dtv = (x > 20.f) ? x : log1pf(expf(x));
    g_dt[(size_t)row * NHEADS + h] = dtv;
    float dA = dtv * (-expf(A_log[h]));
    __shared__ float s[256];
    s[t] = dA;
    __syncthreads();
    #pragma unroll
    for (int off = 1; off < 256; off <<= 1) {
        float pv = (t >= off) ? s[t - off] : 0.f;
        __syncthreads();
        s[t] += pv;
        __syncthreads();
    }
    g_cum[(size_t)bch * CHUNK + t] = s[t];
    if (t == 255) g_cdec[bch] = __expf(s[255]);
}

// ---------------- K6a: scores S = C @ B^T ----------------
__global__ __launch_bounds__(256) void k_scores() {
    if (blockIdx.z > blockIdx.y) return;
    int bc = blockIdx.x, i0 = blockIdx.y * 64, j0 = blockIdx.z * 64;
    __shared__ float Ct[64][65];
    __shared__ float Bt[64][65];
    int row0 = bc * CHUNK;
    for (int idx = threadIdx.x; idx < 4096; idx += 256) {
        int n = idx & 63, r = idx >> 6;
        Ct[n][r] = g_xBC[(size_t)(row0 + i0 + r) * CONVDIM + D_INNER + 64 + n];
        Bt[n][r] = g_xBC[(size_t)(row0 + j0 + r) * CONVDIM + D_INNER + n];
    }
    __syncthreads();
    int ty = threadIdx.x >> 4, tx = threadIdx.x & 15;
    float acc[4][4];
    #pragma unroll
    for (int i = 0; i < 4; i++)
        #pragma unroll
        for (int j = 0; j < 4; j++) acc[i][j] = 0.f;
    #pragma unroll 4
    for (int n = 0; n < 64; n++) {
        float a[4], b[4];
        #pragma unroll
        for (int i = 0; i < 4; i++) a[i] = Ct[n][ty * 4 + i];
        #pragma unroll
        for (int j = 0; j < 4; j++) b[j] = Bt[n][tx * 4 + j];
        #pragma unroll
        for (int i = 0; i < 4; i++)
            #pragma unroll
            for (int j = 0; j < 4; j++) acc[i][j] += a[i] * b[j];
    }
    #pragma unroll
    for (int i = 0; i < 4; i++)
        *(float4*)(g_S + ((size_t)bc * CHUNK + i0 + ty * 4 + i) * CHUNK + j0 + tx * 4) =
            make_float4(acc[i][0], acc[i][1], acc[i][2], acc[i][3]);
}

// ---------------- K6b: y_intra = att @ x ----------------
__global__ __launch_bounds__(256) void k_yintra() {
    int bc = blockIdx.x, h = blockIdx.y, i0 = blockIdx.z * 64;
    __shared__ float4 xs4[16][32];
    __shared__ float att[64][17];
    __shared__ float cum_i[64], cum_j[16], dtj[16];
    int row0 = bc * CHUNK;
    int cb = (bc * NHEADS + h) * CHUNK;
    int tid = threadIdx.x;
    if (tid < 64) cum_i[tid] = g_cum[cb + i0 + tid];
    int il = tid >> 2, fq = tid & 3;
    int i = i0 + il;
    float4 acc[8];
    #pragma unroll
    for (int k = 0; k < 8; k++) acc[k] = make_float4(0.f, 0.f, 0.f, 0.f);
    int nt = (i0 >> 4) + 4;
    for (int jt = 0; jt < nt; jt++) {
        int j0 = jt * 16;
        __syncthreads();
        #pragma unroll
        for (int p = 0; p < 2; p++) {
            int idx = tid + p * 256;
            int jr = idx >> 5, c = idx & 31;
            xs4[jr][c] = ((const float4*)(g_xBC + (size_t)(row0 + j0 + jr) * CONVDIM + h * HEADDIM))[c];
        }
        if (tid < 16) {
            cum_j[tid] = g_cum[cb + j0 + tid];
            dtj[tid]   = g_dt[(size_t)(row0 + j0 + tid) * NHEADS + h];
        }
        __syncthreads();
        #pragma unroll
        for (int q = 0; q < 4; q++) {
            int idx = tid + q * 256;
            int ii = idx >> 4, jj = idx & 15;
            int gi = i0 + ii, gj = j0 + jj;
            float a = 0.f;
            if (gj <= gi)
                a = g_S[((size_t)bc * CHUNK + gi) * CHUNK + gj] *
                    __expf(cum_i[ii] - cum_j[jj]) * dtj[jj];
            att[ii][jj] = a;
        }
        __syncthreads();
        #pragma unroll
        for (int j = 0; j < 16; j++) {
            float a = att[il][j];
            #pragma unroll
            for (int k = 0; k < 8; k++) {
                float4 xv = xs4[j][fq + 4 * k];
                acc[k].x += a * xv.x; acc[k].y += a * xv.y;
                acc[k].z += a * xv.z; acc[k].w += a * xv.w;
            }
        }
    }
    float4* yp = (float4*)(g_y + (size_t)(row0 + i) * D_INNER + h * HEADDIM);
    #pragma unroll
    for (int k = 0; k < 8; k++) yp[fq + 4 * k] = acc[k];
}

// ---------------- K7: per-chunk states ----------------
__global__ __launch_bounds__(256) void k_states() {
    int bc = blockIdx.x, h = blockIdx.y;
    __shared__ __align__(16) float xs[16][128];
    __shared__ float4 Bs4[16][16];
    __shared__ float wsh[16];
    int row0 = bc * CHUNK;
    int cb = (bc * NHEADS + h) * CHUNK;
    int tid = threadIdx.x;
    float cum_last = g_cum[cb + 255];
    int p = tid >> 1, nq = tid & 1;
    float4 acc[8];
    #pragma unroll
    for (int k = 0; k < 8; k++) acc[k] = make_float4(0.f, 0.f, 0.f, 0.f);
    for (int tt = 0; tt < 16; tt++) {
        int t0 = tt * 16;
        __syncthreads();
        #pragma unroll
        for (int ps = 0; ps < 2; ps++) {
            int idx = tid + ps * 256;
            int jr = idx >> 5, c = idx & 31;
            ((float4*)xs[jr])[c] = ((const float4*)(g_xBC + (size_t)(row0 + t0 + jr) * CONVDIM + h * HEADDIM))[c];
        }
        {
            int jr = tid >> 4, c = tid & 15;
            Bs4[jr][c] = ((const float4*)(g_xBC + (size_t)(row0 + t0 + jr) * CONVDIM + D_INNER))[c];
        }
        if (tid < 16) {
            int t = t0 + tid;
            wsh[tid] = g_dt[(size_t)(row0 + t) * NHEADS + h] * __expf(cum_last - g_cum[cb + t]);
        }
        __syncthreads();
        #pragma unroll
        for (int t = 0; t < 16; t++) {
            float xv = xs[t][p] * wsh[t];
            #pragma unroll
            for (int k = 0; k < 8; k++) {
                float4 b = Bs4[t][nq + 2 * k];
                acc[k].x += xv * b.x; acc[k].y += xv * b.y;
                acc[k].z += xv * b.z; acc[k].w += xv * b.w;
            }
        }
    }
    float4* sp = (float4*)(g_st + ((size_t)(bc * NHEADS + h) * HEADDIM + p) * D_STATE);
    #pragma unroll
    for (int k = 0; k < 8; k++) sp[nq + 2 * k] = acc[k];
}

// ---------------- K8: serial inter-chunk scan ----------------
__global__ __launch_bounds__(256) void k_scan() {
    int b = blockIdx.x, h = blockIdx.y;
    int tid = threadIdx.x;
    float carry[32];
    #pragma unroll
    for (int k = 0; k < 32; k++) carry[k] = 0.f;
    for (int c = 0; c < NCPB; c++) {
        int bch = (b * NCPB + c) * NHEADS + h;
        float dec = g_cdec[bch];
        size_t base = (size_t)bch * HEADDIM * D_STATE;
        #pragma unroll
        for (int k = 0; k < 32; k++) {
            int e = tid + 256 * k;
            g_ps[base + e] = carry[k];
            carry[k] = carry[k] * dec + g_st[base + e];
        }
    }
}

// ---------------- K9: y_inter += (C*exp(cum)) @ prev_states^T ----------------
__global__ __launch_bounds__(256) void k_yinter() {
    int bch = blockIdx.x;
    int h = bch & 15, bc = bch >> 4;
    int i0 = blockIdx.y * 64, p0 = blockIdx.z * 64;
    __shared__ float Ct[64][65];
    __shared__ float Pt[64][65];
    __shared__ float es[64];
    int row0 = bc * CHUNK;
    int cb = bch * CHUNK;
    size_t psb = (size_t)bch * HEADDIM * D_STATE;
    for (int idx = threadIdx.x; idx < 4096; idx += 256) {
        int n = idx & 63, r = idx >> 6;
        Ct[n][r] = g_xBC[(size_t)(row0 + i0 + r) * CONVDIM + D_INNER + D_STATE + n];
        Pt[n][r] = g_ps[psb + (size_t)(p0 + r) * D_STATE + n];
    }
    if (threadIdx.x < 64) es[threadIdx.x] = __expf(g_cum[cb + i0 + threadIdx.x]);
    __syncthreads();
    int ty = threadIdx.x >> 4, tx = threadIdx.x & 15;
    float acc[4][4];
    #pragma unroll
    for (int i = 0; i < 4; i++)
        #pragma unroll
        for (int j = 0; j < 4; j++) acc[i][j] = 0.f;
    #pragma unroll 4
    for (int n = 0; n < 64; n++) {
        float a[4], b[4];
        #pragma unroll
        for (int i = 0; i < 4; i++) a[i] = Ct[n][ty * 4 + i];
        #pragma unroll
        for (int j = 0; j < 4; j++) b[j] = Pt[n][tx * 4 + j];
        #pragma unroll
        for (int i = 0; i < 4; i++)
            #pragma unroll
            for (int j = 0; j < 4; j++) acc[i][j] += a[i] * b[j];
    }
    #pragma unroll
    for (int i = 0; i < 4; i++) {
        int gi = i0 + ty * 4 + i;
        float e = es[ty * 4 + i];
        float4* yp = (float4*)(g_y + (size_t)(row0 + gi) * D_INNER + h * HEADDIM + p0 + tx * 4);
        float4 v = *yp;
        v.x += e * acc[i][0]; v.y += e * acc[i][1];
        v.z += e * acc[i][2]; v.w += e * acc[i][3];
        *yp = v;
    }
}

// ---------------- K10: y += D*x, gate, RMS norm (tf32-rounded output) ----------------
__global__ __launch_bounds__(256) void k_gate(const float* __restrict__ Dp,
                                              const float* __restrict__ rms_w) {
    int row = blockIdx.x;
    int tid = threadIdx.x;
    float gg[8];
    float s2 = 0.f;
    #pragma unroll
    for (int k = 0; k < 8; k++) {
        int d = tid + 256 * k;
        float xv = g_xBC[(size_t)row * CONVDIM + d];
        float v = g_y[(size_t)row * D_INNER + d] + Dp[d >> 7] * xv;
        float z = g_zx[(size_t)row * DPROJP + d];
        float sil = z / (1.f + __expf(-z));
        float g = v * sil;
        gg[k] = g;
        s2 += g * g;
    }
    float tot = blockReduceSum256(s2);
    float sc = rsqrtf(tot * (1.f / D_INNER) + 1e-5f);
    #pragma unroll
    for (int k = 0; k < 8; k++) {
        int d = tid + 256 * k;
        g_g[(size_t)row * D_INNER + d] = to_tf32(gg[k] * sc * rms_w[d]);
    }
}

// ---------------- host launcher ----------------
extern "C" void kernel_launch(void* const* d_in, const int* in_sizes, int n_in,
                              void* d_out, int out_size) {
    const float* u          = (const float*)d_in[0];
    const float* in_proj_w  = (const float*)d_in[1];
    const float* conv_w     = (const float*)d_in[2];
    const float* conv_b     = (const float*)d_in[3];
    const float* dt_bias    = (const float*)d_in[4];
    const float* A_log      = (const float*)d_in[5];
    const float* Dp         = (const float*)d_in[6];
    const float* xnw        = (const float*)d_in[7];
    const float* xnb        = (const float*)d_in[8];
    const float* rms_w      = (const float*)d_in[9];
    const float* out_proj_w = (const float*)d_in[10];
    float* out = (float*)d_out;

    float *pWin, *pWout, *pLn, *pZx, *pG;
    cudaGetSymbolAddress((void**)&pWin,  g_Win);
    cudaGetSymbolAddress((void**)&pWout, g_Wout);
    cudaGetSymbolAddress((void**)&pLn,   g_ln);
    cudaGetSymbolAddress((void**)&pZx,   g_zx);
    cudaGetSymbolAddress((void**)&pG,    g_g);

    static int smem_set = 0;
    if (!smem_set) {
        cudaFuncSetAttribute(gemm_tc, cudaFuncAttributeMaxDynamicSharedMemorySize, GEMM_SMEM);
        smem_set = 1;
    }

    // weights: l2norm rows (fold DIM^-0.5 into in_proj), tf32-rounded
    k_normw<<<DPROJ, 256>>>(in_proj_w, pWin, XDIM, 0.03125f);
    k_normw<<<XDIM, 256>>>(out_proj_w, pWout, D_INNER, 1.0f);

    // layernorm input (tf32-rounded)
    k_layernorm<<<R_TOT, 256>>>(u, xnw, xnb);

    // in_proj GEMM (HMMA tf32): (8192 x 1024) @ (4352 x 1024)^T
    gemm_tc<<<dim3(DPROJP / GBN, R_TOT / GBM), 256, GEMM_SMEM>>>(pLn, pWin, pZx, XDIM, DPROJP);

    // depthwise conv + silu
    k_conv<<<(R_TOT * CONVDIM + 255) / 256, 256>>>(conv_w, conv_b);

    // dt softplus + cumulative decay
    k_dtcum<<<NBC * NHEADS, 256>>>(dt_bias, A_log);

    // SSD
    k_scores<<<dim3(NBC, 4, 4), 256>>>();
    k_yintra<<<dim3(NBC, NHEADS, 4), 256>>>();
    k_states<<<dim3(NBC, NHEADS), 256>>>();
    k_scan<<<dim3(NBATCH, NHEADS), 256>>>();
    k_yinter<<<dim3(NBC * NHEADS, 4, 2), 256>>>();

    // gate + RMS norm
    k_gate<<<R_TOT, 256>>>(Dp, rms_w);

    // out_proj GEMM (HMMA tf32): (8192 x 2048) @ (1024 x 2048)^T
    gemm_tc<<<dim3(XDIM / GBN, R_TOT / GBM), 256, GEMM_SMEM>>>(pG, pWout, out, D_INNER, XDIM);
}

// round 4
// speedup vs baseline: 3.0585x; 1.2496x over previous
#include <cuda_runtime.h>
#include <math.h>
#include <stdint.h>

// ---------------- problem constants ----------------
#define XDIM    1024
#define D_STATE 64
#define HEADDIM 128
#define D_INNER 2048
#define NHEADS  16
#define CONVDIM 2176              // D_INNER + 2*64
#define DPROJ   4240              // 2*2048 + 2*64 + 16
#define DPROJP  4352              // padded to 128-multiple for GEMM tiles
#define CHUNK   256
#define NBATCH  2
#define SEQLEN  4096
#define NCPB    16
#define NBC     32
#define R_TOT   8192

// ---------------- device scratch ----------------
__device__ float g_ln  [(size_t)R_TOT * XDIM];
__device__ float g_Win [(size_t)DPROJP * XDIM];      // rows >= DPROJ stay zero (.bss)
__device__ float g_Wout[(size_t)XDIM * D_INNER];
__device__ float g_zx  [(size_t)R_TOT * DPROJP];
__device__ float g_xBC [(size_t)R_TOT * CONVDIM];
__device__ float g_dt  [(size_t)R_TOT * NHEADS];
__device__ float g_cum [(size_t)NBC * NHEADS * CHUNK];
__device__ float g_cdec[(size_t)NBC * NHEADS];
__device__ float g_S   [(size_t)NBC * CHUNK * CHUNK];
__device__ float g_y   [(size_t)R_TOT * D_INNER];
__device__ float g_st  [(size_t)NBC * NHEADS * HEADDIM * D_STATE];
__device__ float g_ps  [(size_t)NBC * NHEADS * HEADDIM * D_STATE];
__device__ float g_g   [(size_t)R_TOT * D_INNER];

// ---------------- PTX helpers (baseline PTX only) ----------------
__device__ __forceinline__ uint32_t smem_u32(const void* p) {
    uint32_t a;
    asm("{ .reg .u64 t; cvta.to.shared.u64 t, %1; cvt.u32.u64 %0, t; }" : "=r"(a) : "l"(p));
    return a;
}
__device__ __forceinline__ float to_tf32(float x) {
    uint32_t r;
    asm("cvt.rna.tf32.f32 %0, %1;" : "=r"(r) : "f"(x));
    return __uint_as_float(r);
}
#define CP_ASYNC16(s, g) \
    asm volatile("cp.async.cg.shared.global [%0], [%1], 16;" :: "r"(s), "l"(g))
#define CP_COMMIT() asm volatile("cp.async.commit_group;" ::: "memory")
#define CP_WAIT(n)  asm volatile("cp.async.wait_group %0;" :: "n"(n) : "memory")

__device__ __forceinline__ void ldsm_x4(uint32_t* r, uint32_t addr) {
    asm volatile("ldmatrix.sync.aligned.m8n8.x4.shared.b16 {%0,%1,%2,%3}, [%4];"
        : "=r"(r[0]), "=r"(r[1]), "=r"(r[2]), "=r"(r[3]) : "r"(addr));
}
__device__ __forceinline__ void mma_tf32(float* d, const uint32_t* a, const uint32_t* b) {
    asm volatile("mma.sync.aligned.m16n8k8.row.col.f32.tf32.tf32.f32 "
        "{%0,%1,%2,%3},{%4,%5,%6,%7},{%8,%9},{%0,%1,%2,%3};"
        : "+f"(d[0]), "+f"(d[1]), "+f"(d[2]), "+f"(d[3])
        : "r"(a[0]), "r"(a[1]), "r"(a[2]), "r"(a[3]), "r"(b[0]), "r"(b[1]));
}

// ================= tensor-core tf32 GEMM: C[M,N] = A[M,K] * B[N,K]^T =================
#define GBM 128
#define GBN 128
#define GBK 32
#define GSTG 3
#define TB_A (GBM * GBK * 4)
#define TB_B (GBN * GBK * 4)
#define STAGE_B (TB_A + TB_B)
#define GEMM_SMEM (GSTG * STAGE_B)

__device__ __forceinline__ void gemm_load_tile(const float* Ab, const float* Bb,
                                               int K, int t, uint32_t sb, int tid) {
    const float* Ap = Ab + (size_t)t * GBK;
    const float* Bp = Bb + (size_t)t * GBK;
    #pragma unroll
    for (int j = 0; j < 4; j++) {
        int c = tid + 256 * j;
        int row = c >> 3;
        uint32_t cc = (uint32_t)(c & 7) * 16;
        uint32_t off = (uint32_t)row * 128 + (cc ^ (((uint32_t)row & 7) << 4));
        CP_ASYNC16(sb + off, Ap + (size_t)row * K + (cc >> 2));
    }
    uint32_t sb2 = sb + TB_A;
    #pragma unroll
    for (int j = 0; j < 4; j++) {
        int c = tid + 256 * j;
        int row = c >> 3;
        uint32_t cc = (uint32_t)(c & 7) * 16;
        uint32_t off = (uint32_t)row * 128 + (cc ^ (((uint32_t)row & 7) << 4));
        CP_ASYNC16(sb2 + off, Bp + (size_t)row * K + (cc >> 2));
    }
    CP_COMMIT();
}

__global__ __launch_bounds__(256, 1) void gemm_tc(const float* __restrict__ A,
                                                  const float* __restrict__ B,
                                                  float* __restrict__ C,
                                                  int K, int ldc) {
    extern __shared__ char sm[];
    uint32_t sbase = smem_u32(sm);
    int tid = threadIdx.x, lane = tid & 31, wid = tid >> 5;
    int wm = (wid & 1) * 64;
    int wn = (wid >> 1) * 32;
    int m0 = blockIdx.y * GBM;
    int n0 = blockIdx.x * GBN;
    const float* Ab = A + (size_t)m0 * K;
    const float* Bb = B + (size_t)n0 * K;

    int a_row = wm + (lane & 15);
    uint32_t a_kb = (uint32_t)(lane >> 4) * 16;
    int b_row = wn + (lane & 7) + ((lane & 16) ? 8 : 0);
    uint32_t b_kb = (lane & 8) ? 16u : 0u;

    float acc[4][4][4];
    #pragma unroll
    for (int mt = 0; mt < 4; mt++)
        #pragma unroll
        for (int nt = 0; nt < 4; nt++)
            #pragma unroll
            for (int q = 0; q < 4; q++) acc[mt][nt][q] = 0.f;

    int T = K / GBK;
    gemm_load_tile(Ab, Bb, K, 0, sbase, tid);
    gemm_load_tile(Ab, Bb, K, 1, sbase + STAGE_B, tid);

    for (int t = 0; t < T; t++) {
        CP_WAIT(1);
        __syncthreads();
        if (t + 2 < T)
            gemm_load_tile(Ab, Bb, K, t + 2, sbase + ((t + 2) % GSTG) * STAGE_B, tid);
        uint32_t sa = sbase + (t % GSTG) * STAGE_B;
        uint32_t sb = sa + TB_A;

        #pragma unroll
        for (int ks = 0; ks < 4; ks++) {
            uint32_t afr[4][4];
            #pragma unroll
            for (int mt = 0; mt < 4; mt++) {
                uint32_t row = (uint32_t)(a_row + mt * 16);
                uint32_t c = (uint32_t)ks * 32 + a_kb;
                ldsm_x4(afr[mt], sa + row * 128 + (c ^ ((row & 7) << 4)));
            }
            uint32_t bfr[2][4];
            #pragma unroll
            for (int nh = 0; nh < 2; nh++) {
                uint32_t row = (uint32_t)(b_row + nh * 16);
                uint32_t c = (uint32_t)ks * 32 + b_kb;
                ldsm_x4(bfr[nh], sb + row * 128 + (c ^ ((row & 7) << 4)));
            }
            #pragma unroll
            for (int mt = 0; mt < 4; mt++)
                #pragma unroll
                for (int nt = 0; nt < 4; nt++)
                    mma_tf32(acc[mt][nt], afr[mt], &bfr[nt >> 1][(nt & 1) * 2]);
        }
    }

    int g = lane >> 2, tg = lane & 3;
    #pragma unroll
    for (int mt = 0; mt < 4; mt++) {
        int rowa = m0 + wm + mt * 16 + g;
        #pragma unroll
        for (int nt = 0; nt < 4; nt++) {
            int col = n0 + wn + nt * 8 + tg * 2;
            *(float2*)(C + (size_t)rowa * ldc + col) =
                make_float2(acc[mt][nt][0], acc[mt][nt][1]);
            *(float2*)(C + (size_t)(rowa + 8) * ldc + col) =
                make_float2(acc[mt][nt][2], acc[mt][nt][3]);
        }
    }
}

// ============ fused SSD y-kernel: Y = att @ X  +  Ce @ P^T (tensor cores, tf32) ============
// Per block: (bc, h, ih). M = 128 rows (i-half), N = 128 (headdim p),
// K = 32*natt (causal att tiles) + 64 (inter-chunk state part).
__global__ __launch_bounds__(256, 1) void k_yfused() {
    __shared__ __align__(16) float As[128 * 32];
    __shared__ __align__(16) float Bs[128 * 32];
    int bc = blockIdx.x, h = blockIdx.y, ih = blockIdx.z;
    int i_base = ih * 128;
    int row0 = bc * CHUNK;
    int cb = (bc * NHEADS + h) * CHUNK;
    size_t psb = (size_t)(bc * NHEADS + h) * HEADDIM * D_STATE;

    int tid = threadIdx.x, lane = tid & 31, wid = tid >> 5;
    int wm = (wid & 3) * 32;       // warp M offset (4 x 32)
    int wn = (wid >> 2) * 64;      // warp N offset (2 x 64)

    // staging thread mapping (A-side): 2 threads per row, 16 cols each
    int si = tid >> 1;
    int sj = (tid & 1) * 16;
    int gi = i_base + si;
    float ci = g_cum[cb + gi];
    float ei = __expf(ci);

    uint32_t as_base = smem_u32(As);
    uint32_t bs_base = smem_u32(Bs);

    // mma fragment addressing (same mapping as gemm_tc)
    int a_row = wm + (lane & 15);
    uint32_t a_kb = (uint32_t)(lane >> 4) * 16;
    int b_row = wn + (lane & 7) + ((lane & 16) ? 8 : 0);
    uint32_t b_kb = (lane & 8) ? 16u : 0u;

    float acc[2][8][4];
    #pragma unroll
    for (int mt = 0; mt < 2; mt++)
        #pragma unroll
        for (int nt = 0; nt < 8; nt++)
            #pragma unroll
            for (int q = 0; q < 4; q++) acc[mt][nt][q] = 0.f;

    int natt = ih ? 8 : 4;
    int ntiles = natt + 2;
    for (int kt = 0; kt < ntiles; kt++) {
        __syncthreads();
        if (kt < natt) {
            int j0 = kt * 32;
            // --- A tile: att[i][j] = S * exp(ci - cum_j) * dt_j (causal mask) ---
            #pragma unroll
            for (int q = 0; q < 4; q++) {
                float tmp[4];
                #pragma unroll
                for (int r = 0; r < 4; r++) {
                    int j = j0 + sj + q * 4 + r;
                    float a = 0.f;
                    if (j <= gi)
                        a = g_S[((size_t)bc * CHUNK + gi) * CHUNK + j] *
                            __expf(ci - g_cum[cb + j]) *
                            g_dt[(size_t)(row0 + j) * NHEADS + h];
                    tmp[r] = to_tf32(a);
                }
                uint32_t cb4 = (uint32_t)(sj + q * 4) * 4;
                uint32_t off = (uint32_t)si * 128 + (cb4 ^ (((uint32_t)si & 7) << 4));
                *(float4*)((char*)As + off) = make_float4(tmp[0], tmp[1], tmp[2], tmp[3]);
            }
            // --- B tile: Xt[p][j] = x[row0+j][h*128+p] (transposed stage) ---
            int jw = wid;  // warp id 0..7
            #pragma unroll
            for (int jp = 0; jp < 4; jp++) {
                int j = jw + 8 * jp;
                const float* xrow = g_xBC + (size_t)(row0 + j0 + j) * CONVDIM + h * HEADDIM;
                #pragma unroll
                for (int r = 0; r < 4; r++) {
                    int p = lane + 32 * r;
                    float v = to_tf32(xrow[p]);
                    uint32_t cb4 = (uint32_t)j * 4;
                    uint32_t off = (uint32_t)p * 128 + (cb4 ^ (((uint32_t)p & 7) << 4));
                    *(float*)((char*)Bs + off) = v;
                }
            }
        } else {
            int n0 = (kt - natt) * 32;
            // --- A tile: Ce[i][n] = C[i][n] * exp(ci) ---
            const float* crow = g_xBC + (size_t)(row0 + gi) * CONVDIM + D_INNER + D_STATE;
            #pragma unroll
            for (int q = 0; q < 4; q++) {
                float tmp[4];
                #pragma unroll
                for (int r = 0; r < 4; r++)
                    tmp[r] = to_tf32(crow[n0 + sj + q * 4 + r] * ei);
                uint32_t cb4 = (uint32_t)(sj + q * 4) * 4;
                uint32_t off = (uint32_t)si * 128 + (cb4 ^ (((uint32_t)si & 7) << 4));
                *(float4*)((char*)As + off) = make_float4(tmp[0], tmp[1], tmp[2], tmp[3]);
            }
            // --- B tile: P[p][n] straight copy (g_ps already [p][n]) ---
            int pr = tid >> 1;
            int nc = (tid & 1) * 16;
            const float* prow = g_ps + psb + (size_t)pr * D_STATE + n0;
            #pragma unroll
            for (int q = 0; q < 4; q++) {
                float4 v = *(const float4*)(prow + nc + q * 4);
                v.x = to_tf32(v.x); v.y = to_tf32(v.y);
                v.z = to_tf32(v.z); v.w = to_tf32(v.w);
                uint32_t cb4 = (uint32_t)(nc + q * 4) * 4;
                uint32_t off = (uint32_t)pr * 128 + (cb4 ^ (((uint32_t)pr & 7) << 4));
                *(float4*)((char*)Bs + off) = v;
            }
        }
        __syncthreads();
        // --- MMA on the staged 32-wide K tile ---
        #pragma unroll
        for (int ks = 0; ks < 4; ks++) {
            uint32_t afr[2][4];
            #pragma unroll
            for (int mt = 0; mt < 2; mt++) {
                uint32_t row = (uint32_t)(a_row + mt * 16);
                uint32_t c = (uint32_t)ks * 32 + a_kb;
                ldsm_x4(afr[mt], as_base + row * 128 + (c ^ ((row & 7) << 4)));
            }
            uint32_t bfr[4][4];
            #pragma unroll
            for (int nh = 0; nh < 4; nh++) {
                uint32_t row = (uint32_t)(b_row + nh * 16);
                uint32_t c = (uint32_t)ks * 32 + b_kb;
                ldsm_x4(bfr[nh], bs_base + row * 128 + (c ^ ((row & 7) << 4)));
            }
            #pragma unroll
            for (int mt = 0; mt < 2; mt++)
                #pragma unroll
                for (int nt = 0; nt < 8; nt++)
                    mma_tf32(acc[mt][nt], afr[mt], &bfr[nt >> 1][(nt & 1) * 2]);
        }
    }

    // epilogue: write final y (single writer)
    int g = lane >> 2, tg = lane & 3;
    #pragma unroll
    for (int mt = 0; mt < 2; mt++) {
        int orow = row0 + i_base + wm + mt * 16 + g;
        #pragma unroll
        for (int nt = 0; nt < 8; nt++) {
            int col = h * HEADDIM + wn + nt * 8 + tg * 2;
            *(float2*)(g_y + (size_t)orow * D_INNER + col) =
                make_float2(acc[mt][nt][0], acc[mt][nt][1]);
            *(float2*)(g_y + (size_t)(orow + 8) * D_INNER + col) =
                make_float2(acc[mt][nt][2], acc[mt][nt][3]);
        }
    }
}

// ---------------- reductions ----------------
__device__ __forceinline__ float blockReduceSum256(float v) {
    __shared__ float red[8];
    __shared__ float tot;
    int lane = threadIdx.x & 31, wid = threadIdx.x >> 5;
    #pragma unroll
    for (int o = 16; o; o >>= 1) v += __shfl_down_sync(0xffffffffu, v, o);
    if (lane == 0) red[wid] = v;
    __syncthreads();
    if (wid == 0) {
        float w = (lane < 8) ? red[lane] : 0.f;
        #pragma unroll
        for (int o = 4; o; o >>= 1) w += __shfl_down_sync(0xffffffffu, w, o);
        if (lane == 0) tot = w;
    }
    __syncthreads();
    return tot;
}

// ---------------- K1: l2-normalize weight rows ----------------
__global__ __launch_bounds__(256) void k_normw(const float* __restrict__ W,
                                               float* __restrict__ Wo, int K, float extra) {
    int r = blockIdx.x;
    const float* wr = W + (size_t)r * K;
    float s2 = 0.f;
    for (int i = threadIdx.x; i < K; i += 256) { float v = wr[i]; s2 += v * v; }
    float totv = blockReduceSum256(s2);
    float sc = extra / fmaxf(sqrtf(totv), 1e-6f);
    for (int i = threadIdx.x; i < K; i += 256) Wo[(size_t)r * K + i] = to_tf32(wr[i] * sc);
}

// ---------------- K2: layernorm ----------------
__global__ __launch_bounds__(256) void k_layernorm(const float* __restrict__ u,
                                                   const float* __restrict__ w,
                                                   const float* __restrict__ b) {
    int row = blockIdx.x;
    const float* ur = u + (size_t)row * XDIM;
    float v[4]; float s = 0.f, s2 = 0.f;
    #pragma unroll
    for (int k = 0; k < 4; k++) {
        v[k] = ur[threadIdx.x + 256 * k];
        s += v[k]; s2 += v[k] * v[k];
    }
    float sum = blockReduceSum256(s);
    float sumsq = blockReduceSum256(s2);
    float mu = sum * (1.f / XDIM);
    float var = sumsq * (1.f / XDIM) - mu * mu;
    float inv = rsqrtf(var + 1e-5f);
    #pragma unroll
    for (int k = 0; k < 4; k++) {
        int d = threadIdx.x + 256 * k;
        g_ln[(size_t)row * XDIM + d] = to_tf32((v[k] - mu) * inv * w[d] + b[d]);
    }
}

// ---------------- K4: depthwise causal conv + bias + silu ----------------
__global__ __launch_bounds__(256) void k_conv(const float* __restrict__ cw,
                                              const float* __restrict__ cb) {
    int gi = blockIdx.x * 256 + threadIdx.x;
    if (gi >= R_TOT * CONVDIM) return;
    int ch = gi % CONVDIM;
    int row = gi / CONVDIM;
    int l = row & (SEQLEN - 1);
    float acc = cb[ch];
    #pragma unroll
    for (int d = 0; d < 4; d++) {
        int ll = l - 3 + d;
        if (ll >= 0)
            acc += cw[ch * 4 + d] * g_zx[(size_t)(row - 3 + d) * DPROJP + D_INNER + ch];
    }
    g_xBC[(size_t)row * CONVDIM + ch] = acc / (1.f + __expf(-acc));
}

// ---------------- K5: dt softplus + per-chunk cumulative dA ----------------
__global__ __launch_bounds__(256) void k_dtcum(const float* __restrict__ dt_bias,
                                               const float* __restrict__ A_log) {
    int bch = blockIdx.x;
    int h = bch & 15, bc = bch >> 4;
    int t = threadIdx.x;
    int row = bc * CHUNK + t;
    float x = g_zx[(size_t)row * DPROJP + (D_INNER + CONVDIM) + h] + dt_bias[h];
    float dtv = (x > 20.f) ? x : log1pf(expf(x));
    g_dt[(size_t)row * NHEADS + h] = dtv;
    float dA = dtv * (-expf(A_log[h]));
    __shared__ float s[256];
    s[t] = dA;
    __syncthreads();
    #pragma unroll
    for (int off = 1; off < 256; off <<= 1) {
        float pv = (t >= off) ? s[t - off] : 0.f;
        __syncthreads();
        s[t] += pv;
        __syncthreads();
    }
    g_cum[(size_t)bch * CHUNK + t] = s[t];
    if (t == 255) g_cdec[bch] = __expf(s[255]);
}

// ---------------- K6a: scores S = C @ B^T ----------------
__global__ __launch_bounds__(256) void k_scores() {
    if (blockIdx.z > blockIdx.y) return;
    int bc = blockIdx.x, i0 = blockIdx.y * 64, j0 = blockIdx.z * 64;
    __shared__ float Ct[64][65];
    __shared__ float Bt[64][65];
    int row0 = bc * CHUNK;
    for (int idx = threadIdx.x; idx < 4096; idx += 256) {
        int n = idx & 63, r = idx >> 6;
        Ct[n][r] = g_xBC[(size_t)(row0 + i0 + r) * CONVDIM + D_INNER + 64 + n];
        Bt[n][r] = g_xBC[(size_t)(row0 + j0 + r) * CONVDIM + D_INNER + n];
    }
    __syncthreads();
    int ty = threadIdx.x >> 4, tx = threadIdx.x & 15;
    float acc[4][4];
    #pragma unroll
    for (int i = 0; i < 4; i++)
        #pragma unroll
        for (int j = 0; j < 4; j++) acc[i][j] = 0.f;
    #pragma unroll 4
    for (int n = 0; n < 64; n++) {
        float a[4], b[4];
        #pragma unroll
        for (int i = 0; i < 4; i++) a[i] = Ct[n][ty * 4 + i];
        #pragma unroll
        for (int j = 0; j < 4; j++) b[j] = Bt[n][tx * 4 + j];
        #pragma unroll
        for (int i = 0; i < 4; i++)
            #pragma unroll
            for (int j = 0; j < 4; j++) acc[i][j] += a[i] * b[j];
    }
    #pragma unroll
    for (int i = 0; i < 4; i++)
        *(float4*)(g_S + ((size_t)bc * CHUNK + i0 + ty * 4 + i) * CHUNK + j0 + tx * 4) =
            make_float4(acc[i][0], acc[i][1], acc[i][2], acc[i][3]);
}

// ---------------- K7: per-chunk states ----------------
__global__ __launch_bounds__(256) void k_states() {
    int bc = blockIdx.x, h = blockIdx.y;
    __shared__ __align__(16) float xs[16][128];
    __shared__ float4 Bs4[16][16];
    __shared__ float wsh[16];
    int row0 = bc * CHUNK;
    int cb = (bc * NHEADS + h) * CHUNK;
    int tid = threadIdx.x;
    float cum_last = g_cum[cb + 255];
    int p = tid >> 1, nq = tid & 1;
    float4 acc[8];
    #pragma unroll
    for (int k = 0; k < 8; k++) acc[k] = make_float4(0.f, 0.f, 0.f, 0.f);
    for (int tt = 0; tt < 16; tt++) {
        int t0 = tt * 16;
        __syncthreads();
        #pragma unroll
        for (int ps = 0; ps < 2; ps++) {
            int idx = tid + ps * 256;
            int jr = idx >> 5, c = idx & 31;
            ((float4*)xs[jr])[c] = ((const float4*)(g_xBC + (size_t)(row0 + t0 + jr) * CONVDIM + h * HEADDIM))[c];
        }
        {
            int jr = tid >> 4, c = tid & 15;
            Bs4[jr][c] = ((const float4*)(g_xBC + (size_t)(row0 + t0 + jr) * CONVDIM + D_INNER))[c];
        }
        if (tid < 16) {
            int t = t0 + tid;
            wsh[tid] = g_dt[(size_t)(row0 + t) * NHEADS + h] * __expf(cum_last - g_cum[cb + t]);
        }
        __syncthreads();
        #pragma unroll
        for (int t = 0; t < 16; t++) {
            float xv = xs[t][p] * wsh[t];
            #pragma unroll
            for (int k = 0; k < 8; k++) {
                float4 b = Bs4[t][nq + 2 * k];
                acc[k].x += xv * b.x; acc[k].y += xv * b.y;
                acc[k].z += xv * b.z; acc[k].w += xv * b.w;
            }
        }
    }
    float4* sp = (float4*)(g_st + ((size_t)(bc * NHEADS + h) * HEADDIM + p) * D_STATE);
    #pragma unroll
    for (int k = 0; k < 8; k++) sp[nq + 2 * k] = acc[k];
}

// ---------------- K8: serial inter-chunk scan ----------------
__global__ __launch_bounds__(256) void k_scan() {
    int b = blockIdx.x, h = blockIdx.y;
    int tid = threadIdx.x;
    float carry[32];
    #pragma unroll
    for (int k = 0; k < 32; k++) carry[k] = 0.f;
    for (int c = 0; c < NCPB; c++) {
        int bch = (b * NCPB + c) * NHEADS + h;
        float dec = g_cdec[bch];
        size_t base = (size_t)bch * HEADDIM * D_STATE;
        #pragma unroll
        for (int k = 0; k < 32; k++) {
            int e = tid + 256 * k;
            g_ps[base + e] = carry[k];
            carry[k] = carry[k] * dec + g_st[base + e];
        }
    }
}

// ---------------- K10: y += D*x, gate, RMS norm ----------------
__global__ __launch_bounds__(256) void k_gate(const float* __restrict__ Dp,
                                              const float* __restrict__ rms_w) {
    int row = blockIdx.x;
    int tid = threadIdx.x;
    float gg[8];
    float s2 = 0.f;
    #pragma unroll
    for (int k = 0; k < 8; k++) {
        int d = tid + 256 * k;
        float xv = g_xBC[(size_t)row * CONVDIM + d];
        float v = g_y[(size_t)row * D_INNER + d] + Dp[d >> 7] * xv;
        float z = g_zx[(size_t)row * DPROJP + d];
        float sil = z / (1.f + __expf(-z));
        float g = v * sil;
        gg[k] = g;
        s2 += g * g;
    }
    float tot = blockReduceSum256(s2);
    float sc = rsqrtf(tot * (1.f / D_INNER) + 1e-5f);
    #pragma unroll
    for (int k = 0; k < 8; k++) {
        int d = tid + 256 * k;
        g_g[(size_t)row * D_INNER + d] = to_tf32(gg[k] * sc * rms_w[d]);
    }
}

// ---------------- host launcher ----------------
extern "C" void kernel_launch(void* const* d_in, const int* in_sizes, int n_in,
                              void* d_out, int out_size) {
    const float* u          = (const float*)d_in[0];
    const float* in_proj_w  = (const float*)d_in[1];
    const float* conv_w     = (const float*)d_in[2];
    const float* conv_b     = (const float*)d_in[3];
    const float* dt_bias    = (const float*)d_in[4];
    const float* A_log      = (const float*)d_in[5];
    const float* Dp         = (const float*)d_in[6];
    const float* xnw        = (const float*)d_in[7];
    const float* xnb        = (const float*)d_in[8];
    const float* rms_w      = (const float*)d_in[9];
    const float* out_proj_w = (const float*)d_in[10];
    float* out = (float*)d_out;

    float *pWin, *pWout, *pLn, *pZx, *pG;
    cudaGetSymbolAddress((void**)&pWin,  g_Win);
    cudaGetSymbolAddress((void**)&pWout, g_Wout);
    cudaGetSymbolAddress((void**)&pLn,   g_ln);
    cudaGetSymbolAddress((void**)&pZx,   g_zx);
    cudaGetSymbolAddress((void**)&pG,    g_g);

    static int smem_set = 0;
    if (!smem_set) {
        cudaFuncSetAttribute(gemm_tc, cudaFuncAttributeMaxDynamicSharedMemorySize, GEMM_SMEM);
        smem_set = 1;
    }

    k_normw<<<DPROJ, 256>>>(in_proj_w, pWin, XDIM, 0.03125f);
    k_normw<<<XDIM, 256>>>(out_proj_w, pWout, D_INNER, 1.0f);

    k_layernorm<<<R_TOT, 256>>>(u, xnw, xnb);

    gemm_tc<<<dim3(DPROJP / GBN, R_TOT / GBM), 256, GEMM_SMEM>>>(pLn, pWin, pZx, XDIM, DPROJP);

    k_conv<<<(R_TOT * CONVDIM + 255) / 256, 256>>>(conv_w, conv_b);
    k_dtcum<<<NBC * NHEADS, 256>>>(dt_bias, A_log);

    k_scores<<<dim3(NBC, 4, 4), 256>>>();
    k_states<<<dim3(NBC, NHEADS), 256>>>();
    k_scan<<<dim3(NBATCH, NHEADS), 256>>>();
    k_yfused<<<dim3(NBC, NHEADS, 2), 256>>>();

    k_gate<<<R_TOT, 256>>>(Dp, rms_w);

    gemm_tc<<<dim3(XDIM / GBN, R_TOT / GBM), 256, GEMM_SMEM>>>(pG, pWout, out, D_INNER, XDIM);
}

// round 5
// speedup vs baseline: 3.4583x; 1.1307x over previous
#include <cuda_runtime.h>
#include <math.h>
#include <stdint.h>

// ---------------- problem constants ----------------
#define XDIM    1024
#define D_STATE 64
#define HEADDIM 128
#define D_INNER 2048
#define NHEADS  16
#define CONVDIM 2176              // D_INNER + 2*64
#define DPROJ   4240              // 2*2048 + 2*64 + 16
#define DPROJP  4352              // padded to 128-multiple for GEMM tiles
#define CHUNK   256
#define NBATCH  2
#define SEQLEN  4096
#define NCPB    16
#define NBC     32
#define R_TOT   8192

// ---------------- device scratch ----------------
__device__ float g_ln  [(size_t)R_TOT * XDIM];
__device__ float g_Win [(size_t)DPROJP * XDIM];      // rows >= DPROJ stay zero (.bss)
__device__ float g_Wout[(size_t)XDIM * D_INNER];
__device__ float g_zx  [(size_t)R_TOT * DPROJP];
__device__ float g_xBC [(size_t)R_TOT * CONVDIM];
__device__ float g_dt  [(size_t)R_TOT * NHEADS];
__device__ float g_cum [(size_t)NBC * NHEADS * CHUNK];
__device__ float g_cdec[(size_t)NBC * NHEADS];
__device__ float g_S   [(size_t)NBC * CHUNK * CHUNK];
__device__ float g_y   [(size_t)R_TOT * D_INNER];
__device__ float g_st  [(size_t)NBC * NHEADS * HEADDIM * D_STATE];
__device__ float g_ps  [(size_t)NBC * NHEADS * HEADDIM * D_STATE];
__device__ float g_g   [(size_t)R_TOT * D_INNER];

// ---------------- PTX helpers (baseline PTX only) ----------------
__device__ __forceinline__ uint32_t smem_u32(const void* p) {
    uint32_t a;
    asm("{ .reg .u64 t; cvta.to.shared.u64 t, %1; cvt.u32.u64 %0, t; }" : "=r"(a) : "l"(p));
    return a;
}
__device__ __forceinline__ float to_tf32(float x) {
    uint32_t r;
    asm("cvt.rna.tf32.f32 %0, %1;" : "=r"(r) : "f"(x));
    return __uint_as_float(r);
}
#define CP_ASYNC16(s, g) \
    asm volatile("cp.async.cg.shared.global [%0], [%1], 16;" :: "r"(s), "l"(g))
#define CP_COMMIT() asm volatile("cp.async.commit_group;" ::: "memory")
#define CP_WAIT(n)  asm volatile("cp.async.wait_group %0;" :: "n"(n) : "memory")

__device__ __forceinline__ void ldsm_x4(uint32_t* r, uint32_t addr) {
    asm volatile("ldmatrix.sync.aligned.m8n8.x4.shared.b16 {%0,%1,%2,%3}, [%4];"
        : "=r"(r[0]), "=r"(r[1]), "=r"(r[2]), "=r"(r[3]) : "r"(addr));
}
__device__ __forceinline__ void mma_tf32(float* d, const uint32_t* a, const uint32_t* b) {
    asm volatile("mma.sync.aligned.m16n8k8.row.col.f32.tf32.tf32.f32 "
        "{%0,%1,%2,%3},{%4,%5,%6,%7},{%8,%9},{%0,%1,%2,%3};"
        : "+f"(d[0]), "+f"(d[1]), "+f"(d[2]), "+f"(d[3])
        : "r"(a[0]), "r"(a[1]), "r"(a[2]), "r"(a[3]), "r"(b[0]), "r"(b[1]));
}

// ================= tensor-core tf32 GEMM: C[M,N] = A[M,K] * B[N,K]^T =================
// 128x128x32 CTA tile, 4 warps (warp tile 64x64), 3-stage cp.async pipeline, 2 CTAs/SM.
#define GBM 128
#define GBN 128
#define GBK 32
#define GSTG 3
#define TB_A (GBM * GBK * 4)
#define TB_B (GBN * GBK * 4)
#define STAGE_B (TB_A + TB_B)
#define GEMM_SMEM (GSTG * STAGE_B)

__device__ __forceinline__ void gemm_load_tile(const float* Ab, const float* Bb,
                                               int K, int t, uint32_t sb, int tid) {
    const float* Ap = Ab + (size_t)t * GBK;
    const float* Bp = Bb + (size_t)t * GBK;
    #pragma unroll
    for (int j = 0; j < 8; j++) {
        int c = tid + 128 * j;
        int row = c >> 3;
        uint32_t cc = (uint32_t)(c & 7) * 16;
        uint32_t off = (uint32_t)row * 128 + (cc ^ (((uint32_t)row & 7) << 4));
        CP_ASYNC16(sb + off, Ap + (size_t)row * K + (cc >> 2));
    }
    uint32_t sb2 = sb + TB_A;
    #pragma unroll
    for (int j = 0; j < 8; j++) {
        int c = tid + 128 * j;
        int row = c >> 3;
        uint32_t cc = (uint32_t)(c & 7) * 16;
        uint32_t off = (uint32_t)row * 128 + (cc ^ (((uint32_t)row & 7) << 4));
        CP_ASYNC16(sb2 + off, Bp + (size_t)row * K + (cc >> 2));
    }
    CP_COMMIT();
}

__global__ __launch_bounds__(128, 2) void gemm_tc(const float* __restrict__ A,
                                                  const float* __restrict__ B,
                                                  float* __restrict__ C,
                                                  int K, int ldc) {
    extern __shared__ char sm[];
    uint32_t sbase = smem_u32(sm);
    int tid = threadIdx.x, lane = tid & 31, wid = tid >> 5;
    int wm = (wid & 1) * 64;            // 2 warps in M
    int wn = (wid >> 1) * 64;           // 2 warps in N
    int m0 = blockIdx.y * GBM;
    int n0 = blockIdx.x * GBN;
    const float* Ab = A + (size_t)m0 * K;
    const float* Bb = B + (size_t)n0 * K;

    int a_row = wm + (lane & 15);
    uint32_t a_kb = (uint32_t)(lane >> 4) * 16;
    int b_row = wn + (lane & 7) + ((lane & 16) ? 8 : 0);
    uint32_t b_kb = (lane & 8) ? 16u : 0u;

    float acc[4][8][4];
    #pragma unroll
    for (int mt = 0; mt < 4; mt++)
        #pragma unroll
        for (int nt = 0; nt < 8; nt++)
            #pragma unroll
            for (int q = 0; q < 4; q++) acc[mt][nt][q] = 0.f;

    int T = K / GBK;
    gemm_load_tile(Ab, Bb, K, 0, sbase, tid);
    gemm_load_tile(Ab, Bb, K, 1, sbase + STAGE_B, tid);

    for (int t = 0; t < T; t++) {
        CP_WAIT(1);
        __syncthreads();
        if (t + 2 < T)
            gemm_load_tile(Ab, Bb, K, t + 2, sbase + ((t + 2) % GSTG) * STAGE_B, tid);
        uint32_t sa = sbase + (t % GSTG) * STAGE_B;
        uint32_t sb = sa + TB_A;

        #pragma unroll
        for (int ks = 0; ks < 4; ks++) {
            uint32_t afr[4][4];
            #pragma unroll
            for (int mt = 0; mt < 4; mt++) {
                uint32_t row = (uint32_t)(a_row + mt * 16);
                uint32_t c = (uint32_t)ks * 32 + a_kb;
                ldsm_x4(afr[mt], sa + row * 128 + (c ^ ((row & 7) << 4)));
            }
            uint32_t bfr[4][4];
            #pragma unroll
            for (int nh = 0; nh < 4; nh++) {
                uint32_t row = (uint32_t)(b_row + nh * 16);
                uint32_t c = (uint32_t)ks * 32 + b_kb;
                ldsm_x4(bfr[nh], sb + row * 128 + (c ^ ((row & 7) << 4)));
            }
            #pragma unroll
            for (int mt = 0; mt < 4; mt++)
                #pragma unroll
                for (int nt = 0; nt < 8; nt++)
                    mma_tf32(acc[mt][nt], afr[mt], &bfr[nt >> 1][(nt & 1) * 2]);
        }
    }

    int g = lane >> 2, tg = lane & 3;
    #pragma unroll
    for (int mt = 0; mt < 4; mt++) {
        int rowa = m0 + wm + mt * 16 + g;
        #pragma unroll
        for (int nt = 0; nt < 8; nt++) {
            int col = n0 + wn + nt * 8 + tg * 2;
            *(float2*)(C + (size_t)rowa * ldc + col) =
                make_float2(acc[mt][nt][0], acc[mt][nt][1]);
            *(float2*)(C + (size_t)(rowa + 8) * ldc + col) =
                make_float2(acc[mt][nt][2], acc[mt][nt][3]);
        }
    }
}

// ============ fused SSD y-kernel: Y = att @ X  +  Ce @ P^T (tensor cores, tf32) ============
__global__ __launch_bounds__(256, 1) void k_yfused() {
    __shared__ __align__(16) float As[128 * 32];
    __shared__ __align__(16) float Bs[128 * 32];
    int bc = blockIdx.x, h = blockIdx.y, ih = blockIdx.z;
    int i_base = ih * 128;
    int row0 = bc * CHUNK;
    int cb = (bc * NHEADS + h) * CHUNK;
    size_t psb = (size_t)(bc * NHEADS + h) * HEADDIM * D_STATE;

    int tid = threadIdx.x, lane = tid & 31, wid = tid >> 5;
    int wm = (wid & 3) * 32;
    int wn = (wid >> 2) * 64;

    int si = tid >> 1;
    int sj = (tid & 1) * 16;
    int gi = i_base + si;
    float ci = g_cum[cb + gi];
    float ei = __expf(ci);

    uint32_t as_base = smem_u32(As);
    uint32_t bs_base = smem_u32(Bs);

    int a_row = wm + (lane & 15);
    uint32_t a_kb = (uint32_t)(lane >> 4) * 16;
    int b_row = wn + (lane & 7) + ((lane & 16) ? 8 : 0);
    uint32_t b_kb = (lane & 8) ? 16u : 0u;

    float acc[2][8][4];
    #pragma unroll
    for (int mt = 0; mt < 2; mt++)
        #pragma unroll
        for (int nt = 0; nt < 8; nt++)
            #pragma unroll
            for (int q = 0; q < 4; q++) acc[mt][nt][q] = 0.f;

    int natt = ih ? 8 : 4;
    int ntiles = natt + 2;
    for (int kt = 0; kt < ntiles; kt++) {
        __syncthreads();
        if (kt < natt) {
            int j0 = kt * 32;
            #pragma unroll
            for (int q = 0; q < 4; q++) {
                float tmp[4];
                #pragma unroll
                for (int r = 0; r < 4; r++) {
                    int j = j0 + sj + q * 4 + r;
                    float a = 0.f;
                    if (j <= gi)
                        a = g_S[((size_t)bc * CHUNK + gi) * CHUNK + j] *
                            __expf(ci - g_cum[cb + j]) *
                            g_dt[(size_t)(row0 + j) * NHEADS + h];
                    tmp[r] = to_tf32(a);
                }
                uint32_t cb4 = (uint32_t)(sj + q * 4) * 4;
                uint32_t off = (uint32_t)si * 128 + (cb4 ^ (((uint32_t)si & 7) << 4));
                *(float4*)((char*)As + off) = make_float4(tmp[0], tmp[1], tmp[2], tmp[3]);
            }
            int jw = wid;
            #pragma unroll
            for (int jp = 0; jp < 4; jp++) {
                int j = jw + 8 * jp;
                const float* xrow = g_xBC + (size_t)(row0 + j0 + j) * CONVDIM + h * HEADDIM;
                #pragma unroll
                for (int r = 0; r < 4; r++) {
                    int p = lane + 32 * r;
                    float v = to_tf32(xrow[p]);
                    uint32_t cb4 = (uint32_t)j * 4;
                    uint32_t off = (uint32_t)p * 128 + (cb4 ^ (((uint32_t)p & 7) << 4));
                    *(float*)((char*)Bs + off) = v;
                }
            }
        } else {
            int n0 = (kt - natt) * 32;
            const float* crow = g_xBC + (size_t)(row0 + gi) * CONVDIM + D_INNER + D_STATE;
            #pragma unroll
            for (int q = 0; q < 4; q++) {
                float tmp[4];
                #pragma unroll
                for (int r = 0; r < 4; r++)
                    tmp[r] = to_tf32(crow[n0 + sj + q * 4 + r] * ei);
                uint32_t cb4 = (uint32_t)(sj + q * 4) * 4;
                uint32_t off = (uint32_t)si * 128 + (cb4 ^ (((uint32_t)si & 7) << 4));
                *(float4*)((char*)As + off) = make_float4(tmp[0], tmp[1], tmp[2], tmp[3]);
            }
            int pr = tid >> 1;
            int nc = (tid & 1) * 16;
            const float* prow = g_ps + psb + (size_t)pr * D_STATE + n0;
            #pragma unroll
            for (int q = 0; q < 4; q++) {
                float4 v = *(const float4*)(prow + nc + q * 4);
                v.x = to_tf32(v.x); v.y = to_tf32(v.y);
                v.z = to_tf32(v.z); v.w = to_tf32(v.w);
                uint32_t cb4 = (uint32_t)(nc + q * 4) * 4;
                uint32_t off = (uint32_t)pr * 128 + (cb4 ^ (((uint32_t)pr & 7) << 4));
                *(float4*)((char*)Bs + off) = v;
            }
        }
        __syncthreads();
        #pragma unroll
        for (int ks = 0; ks < 4; ks++) {
            uint32_t afr[2][4];
            #pragma unroll
            for (int mt = 0; mt < 2; mt++) {
                uint32_t row = (uint32_t)(a_row + mt * 16);
                uint32_t c = (uint32_t)ks * 32 + a_kb;
                ldsm_x4(afr[mt], as_base + row * 128 + (c ^ ((row & 7) << 4)));
            }
            uint32_t bfr[4][4];
            #pragma unroll
            for (int nh = 0; nh < 4; nh++) {
                uint32_t row = (uint32_t)(b_row + nh * 16);
                uint32_t c = (uint32_t)ks * 32 + b_kb;
                ldsm_x4(bfr[nh], bs_base + row * 128 + (c ^ ((row & 7) << 4)));
            }
            #pragma unroll
            for (int mt = 0; mt < 2; mt++)
                #pragma unroll
                for (int nt = 0; nt < 8; nt++)
                    mma_tf32(acc[mt][nt], afr[mt], &bfr[nt >> 1][(nt & 1) * 2]);
        }
    }

    int g = lane >> 2, tg = lane & 3;
    #pragma unroll
    for (int mt = 0; mt < 2; mt++) {
        int orow = row0 + i_base + wm + mt * 16 + g;
        #pragma unroll
        for (int nt = 0; nt < 8; nt++) {
            int col = h * HEADDIM + wn + nt * 8 + tg * 2;
            *(float2*)(g_y + (size_t)orow * D_INNER + col) =
                make_float2(acc[mt][nt][0], acc[mt][nt][1]);
            *(float2*)(g_y + (size_t)(orow + 8) * D_INNER + col) =
                make_float2(acc[mt][nt][2], acc[mt][nt][3]);
        }
    }
}

// ---------------- reductions ----------------
__device__ __forceinline__ float blockReduceSum256(float v) {
    __shared__ float red[8];
    __shared__ float tot;
    int lane = threadIdx.x & 31, wid = threadIdx.x >> 5;
    #pragma unroll
    for (int o = 16; o; o >>= 1) v += __shfl_down_sync(0xffffffffu, v, o);
    if (lane == 0) red[wid] = v;
    __syncthreads();
    if (wid == 0) {
        float w = (lane < 8) ? red[lane] : 0.f;
        #pragma unroll
        for (int o = 4; o; o >>= 1) w += __shfl_down_sync(0xffffffffu, w, o);
        if (lane == 0) tot = w;
    }
    __syncthreads();
    return tot;
}

// ---------------- K1: l2-normalize weight rows ----------------
__global__ __launch_bounds__(256) void k_normw(const float* __restrict__ W,
                                               float* __restrict__ Wo, int K, float extra) {
    int r = blockIdx.x;
    const float* wr = W + (size_t)r * K;
    float s2 = 0.f;
    for (int i = threadIdx.x; i < K; i += 256) { float v = wr[i]; s2 += v * v; }
    float totv = blockReduceSum256(s2);
    float sc = extra / fmaxf(sqrtf(totv), 1e-6f);
    for (int i = threadIdx.x; i < K; i += 256) Wo[(size_t)r * K + i] = to_tf32(wr[i] * sc);
}

// ---------------- K2: layernorm ----------------
__global__ __launch_bounds__(256) void k_layernorm(const float* __restrict__ u,
                                                   const float* __restrict__ w,
                                                   const float* __restrict__ b) {
    int row = blockIdx.x;
    const float* ur = u + (size_t)row * XDIM;
    float v[4]; float s = 0.f, s2 = 0.f;
    #pragma unroll
    for (int k = 0; k < 4; k++) {
        v[k] = ur[threadIdx.x + 256 * k];
        s += v[k]; s2 += v[k] * v[k];
    }
    float sum = blockReduceSum256(s);
    float sumsq = blockReduceSum256(s2);
    float mu = sum * (1.f / XDIM);
    float var = sumsq * (1.f / XDIM) - mu * mu;
    float inv = rsqrtf(var + 1e-5f);
    #pragma unroll
    for (int k = 0; k < 4; k++) {
        int d = threadIdx.x + 256 * k;
        g_ln[(size_t)row * XDIM + d] = to_tf32((v[k] - mu) * inv * w[d] + b[d]);
    }
}

// ---------------- K4: depthwise causal conv + bias + silu ----------------
__global__ __launch_bounds__(256) void k_conv(const float* __restrict__ cw,
                                              const float* __restrict__ cb) {
    int gi = blockIdx.x * 256 + threadIdx.x;
    if (gi >= R_TOT * CONVDIM) return;
    int ch = gi % CONVDIM;
    int row = gi / CONVDIM;
    int l = row & (SEQLEN - 1);
    float acc = cb[ch];
    #pragma unroll
    for (int d = 0; d < 4; d++) {
        int ll = l - 3 + d;
        if (ll >= 0)
            acc += cw[ch * 4 + d] * g_zx[(size_t)(row - 3 + d) * DPROJP + D_INNER + ch];
    }
    g_xBC[(size_t)row * CONVDIM + ch] = acc / (1.f + __expf(-acc));
}

// ---------------- K5: dt softplus + per-chunk cumulative dA ----------------
__global__ __launch_bounds__(256) void k_dtcum(const float* __restrict__ dt_bias,
                                               const float* __restrict__ A_log) {
    int bch = blockIdx.x;
    int h = bch & 15, bc = bch >> 4;
    int t = threadIdx.x;
    int row = bc * CHUNK + t;
    float x = g_zx[(size_t)row * DPROJP + (D_INNER + CONVDIM) + h] + dt_bias[h];
    float dtv = (x > 20.f) ? x : log1pf(expf(x));
    g_dt[(size_t)row * NHEADS + h] = dtv;
    float dA = dtv * (-expf(A_log[h]));
    __shared__ float s[256];
    s[t] = dA;
    __syncthreads();
    #pragma unroll
    for (int off = 1; off < 256; off <<= 1) {
        float pv = (t >= off) ? s[t - off] : 0.f;
        __syncthreads();
        s[t] += pv;
        __syncthreads();
    }
    g_cum[(size_t)bch * CHUNK + t] = s[t];
    if (t == 255) g_cdec[bch] = __expf(s[255]);
}

// ---------------- K6a: scores S = C @ B^T ----------------
__global__ __launch_bounds__(256) void k_scores() {
    if (blockIdx.z > blockIdx.y) return;
    int bc = blockIdx.x, i0 = blockIdx.y * 64, j0 = blockIdx.z * 64;
    __shared__ float Ct[64][65];
    __shared__ float Bt[64][65];
    int row0 = bc * CHUNK;
    for (int idx = threadIdx.x; idx < 4096; idx += 256) {
        int n = idx & 63, r = idx >> 6;
        Ct[n][r] = g_xBC[(size_t)(row0 + i0 + r) * CONVDIM + D_INNER + 64 + n];
        Bt[n][r] = g_xBC[(size_t)(row0 + j0 + r) * CONVDIM + D_INNER + n];
    }
    __syncthreads();
    int ty = threadIdx.x >> 4, tx = threadIdx.x & 15;
    float acc[4][4];
    #pragma unroll
    for (int i = 0; i < 4; i++)
        #pragma unroll
        for (int j = 0; j < 4; j++) acc[i][j] = 0.f;
    #pragma unroll 4
    for (int n = 0; n < 64; n++) {
        float a[4], b[4];
        #pragma unroll
        for (int i = 0; i < 4; i++) a[i] = Ct[n][ty * 4 + i];
        #pragma unroll
        for (int j = 0; j < 4; j++) b[j] = Bt[n][tx * 4 + j];
        #pragma unroll
        for (int i = 0; i < 4; i++)
            #pragma unroll
            for (int j = 0; j < 4; j++) acc[i][j] += a[i] * b[j];
    }
    #pragma unroll
    for (int i = 0; i < 4; i++)
        *(float4*)(g_S + ((size_t)bc * CHUNK + i0 + ty * 4 + i) * CHUNK + j0 + tx * 4) =
            make_float4(acc[i][0], acc[i][1], acc[i][2], acc[i][3]);
}

// ---------------- K7: per-chunk states ----------------
__global__ __launch_bounds__(256) void k_states() {
    int bc = blockIdx.x, h = blockIdx.y;
    __shared__ __align__(16) float xs[16][128];
    __shared__ float4 Bs4[16][16];
    __shared__ float wsh[16];
    int row0 = bc * CHUNK;
    int cb = (bc * NHEADS + h) * CHUNK;
    int tid = threadIdx.x;
    float cum_last = g_cum[cb + 255];
    int p = tid >> 1, nq = tid & 1;
    float4 acc[8];
    #pragma unroll
    for (int k = 0; k < 8; k++) acc[k] = make_float4(0.f, 0.f, 0.f, 0.f);
    for (int tt = 0; tt < 16; tt++) {
        int t0 = tt * 16;
        __syncthreads();
        #pragma unroll
        for (int ps = 0; ps < 2; ps++) {
            int idx = tid + ps * 256;
            int jr = idx >> 5, c = idx & 31;
            ((float4*)xs[jr])[c] = ((const float4*)(g_xBC + (size_t)(row0 + t0 + jr) * CONVDIM + h * HEADDIM))[c];
        }
        {
            int jr = tid >> 4, c = tid & 15;
            Bs4[jr][c] = ((const float4*)(g_xBC + (size_t)(row0 + t0 + jr) * CONVDIM + D_INNER))[c];
        }
        if (tid < 16) {
            int t = t0 + tid;
            wsh[tid] = g_dt[(size_t)(row0 + t) * NHEADS + h] * __expf(cum_last - g_cum[cb + t]);
        }
        __syncthreads();
        #pragma unroll
        for (int t = 0; t < 16; t++) {
            float xv = xs[t][p] * wsh[t];
            #pragma unroll
            for (int k = 0; k < 8; k++) {
                float4 b = Bs4[t][nq + 2 * k];
                acc[k].x += xv * b.x; acc[k].y += xv * b.y;
                acc[k].z += xv * b.z; acc[k].w += xv * b.w;
            }
        }
    }
    float4* sp = (float4*)(g_st + ((size_t)(bc * NHEADS + h) * HEADDIM + p) * D_STATE);
    #pragma unroll
    for (int k = 0; k < 8; k++) sp[nq + 2 * k] = acc[k];
}

// ---------------- K8: serial inter-chunk scan ----------------
__global__ __launch_bounds__(256) void k_scan() {
    int b = blockIdx.x, h = blockIdx.y;
    int tid = threadIdx.x;
    float carry[32];
    #pragma unroll
    for (int k = 0; k < 32; k++) carry[k] = 0.f;
    for (int c = 0; c < NCPB; c++) {
        int bch = (b * NCPB + c) * NHEADS + h;
        float dec = g_cdec[bch];
        size_t base = (size_t)bch * HEADDIM * D_STATE;
        #pragma unroll
        for (int k = 0; k < 32; k++) {
            int e = tid + 256 * k;
            g_ps[base + e] = carry[k];
            carry[k] = carry[k] * dec + g_st[base + e];
        }
    }
}

// ---------------- K10: y += D*x, gate, RMS norm ----------------
__global__ __launch_bounds__(256) void k_gate(const float* __restrict__ Dp,
                                              const float* __restrict__ rms_w) {
    int row = blockIdx.x;
    int tid = threadIdx.x;
    float gg[8];
    float s2 = 0.f;
    #pragma unroll
    for (int k = 0; k < 8; k++) {
        int d = tid + 256 * k;
        float xv = g_xBC[(size_t)row * CONVDIM + d];
        float v = g_y[(size_t)row * D_INNER + d] + Dp[d >> 7] * xv;
        float z = g_zx[(size_t)row * DPROJP + d];
        float sil = z / (1.f + __expf(-z));
        float g = v * sil;
        gg[k] = g;
        s2 += g * g;
    }
    float tot = blockReduceSum256(s2);
    float sc = rsqrtf(tot * (1.f / D_INNER) + 1e-5f);
    #pragma unroll
    for (int k = 0; k < 8; k++) {
        int d = tid + 256 * k;
        g_g[(size_t)row * D_INNER + d] = to_tf32(gg[k] * sc * rms_w[d]);
    }
}

// ---------------- host launcher ----------------
extern "C" void kernel_launch(void* const* d_in, const int* in_sizes, int n_in,
                              void* d_out, int out_size) {
    const float* u          = (const float*)d_in[0];
    const float* in_proj_w  = (const float*)d_in[1];
    const float* conv_w     = (const float*)d_in[2];
    const float* conv_b     = (const float*)d_in[3];
    const float* dt_bias    = (const float*)d_in[4];
    const float* A_log      = (const float*)d_in[5];
    const float* Dp         = (const float*)d_in[6];
    const float* xnw        = (const float*)d_in[7];
    const float* xnb        = (const float*)d_in[8];
    const float* rms_w      = (const float*)d_in[9];
    const float* out_proj_w = (const float*)d_in[10];
    float* out = (float*)d_out;

    float *pWin, *pWout, *pLn, *pZx, *pG;
    cudaGetSymbolAddress((void**)&pWin,  g_Win);
    cudaGetSymbolAddress((void**)&pWout, g_Wout);
    cudaGetSymbolAddress((void**)&pLn,   g_ln);
    cudaGetSymbolAddress((void**)&pZx,   g_zx);
    cudaGetSymbolAddress((void**)&pG,    g_g);

    static int smem_set = 0;
    if (!smem_set) {
        cudaFuncSetAttribute(gemm_tc, cudaFuncAttributeMaxDynamicSharedMemorySize, GEMM_SMEM);
        smem_set = 1;
    }

    k_normw<<<DPROJ, 256>>>(in_proj_w, pWin, XDIM, 0.03125f);
    k_normw<<<XDIM, 256>>>(out_proj_w, pWout, D_INNER, 1.0f);

    k_layernorm<<<R_TOT, 256>>>(u, xnw, xnb);

    gemm_tc<<<dim3(DPROJP / GBN, R_TOT / GBM), 128, GEMM_SMEM>>>(pLn, pWin, pZx, XDIM, DPROJP);

    k_conv<<<(R_TOT * CONVDIM + 255) / 256, 256>>>(conv_w, conv_b);
    k_dtcum<<<NBC * NHEADS, 256>>>(dt_bias, A_log);

    k_scores<<<dim3(NBC, 4, 4), 256>>>();
    k_states<<<dim3(NBC, NHEADS), 256>>>();
    k_scan<<<dim3(NBATCH, NHEADS), 256>>>();
    k_yfused<<<dim3(NBC, NHEADS, 2), 256>>>();

    k_gate<<<R_TOT, 256>>>(Dp, rms_w);

    gemm_tc<<<dim3(XDIM / GBN, R_TOT / GBM), 128, GEMM_SMEM>>>(pG, pWout, out, D_INNER, XDIM);
}

// round 6
// speedup vs baseline: 3.5123x; 1.0156x over previous
#include <cuda_runtime.h>
#include <math.h>
#include <stdint.h>

// ---------------- problem constants ----------------
#define XDIM    1024
#define D_STATE 64
#define HEADDIM 128
#define D_INNER 2048
#define NHEADS  16
#define CONVDIM 2176              // D_INNER + 2*64
#define DPROJ   4240              // 2*2048 + 2*64 + 16
#define DPROJP  4352              // padded to 128-multiple for GEMM tiles
#define CHUNK   256
#define NBATCH  2
#define SEQLEN  4096
#define NCPB    16
#define NBC     32
#define R_TOT   8192

// ---------------- device scratch ----------------
__device__ float g_ln  [(size_t)R_TOT * XDIM];
__device__ float g_Win [(size_t)DPROJP * XDIM];      // rows >= DPROJ stay zero (.bss)
__device__ float g_Wout[(size_t)XDIM * D_INNER];
__device__ float g_zx  [(size_t)R_TOT * DPROJP];
__device__ float g_xBC [(size_t)R_TOT * CONVDIM];
__device__ float g_dt  [(size_t)R_TOT * NHEADS];
__device__ float g_cum [(size_t)NBC * NHEADS * CHUNK];
__device__ float g_cdec[(size_t)NBC * NHEADS];
__device__ float g_S   [(size_t)NBC * CHUNK * CHUNK];
__device__ float g_y   [(size_t)R_TOT * D_INNER];
__device__ float g_st  [(size_t)NBC * NHEADS * HEADDIM * D_STATE];
__device__ float g_ps  [(size_t)NBC * NHEADS * HEADDIM * D_STATE];
__device__ float g_g   [(size_t)R_TOT * D_INNER];

// ---------------- PTX helpers (baseline PTX only) ----------------
__device__ __forceinline__ uint32_t smem_u32(const void* p) {
    uint32_t a;
    asm("{ .reg .u64 t; cvta.to.shared.u64 t, %1; cvt.u32.u64 %0, t; }" : "=r"(a) : "l"(p));
    return a;
}
__device__ __forceinline__ float to_tf32(float x) {
    uint32_t r;
    asm("cvt.rna.tf32.f32 %0, %1;" : "=r"(r) : "f"(x));
    return __uint_as_float(r);
}
#define CP_ASYNC16(s, g) \
    asm volatile("cp.async.cg.shared.global [%0], [%1], 16;" :: "r"(s), "l"(g))
#define CP_COMMIT() asm volatile("cp.async.commit_group;" ::: "memory")
#define CP_WAIT(n)  asm volatile("cp.async.wait_group %0;" :: "n"(n) : "memory")

__device__ __forceinline__ void ldsm_x4(uint32_t* r, uint32_t addr) {
    asm volatile("ldmatrix.sync.aligned.m8n8.x4.shared.b16 {%0,%1,%2,%3}, [%4];"
        : "=r"(r[0]), "=r"(r[1]), "=r"(r[2]), "=r"(r[3]) : "r"(addr));
}
__device__ __forceinline__ void mma_tf32(float* d, const uint32_t* a, const uint32_t* b) {
    asm volatile("mma.sync.aligned.m16n8k8.row.col.f32.tf32.tf32.f32 "
        "{%0,%1,%2,%3},{%4,%5,%6,%7},{%8,%9},{%0,%1,%2,%3};"
        : "+f"(d[0]), "+f"(d[1]), "+f"(d[2]), "+f"(d[3])
        : "r"(a[0]), "r"(a[1]), "r"(a[2]), "r"(a[3]), "r"(b[0]), "r"(b[1]));
}

// ================= tensor-core tf32 GEMM: C[M,N] = A[M,K] * B[N,K]^T =================
// 128x128x32 CTA tile, 4 warps (warp tile 64x64), 3-stage cp.async pipeline, 2 CTAs/SM.
#define GBM 128
#define GBN 128
#define GBK 32
#define GSTG 3
#define TB_A (GBM * GBK * 4)
#define TB_B (GBN * GBK * 4)
#define STAGE_B (TB_A + TB_B)
#define GEMM_SMEM (GSTG * STAGE_B)

__device__ __forceinline__ void gemm_load_tile(const float* Ab, const float* Bb,
                                               int K, int t, uint32_t sb, int tid) {
    const float* Ap = Ab + (size_t)t * GBK;
    const float* Bp = Bb + (size_t)t * GBK;
    #pragma unroll
    for (int j = 0; j < 8; j++) {
        int c = tid + 128 * j;
        int row = c >> 3;
        uint32_t cc = (uint32_t)(c & 7) * 16;
        uint32_t off = (uint32_t)row * 128 + (cc ^ (((uint32_t)row & 7) << 4));
        CP_ASYNC16(sb + off, Ap + (size_t)row * K + (cc >> 2));
    }
    uint32_t sb2 = sb + TB_A;
    #pragma unroll
    for (int j = 0; j < 8; j++) {
        int c = tid + 128 * j;
        int row = c >> 3;
        uint32_t cc = (uint32_t)(c & 7) * 16;
        uint32_t off = (uint32_t)row * 128 + (cc ^ (((uint32_t)row & 7) << 4));
        CP_ASYNC16(sb2 + off, Bp + (size_t)row * K + (cc >> 2));
    }
    CP_COMMIT();
}

__global__ __launch_bounds__(128, 2) void gemm_tc(const float* __restrict__ A,
                                                  const float* __restrict__ B,
                                                  float* __restrict__ C,
                                                  int K, int ldc) {
    extern __shared__ char sm[];
    uint32_t sbase = smem_u32(sm);
    int tid = threadIdx.x, lane = tid & 31, wid = tid >> 5;
    int wm = (wid & 1) * 64;
    int wn = (wid >> 1) * 64;
    int m0 = blockIdx.y * GBM;
    int n0 = blockIdx.x * GBN;
    const float* Ab = A + (size_t)m0 * K;
    const float* Bb = B + (size_t)n0 * K;

    int a_row = wm + (lane & 15);
    uint32_t a_kb = (uint32_t)(lane >> 4) * 16;
    int b_row = wn + (lane & 7) + ((lane & 16) ? 8 : 0);
    uint32_t b_kb = (lane & 8) ? 16u : 0u;

    float acc[4][8][4];
    #pragma unroll
    for (int mt = 0; mt < 4; mt++)
        #pragma unroll
        for (int nt = 0; nt < 8; nt++)
            #pragma unroll
            for (int q = 0; q < 4; q++) acc[mt][nt][q] = 0.f;

    int T = K / GBK;
    gemm_load_tile(Ab, Bb, K, 0, sbase, tid);
    gemm_load_tile(Ab, Bb, K, 1, sbase + STAGE_B, tid);

    for (int t = 0; t < T; t++) {
        CP_WAIT(1);
        __syncthreads();
        if (t + 2 < T)
            gemm_load_tile(Ab, Bb, K, t + 2, sbase + ((t + 2) % GSTG) * STAGE_B, tid);
        uint32_t sa = sbase + (t % GSTG) * STAGE_B;
        uint32_t sb = sa + TB_A;

        #pragma unroll
        for (int ks = 0; ks < 4; ks++) {
            uint32_t afr[4][4];
            #pragma unroll
            for (int mt = 0; mt < 4; mt++) {
                uint32_t row = (uint32_t)(a_row + mt * 16);
                uint32_t c = (uint32_t)ks * 32 + a_kb;
                ldsm_x4(afr[mt], sa + row * 128 + (c ^ ((row & 7) << 4)));
            }
            uint32_t bfr[4][4];
            #pragma unroll
            for (int nh = 0; nh < 4; nh++) {
                uint32_t row = (uint32_t)(b_row + nh * 16);
                uint32_t c = (uint32_t)ks * 32 + b_kb;
                ldsm_x4(bfr[nh], sb + row * 128 + (c ^ ((row & 7) << 4)));
            }
            #pragma unroll
            for (int mt = 0; mt < 4; mt++)
                #pragma unroll
                for (int nt = 0; nt < 8; nt++)
                    mma_tf32(acc[mt][nt], afr[mt], &bfr[nt >> 1][(nt & 1) * 2]);
        }
    }

    int g = lane >> 2, tg = lane & 3;
    #pragma unroll
    for (int mt = 0; mt < 4; mt++) {
        int rowa = m0 + wm + mt * 16 + g;
        #pragma unroll
        for (int nt = 0; nt < 8; nt++) {
            int col = n0 + wn + nt * 8 + tg * 2;
            *(float2*)(C + (size_t)rowa * ldc + col) =
                make_float2(acc[mt][nt][0], acc[mt][nt][1]);
            *(float2*)(C + (size_t)(rowa + 8) * ldc + col) =
                make_float2(acc[mt][nt][2], acc[mt][nt][3]);
        }
    }
}

// ============ fused SSD y-kernel: Y = att @ X  +  Ce @ P^T (tensor cores, tf32) ============
// Decay factored through per-j-tile anchors to cut MUFU ~10x:
//   exp(ci - cj) = exp(ci - ca) * exp(ca - cj), ca = cum[j0+31]; both factors <= 1
//   whenever the i-row is at/after the tile end (gi >= j0+31).
__global__ __launch_bounds__(256, 1) void k_yfused() {
    __shared__ __align__(16) float As[128 * 32];
    __shared__ __align__(16) float Bs[128 * 32];
    __shared__ float gj_all[256];   // exp(ca(tile) - cj) * dt_j
    __shared__ float cas[8];        // per-tile anchors
    int bc = blockIdx.x, h = blockIdx.y, ih = blockIdx.z;
    int i_base = ih * 128;
    int row0 = bc * CHUNK;
    int cb = (bc * NHEADS + h) * CHUNK;
    size_t psb = (size_t)(bc * NHEADS + h) * HEADDIM * D_STATE;

    int tid = threadIdx.x, lane = tid & 31, wid = tid >> 5;
    int wm = (wid & 3) * 32;
    int wn = (wid >> 2) * 64;

    int si = tid >> 1;
    int sj = (tid & 1) * 16;
    int gi = i_base + si;
    float ci = g_cum[cb + gi];
    float ei = __expf(ci);

    uint32_t as_base = smem_u32(As);
    uint32_t bs_base = smem_u32(Bs);

    int a_row = wm + (lane & 15);
    uint32_t a_kb = (uint32_t)(lane >> 4) * 16;
    int b_row = wn + (lane & 7) + ((lane & 16) ? 8 : 0);
    uint32_t b_kb = (lane & 8) ? 16u : 0u;

    int natt = ih ? 8 : 4;

    // --- one-time precompute: anchors + per-j factors ---
    if (tid < natt * 32) {
        int j = tid;
        float ca = g_cum[cb + (j & ~31) + 31];
        gj_all[j] = __expf(ca - g_cum[cb + j]) *
                    g_dt[(size_t)(row0 + j) * NHEADS + h];
    }
    if (tid < natt) cas[tid] = g_cum[cb + tid * 32 + 31];

    float acc[2][8][4];
    #pragma unroll
    for (int mt = 0; mt < 2; mt++)
        #pragma unroll
        for (int nt = 0; nt < 8; nt++)
            #pragma unroll
            for (int q = 0; q < 4; q++) acc[mt][nt][q] = 0.f;

    int ntiles = natt + 2;
    for (int kt = 0; kt < ntiles; kt++) {
        __syncthreads();
        if (kt < natt) {
            int j0 = kt * 32;
            // --- A tile: att[i][j] ---
            if (gi >= j0 + 31) {
                float fi = __expf(ci - cas[kt]);
                const float* Srow = g_S + ((size_t)bc * CHUNK + gi) * CHUNK + j0 + sj;
                const float* gjp = gj_all + j0 + sj;
                #pragma unroll
                for (int q = 0; q < 4; q++) {
                    float4 sv = *(const float4*)(Srow + q * 4);
                    float tmp[4];
                    tmp[0] = to_tf32(sv.x * fi * gjp[q * 4 + 0]);
                    tmp[1] = to_tf32(sv.y * fi * gjp[q * 4 + 1]);
                    tmp[2] = to_tf32(sv.z * fi * gjp[q * 4 + 2]);
                    tmp[3] = to_tf32(sv.w * fi * gjp[q * 4 + 3]);
                    uint32_t cb4 = (uint32_t)(sj + q * 4) * 4;
                    uint32_t off = (uint32_t)si * 128 + (cb4 ^ (((uint32_t)si & 7) << 4));
                    *(float4*)((char*)As + off) = make_float4(tmp[0], tmp[1], tmp[2], tmp[3]);
                }
            } else if (gi >= j0) {
                // diagonal-crossing row: direct per-element exp with causal mask
                #pragma unroll
                for (int q = 0; q < 4; q++) {
                    float tmp[4];
                    #pragma unroll
                    for (int r = 0; r < 4; r++) {
                        int j = j0 + sj + q * 4 + r;
                        float a = 0.f;
                        if (j <= gi)
                            a = g_S[((size_t)bc * CHUNK + gi) * CHUNK + j] *
                                __expf(ci - g_cum[cb + j]) *
                                g_dt[(size_t)(row0 + j) * NHEADS + h];
                        tmp[r] = to_tf32(a);
                    }
                    uint32_t cb4 = (uint32_t)(sj + q * 4) * 4;
                    uint32_t off = (uint32_t)si * 128 + (cb4 ^ (((uint32_t)si & 7) << 4));
                    *(float4*)((char*)As + off) = make_float4(tmp[0], tmp[1], tmp[2], tmp[3]);
                }
            } else {
                // fully-future tile for this row: zeros
                #pragma unroll
                for (int q = 0; q < 4; q++) {
                    uint32_t cb4 = (uint32_t)(sj + q * 4) * 4;
                    uint32_t off = (uint32_t)si * 128 + (cb4 ^ (((uint32_t)si & 7) << 4));
                    *(float4*)((char*)As + off) = make_float4(0.f, 0.f, 0.f, 0.f);
                }
            }
            // --- B tile: Xt[p][j] (transposed stage) ---
            int jw = wid;
            #pragma unroll
            for (int jp = 0; jp < 4; jp++) {
                int j = jw + 8 * jp;
                const float* xrow = g_xBC + (size_t)(row0 + j0 + j) * CONVDIM + h * HEADDIM;
                #pragma unroll
                for (int r = 0; r < 4; r++) {
                    int p = lane + 32 * r;
                    float v = to_tf32(xrow[p]);
                    uint32_t cb4 = (uint32_t)j * 4;
                    uint32_t off = (uint32_t)p * 128 + (cb4 ^ (((uint32_t)p & 7) << 4));
                    *(float*)((char*)Bs + off) = v;
                }
            }
        } else {
            int n0 = (kt - natt) * 32;
            const float* crow = g_xBC + (size_t)(row0 + gi) * CONVDIM + D_INNER + D_STATE;
            #pragma unroll
            for (int q = 0; q < 4; q++) {
                float tmp[4];
                #pragma unroll
                for (int r = 0; r < 4; r++)
                    tmp[r] = to_tf32(crow[n0 + sj + q * 4 + r] * ei);
                uint32_t cb4 = (uint32_t)(sj + q * 4) * 4;
                uint32_t off = (uint32_t)si * 128 + (cb4 ^ (((uint32_t)si & 7) << 4));
                *(float4*)((char*)As + off) = make_float4(tmp[0], tmp[1], tmp[2], tmp[3]);
            }
            int pr = tid >> 1;
            int nc = (tid & 1) * 16;
            const float* prow = g_ps + psb + (size_t)pr * D_STATE + n0;
            #pragma unroll
            for (int q = 0; q < 4; q++) {
                float4 v = *(const float4*)(prow + nc + q * 4);
                v.x = to_tf32(v.x); v.y = to_tf32(v.y);
                v.z = to_tf32(v.z); v.w = to_tf32(v.w);
                uint32_t cb4 = (uint32_t)(nc + q * 4) * 4;
                uint32_t off = (uint32_t)pr * 128 + (cb4 ^ (((uint32_t)pr & 7) << 4));
                *(float4*)((char*)Bs + off) = v;
            }
        }
        __syncthreads();
        #pragma unroll
        for (int ks = 0; ks < 4; ks++) {
            uint32_t afr[2][4];
            #pragma unroll
            for (int mt = 0; mt < 2; mt++) {
                uint32_t row = (uint32_t)(a_row + mt * 16);
                uint32_t c = (uint32_t)ks * 32 + a_kb;
                ldsm_x4(afr[mt], as_base + row * 128 + (c ^ ((row & 7) << 4)));
            }
            uint32_t bfr[4][4];
            #pragma unroll
            for (int nh = 0; nh < 4; nh++) {
                uint32_t row = (uint32_t)(b_row + nh * 16);
                uint32_t c = (uint32_t)ks * 32 + b_kb;
                ldsm_x4(bfr[nh], bs_base + row * 128 + (c ^ ((row & 7) << 4)));
            }
            #pragma unroll
            for (int mt = 0; mt < 2; mt++)
                #pragma unroll
                for (int nt = 0; nt < 8; nt++)
                    mma_tf32(acc[mt][nt], afr[mt], &bfr[nt >> 1][(nt & 1) * 2]);
        }
    }

    int g = lane >> 2, tg = lane & 3;
    #pragma unroll
    for (int mt = 0; mt < 2; mt++) {
        int orow = row0 + i_base + wm + mt * 16 + g;
        #pragma unroll
        for (int nt = 0; nt < 8; nt++) {
            int col = h * HEADDIM + wn + nt * 8 + tg * 2;
            *(float2*)(g_y + (size_t)orow * D_INNER + col) =
                make_float2(acc[mt][nt][0], acc[mt][nt][1]);
            *(float2*)(g_y + (size_t)(orow + 8) * D_INNER + col) =
                make_float2(acc[mt][nt][2], acc[mt][nt][3]);
        }
    }
}

// ---------------- reductions ----------------
__device__ __forceinline__ float blockReduceSum256(float v) {
    __shared__ float red[8];
    __shared__ float tot;
    int lane = threadIdx.x & 31, wid = threadIdx.x >> 5;
    #pragma unroll
    for (int o = 16; o; o >>= 1) v += __shfl_down_sync(0xffffffffu, v, o);
    if (lane == 0) red[wid] = v;
    __syncthreads();
    if (wid == 0) {
        float w = (lane < 8) ? red[lane] : 0.f;
        #pragma unroll
        for (int o = 4; o; o >>= 1) w += __shfl_down_sync(0xffffffffu, w, o);
        if (lane == 0) tot = w;
    }
    __syncthreads();
    return tot;
}

// ---------------- K1: l2-normalize weight rows ----------------
__global__ __launch_bounds__(256) void k_normw(const float* __restrict__ W,
                                               float* __restrict__ Wo, int K, float extra) {
    int r = blockIdx.x;
    const float* wr = W + (size_t)r * K;
    float s2 = 0.f;
    for (int i = threadIdx.x; i < K; i += 256) { float v = wr[i]; s2 += v * v; }
    float totv = blockReduceSum256(s2);
    float sc = extra / fmaxf(sqrtf(totv), 1e-6f);
    for (int i = threadIdx.x; i < K; i += 256) Wo[(size_t)r * K + i] = to_tf32(wr[i] * sc);
}

// ---------------- K2: layernorm ----------------
__global__ __launch_bounds__(256) void k_layernorm(const float* __restrict__ u,
                                                   const float* __restrict__ w,
                                                   const float* __restrict__ b) {
    int row = blockIdx.x;
    const float* ur = u + (size_t)row * XDIM;
    float v[4]; float s = 0.f, s2 = 0.f;
    #pragma unroll
    for (int k = 0; k < 4; k++) {
        v[k] = ur[threadIdx.x + 256 * k];
        s += v[k]; s2 += v[k] * v[k];
    }
    float sum = blockReduceSum256(s);
    float sumsq = blockReduceSum256(s2);
    float mu = sum * (1.f / XDIM);
    float var = sumsq * (1.f / XDIM) - mu * mu;
    float inv = rsqrtf(var + 1e-5f);
    #pragma unroll
    for (int k = 0; k < 4; k++) {
        int d = threadIdx.x + 256 * k;
        g_ln[(size_t)row * XDIM + d] = to_tf32((v[k] - mu) * inv * w[d] + b[d]);
    }
}

// ---------------- K4: depthwise causal conv + bias + silu ----------------
__global__ __launch_bounds__(256) void k_conv(const float* __restrict__ cw,
                                              const float* __restrict__ cb) {
    int gi = blockIdx.x * 256 + threadIdx.x;
    if (gi >= R_TOT * CONVDIM) return;
    int ch = gi % CONVDIM;
    int row = gi / CONVDIM;
    int l = row & (SEQLEN - 1);
    float acc = cb[ch];
    #pragma unroll
    for (int d = 0; d < 4; d++) {
        int ll = l - 3 + d;
        if (ll >= 0)
            acc += cw[ch * 4 + d] * g_zx[(size_t)(row - 3 + d) * DPROJP + D_INNER + ch];
    }
    g_xBC[(size_t)row * CONVDIM + ch] = acc / (1.f + __expf(-acc));
}

// ---------------- K5: dt softplus + per-chunk cumulative dA ----------------
__global__ __launch_bounds__(256) void k_dtcum(const float* __restrict__ dt_bias,
                                               const float* __restrict__ A_log) {
    int bch = blockIdx.x;
    int h = bch & 15, bc = bch >> 4;
    int t = threadIdx.x;
    int row = bc * CHUNK + t;
    float x = g_zx[(size_t)row * DPROJP + (D_INNER + CONVDIM) + h] + dt_bias[h];
    float dtv = (x > 20.f) ? x : log1pf(expf(x));
    g_dt[(size_t)row * NHEADS + h] = dtv;
    float dA = dtv * (-expf(A_log[h]));
    __shared__ float s[256];
    s[t] = dA;
    __syncthreads();
    #pragma unroll
    for (int off = 1; off < 256; off <<= 1) {
        float pv = (t >= off) ? s[t - off] : 0.f;
        __syncthreads();
        s[t] += pv;
        __syncthreads();
    }
    g_cum[(size_t)bch * CHUNK + t] = s[t];
    if (t == 255) g_cdec[bch] = __expf(s[255]);
}

// ---------------- K6a: scores S = C @ B^T ----------------
__global__ __launch_bounds__(256) void k_scores() {
    if (blockIdx.z > blockIdx.y) return;
    int bc = blockIdx.x, i0 = blockIdx.y * 64, j0 = blockIdx.z * 64;
    __shared__ float Ct[64][65];
    __shared__ float Bt[64][65];
    int row0 = bc * CHUNK;
    for (int idx = threadIdx.x; idx < 4096; idx += 256) {
        int n = idx & 63, r = idx >> 6;
        Ct[n][r] = g_xBC[(size_t)(row0 + i0 + r) * CONVDIM + D_INNER + 64 + n];
        Bt[n][r] = g_xBC[(size_t)(row0 + j0 + r) * CONVDIM + D_INNER + n];
    }
    __syncthreads();
    int ty = threadIdx.x >> 4, tx = threadIdx.x & 15;
    float acc[4][4];
    #pragma unroll
    for (int i = 0; i < 4; i++)
        #pragma unroll
        for (int j = 0; j < 4; j++) acc[i][j] = 0.f;
    #pragma unroll 4
    for (int n = 0; n < 64; n++) {
        float a[4], b[4];
        #pragma unroll
        for (int i = 0; i < 4; i++) a[i] = Ct[n][ty * 4 + i];
        #pragma unroll
        for (int j = 0; j < 4; j++) b[j] = Bt[n][tx * 4 + j];
        #pragma unroll
        for (int i = 0; i < 4; i++)
            #pragma unroll
            for (int j = 0; j < 4; j++) acc[i][j] += a[i] * b[j];
    }
    #pragma unroll
    for (int i = 0; i < 4; i++)
        *(float4*)(g_S + ((size_t)bc * CHUNK + i0 + ty * 4 + i) * CHUNK + j0 + tx * 4) =
            make_float4(acc[i][0], acc[i][1], acc[i][2], acc[i][3]);
}

// ---------------- K7: per-chunk states ----------------
__global__ __launch_bounds__(256) void k_states() {
    int bc = blockIdx.x, h = blockIdx.y;
    __shared__ __align__(16) float xs[16][128];
    __shared__ float4 Bs4[16][16];
    __shared__ float wsh[16];
    int row0 = bc * CHUNK;
    int cb = (bc * NHEADS + h) * CHUNK;
    int tid = threadIdx.x;
    float cum_last = g_cum[cb + 255];
    int p = tid >> 1, nq = tid & 1;
    float4 acc[8];
    #pragma unroll
    for (int k = 0; k < 8; k++) acc[k] = make_float4(0.f, 0.f, 0.f, 0.f);
    for (int tt = 0; tt < 16; tt++) {
        int t0 = tt * 16;
        __syncthreads();
        #pragma unroll
        for (int ps = 0; ps < 2; ps++) {
            int idx = tid + ps * 256;
            int jr = idx >> 5, c = idx & 31;
            ((float4*)xs[jr])[c] = ((const float4*)(g_xBC + (size_t)(row0 + t0 + jr) * CONVDIM + h * HEADDIM))[c];
        }
        {
            int jr = tid >> 4, c = tid & 15;
            Bs4[jr][c] = ((const float4*)(g_xBC + (size_t)(row0 + t0 + jr) * CONVDIM + D_INNER))[c];
        }
        if (tid < 16) {
            int t = t0 + tid;
            wsh[tid] = g_dt[(size_t)(row0 + t) * NHEADS + h] * __expf(cum_last - g_cum[cb + t]);
        }
        __syncthreads();
        #pragma unroll
        for (int t = 0; t < 16; t++) {
            float xv = xs[t][p] * wsh[t];
            #pragma unroll
            for (int k = 0; k < 8; k++) {
                float4 b = Bs4[t][nq + 2 * k];
                acc[k].x += xv * b.x; acc[k].y += xv * b.y;
                acc[k].z += xv * b.z; acc[k].w += xv * b.w;
            }
        }
    }
    float4* sp = (float4*)(g_st + ((size_t)(bc * NHEADS + h) * HEADDIM + p) * D_STATE);
    #pragma unroll
    for (int k = 0; k < 8; k++) sp[nq + 2 * k] = acc[k];
}

// ---------------- K8: serial inter-chunk scan ----------------
__global__ __launch_bounds__(256) void k_scan() {
    int b = blockIdx.x, h = blockIdx.y;
    int tid = threadIdx.x;
    float carry[32];
    #pragma unroll
    for (int k = 0; k < 32; k++) carry[k] = 0.f;
    for (int c = 0; c < NCPB; c++) {
        int bch = (b * NCPB + c) * NHEADS + h;
        float dec = g_cdec[bch];
        size_t base = (size_t)bch * HEADDIM * D_STATE;
        #pragma unroll
        for (int k = 0; k < 32; k++) {
            int e = tid + 256 * k;
            g_ps[base + e] = carry[k];
            carry[k] = carry[k] * dec + g_st[base + e];
        }
    }
}

// ---------------- K10: y += D*x, gate, RMS norm ----------------
__global__ __launch_bounds__(256) void k_gate(const float* __restrict__ Dp,
                                              const float* __restrict__ rms_w) {
    int row = blockIdx.x;
    int tid = threadIdx.x;
    float gg[8];
    float s2 = 0.f;
    #pragma unroll
    for (int k = 0; k < 8; k++) {
        int d = tid + 256 * k;
        float xv = g_xBC[(size_t)row * CONVDIM + d];
        float v = g_y[(size_t)row * D_INNER + d] + Dp[d >> 7] * xv;
        float z = g_zx[(size_t)row * DPROJP + d];
        float sil = z / (1.f + __expf(-z));
        float g = v * sil;
        gg[k] = g;
        s2 += g * g;
    }
    float tot = blockReduceSum256(s2);
    float sc = rsqrtf(tot * (1.f / D_INNER) + 1e-5f);
    #pragma unroll
    for (int k = 0; k < 8; k++) {
        int d = tid + 256 * k;
        g_g[(size_t)row * D_INNER + d] = to_tf32(gg[k] * sc * rms_w[d]);
    }
}

// ---------------- host launcher ----------------
extern "C" void kernel_launch(void* const* d_in, const int* in_sizes, int n_in,
                              void* d_out, int out_size) {
    const float* u          = (const float*)d_in[0];
    const float* in_proj_w  = (const float*)d_in[1];
    const float* conv_w     = (const float*)d_in[2];
    const float* conv_b     = (const float*)d_in[3];
    const float* dt_bias    = (const float*)d_in[4];
    const float* A_log      = (const float*)d_in[5];
    const float* Dp         = (const float*)d_in[6];
    const float* xnw        = (const float*)d_in[7];
    const float* xnb        = (const float*)d_in[8];
    const float* rms_w      = (const float*)d_in[9];
    const float* out_proj_w = (const float*)d_in[10];
    float* out = (float*)d_out;

    float *pWin, *pWout, *pLn, *pZx, *pG;
    cudaGetSymbolAddress((void**)&pWin,  g_Win);
    cudaGetSymbolAddress((void**)&pWout, g_Wout);
    cudaGetSymbolAddress((void**)&pLn,   g_ln);
    cudaGetSymbolAddress((void**)&pZx,   g_zx);
    cudaGetSymbolAddress((void**)&pG,    g_g);

    static int smem_set = 0;
    if (!smem_set) {
        cudaFuncSetAttribute(gemm_tc, cudaFuncAttributeMaxDynamicSharedMemorySize, GEMM_SMEM);
        smem_set = 1;
    }

    k_normw<<<DPROJ, 256>>>(in_proj_w, pWin, XDIM, 0.03125f);
    k_normw<<<XDIM, 256>>>(out_proj_w, pWout, D_INNER, 1.0f);

    k_layernorm<<<R_TOT, 256>>>(u, xnw, xnb);

    gemm_tc<<<dim3(DPROJP / GBN, R_TOT / GBM), 128, GEMM_SMEM>>>(pLn, pWin, pZx, XDIM, DPROJP);

    k_conv<<<(R_TOT * CONVDIM + 255) / 256, 256>>>(conv_w, conv_b);
    k_dtcum<<<NBC * NHEADS, 256>>>(dt_bias, A_log);

    k_scores<<<dim3(NBC, 4, 4), 256>>>();
    k_states<<<dim3(NBC, NHEADS), 256>>>();
    k_scan<<<dim3(NBATCH, NHEADS), 256>>>();
    k_yfused<<<dim3(NBC, NHEADS, 2), 256>>>();

    k_gate<<<R_TOT, 256>>>(Dp, rms_w);

    gemm_tc<<<dim3(XDIM / GBN, R_TOT / GBM), 128, GEMM_SMEM>>>(pG, pWout, out, D_INNER, XDIM);
}

// round 7
// speedup vs baseline: 4.6865x; 1.3343x over previous
#include <cuda_runtime.h>
#include <cuda_fp16.h>
#include <math.h>
#include <stdint.h>

// ---------------- problem constants ----------------
#define XDIM    1024
#define D_STATE 64
#define HEADDIM 128
#define D_INNER 2048
#define NHEADS  16
#define CONVDIM 2176              // D_INNER + 2*64
#define DPROJ   4240              // 2*2048 + 2*64 + 16
#define DPROJP  4352              // padded to 128-multiple for GEMM tiles
#define CHUNK   256
#define NBATCH  2
#define SEQLEN  4096
#define NCPB    16
#define NBC     32
#define R_TOT   8192

// ---------------- device scratch ----------------
__device__ __half g_lnh [(size_t)R_TOT * XDIM];
__device__ __half g_Winh[(size_t)DPROJP * XDIM];     // rows >= DPROJ stay zero (.bss)
__device__ __half g_Wouth[(size_t)XDIM * D_INNER];
__device__ __half g_gh  [(size_t)R_TOT * D_INNER];
__device__ float g_zx  [(size_t)R_TOT * DPROJP];
__device__ float g_xBC [(size_t)R_TOT * CONVDIM];
__device__ float g_dt  [(size_t)R_TOT * NHEADS];
__device__ float g_cum [(size_t)NBC * NHEADS * CHUNK];
__device__ float g_cdec[(size_t)NBC * NHEADS];
__device__ float g_S   [(size_t)NBC * CHUNK * CHUNK];
__device__ float g_y   [(size_t)R_TOT * D_INNER];
__device__ float g_st  [(size_t)NBC * NHEADS * HEADDIM * D_STATE];
__device__ float g_ps  [(size_t)NBC * NHEADS * HEADDIM * D_STATE];

// ---------------- PTX helpers (baseline PTX only) ----------------
__device__ __forceinline__ uint32_t smem_u32(const void* p) {
    uint32_t a;
    asm("{ .reg .u64 t; cvta.to.shared.u64 t, %1; cvt.u32.u64 %0, t; }" : "=r"(a) : "l"(p));
    return a;
}
__device__ __forceinline__ float to_tf32(float x) {
    uint32_t r;
    asm("cvt.rna.tf32.f32 %0, %1;" : "=r"(r) : "f"(x));
    return __uint_as_float(r);
}
#define CP_ASYNC16(s, g) \
    asm volatile("cp.async.cg.shared.global [%0], [%1], 16;" :: "r"(s), "l"(g))
#define CP_COMMIT() asm volatile("cp.async.commit_group;" ::: "memory")
#define CP_WAIT(n)  asm volatile("cp.async.wait_group %0;" :: "n"(n) : "memory")

__device__ __forceinline__ void ldsm_x4(uint32_t* r, uint32_t addr) {
    asm volatile("ldmatrix.sync.aligned.m8n8.x4.shared.b16 {%0,%1,%2,%3}, [%4];"
        : "=r"(r[0]), "=r"(r[1]), "=r"(r[2]), "=r"(r[3]) : "r"(addr));
}
__device__ __forceinline__ void mma_tf32(float* d, const uint32_t* a, const uint32_t* b) {
    asm volatile("mma.sync.aligned.m16n8k8.row.col.f32.tf32.tf32.f32 "
        "{%0,%1,%2,%3},{%4,%5,%6,%7},{%8,%9},{%0,%1,%2,%3};"
        : "+f"(d[0]), "+f"(d[1]), "+f"(d[2]), "+f"(d[3])
        : "r"(a[0]), "r"(a[1]), "r"(a[2]), "r"(a[3]), "r"(b[0]), "r"(b[1]));
}
__device__ __forceinline__ void mma_fp16(float* d, const uint32_t* a, const uint32_t* b) {
    asm volatile("mma.sync.aligned.m16n8k16.row.col.f32.f16.f16.f32 "
        "{%0,%1,%2,%3},{%4,%5,%6,%7},{%8,%9},{%0,%1,%2,%3};"
        : "+f"(d[0]), "+f"(d[1]), "+f"(d[2]), "+f"(d[3])
        : "r"(a[0]), "r"(a[1]), "r"(a[2]), "r"(a[3]), "r"(b[0]), "r"(b[1]));
}

// ================= fp16 tensor-core GEMM: C[M,N] = A[M,K] * B[N,K]^T =================
// 128x128x64 CTA tile (fp16: 64 k-elems = 128 bytes/row), 4 warps (64x64 warp tile),
// 3-stage cp.async pipeline, 2 CTAs/SM. fp32 accumulate.
#define GBM 128
#define GBN 128
#define GBK 64
#define GSTG 3
#define TB_A (GBM * GBK * 2)            // 16384 bytes
#define TB_B (GBN * GBK * 2)
#define STAGE_B (TB_A + TB_B)           // 32768
#define GEMM_SMEM (GSTG * STAGE_B)      // 98304

__device__ __forceinline__ void gemm_load_tile_h(const __half* Ab, const __half* Bb,
                                                 int K, int t, uint32_t sb, int tid) {
    const __half* Ap = Ab + (size_t)t * GBK;
    const __half* Bp = Bb + (size_t)t * GBK;
    #pragma unroll
    for (int j = 0; j < 8; j++) {
        int c = tid + 128 * j;
        int row = c >> 3;
        uint32_t cc = (uint32_t)(c & 7) * 16;          // byte offset in 128B row
        uint32_t off = (uint32_t)row * 128 + (cc ^ (((uint32_t)row & 7) << 4));
        CP_ASYNC16(sb + off, Ap + (size_t)row * K + (cc >> 1));
    }
    uint32_t sb2 = sb + TB_A;
    #pragma unroll
    for (int j = 0; j < 8; j++) {
        int c = tid + 128 * j;
        int row = c >> 3;
        uint32_t cc = (uint32_t)(c & 7) * 16;
        uint32_t off = (uint32_t)row * 128 + (cc ^ (((uint32_t)row & 7) << 4));
        CP_ASYNC16(sb2 + off, Bp + (size_t)row * K + (cc >> 1));
    }
    CP_COMMIT();
}

__global__ __launch_bounds__(128, 2) void gemm_hc(const __half* __restrict__ A,
                                                  const __half* __restrict__ B,
                                                  float* __restrict__ C,
                                                  int K, int ldc) {
    extern __shared__ char sm[];
    uint32_t sbase = smem_u32(sm);
    int tid = threadIdx.x, lane = tid & 31, wid = tid >> 5;
    int wm = (wid & 1) * 64;
    int wn = (wid >> 1) * 64;
    int m0 = blockIdx.y * GBM;
    int n0 = blockIdx.x * GBN;
    const __half* Ab = A + (size_t)m0 * K;
    const __half* Bb = B + (size_t)n0 * K;

    // fp16 m16n8k16 ldmatrix address pattern (same shape as tf32 variant)
    int a_row = wm + (lane & 15);
    uint32_t a_kb = (uint32_t)(lane >> 4) * 16;
    int b_row = wn + (lane & 7) + ((lane & 16) ? 8 : 0);
    uint32_t b_kb = (lane & 8) ? 16u : 0u;

    float acc[4][8][4];
    #pragma unroll
    for (int mt = 0; mt < 4; mt++)
        #pragma unroll
        for (int nt = 0; nt < 8; nt++)
            #pragma unroll
            for (int q = 0; q < 4; q++) acc[mt][nt][q] = 0.f;

    int T = K / GBK;
    gemm_load_tile_h(Ab, Bb, K, 0, sbase, tid);
    gemm_load_tile_h(Ab, Bb, K, 1, sbase + STAGE_B, tid);

    for (int t = 0; t < T; t++) {
        CP_WAIT(1);
        __syncthreads();
        if (t + 2 < T)
            gemm_load_tile_h(Ab, Bb, K, t + 2, sbase + ((t + 2) % GSTG) * STAGE_B, tid);
        uint32_t sa = sbase + (t % GSTG) * STAGE_B;
        uint32_t sb = sa + TB_A;

        #pragma unroll
        for (int ks = 0; ks < 4; ks++) {               // 4 x k16 = 64
            uint32_t afr[4][4];
            #pragma unroll
            for (int mt = 0; mt < 4; mt++) {
                uint32_t row = (uint32_t)(a_row + mt * 16);
                uint32_t c = (uint32_t)ks * 32 + a_kb;
                ldsm_x4(afr[mt], sa + row * 128 + (c ^ ((row & 7) << 4)));
            }
            uint32_t bfr[4][4];
            #pragma unroll
            for (int nh = 0; nh < 4; nh++) {
                uint32_t row = (uint32_t)(b_row + nh * 16);
                uint32_t c = (uint32_t)ks * 32 + b_kb;
                ldsm_x4(bfr[nh], sb + row * 128 + (c ^ ((row & 7) << 4)));
            }
            #pragma unroll
            for (int mt = 0; mt < 4; mt++)
                #pragma unroll
                for (int nt = 0; nt < 8; nt++)
                    mma_fp16(acc[mt][nt], afr[mt], &bfr[nt >> 1][(nt & 1) * 2]);
        }
    }

    int g = lane >> 2, tg = lane & 3;
    #pragma unroll
    for (int mt = 0; mt < 4; mt++) {
        int rowa = m0 + wm + mt * 16 + g;
        #pragma unroll
        for (int nt = 0; nt < 8; nt++) {
            int col = n0 + wn + nt * 8 + tg * 2;
            *(float2*)(C + (size_t)rowa * ldc + col) =
                make_float2(acc[mt][nt][0], acc[mt][nt][1]);
            *(float2*)(C + (size_t)(rowa + 8) * ldc + col) =
                make_float2(acc[mt][nt][2], acc[mt][nt][3]);
        }
    }
}

// ============ fused SSD y-kernel: Y = att @ X  +  Ce @ P^T (tensor cores, tf32) ============
__global__ __launch_bounds__(256, 1) void k_yfused() {
    __shared__ __align__(16) float As[128 * 32];
    __shared__ __align__(16) float Bs[128 * 32];
    __shared__ float gj_all[256];
    __shared__ float cas[8];
    int bc = blockIdx.x, h = blockIdx.y, ih = blockIdx.z;
    int i_base = ih * 128;
    int row0 = bc * CHUNK;
    int cb = (bc * NHEADS + h) * CHUNK;
    size_t psb = (size_t)(bc * NHEADS + h) * HEADDIM * D_STATE;

    int tid = threadIdx.x, lane = tid & 31, wid = tid >> 5;
    int wm = (wid & 3) * 32;
    int wn = (wid >> 2) * 64;

    int si = tid >> 1;
    int sj = (tid & 1) * 16;
    int gi = i_base + si;
    float ci = g_cum[cb + gi];
    float ei = __expf(ci);

    uint32_t as_base = smem_u32(As);
    uint32_t bs_base = smem_u32(Bs);

    int a_row = wm + (lane & 15);
    uint32_t a_kb = (uint32_t)(lane >> 4) * 16;
    int b_row = wn + (lane & 7) + ((lane & 16) ? 8 : 0);
    uint32_t b_kb = (lane & 8) ? 16u : 0u;

    int natt = ih ? 8 : 4;

    if (tid < natt * 32) {
        int j = tid;
        float ca = g_cum[cb + (j & ~31) + 31];
        gj_all[j] = __expf(ca - g_cum[cb + j]) *
                    g_dt[(size_t)(row0 + j) * NHEADS + h];
    }
    if (tid < natt) cas[tid] = g_cum[cb + tid * 32 + 31];

    float acc[2][8][4];
    #pragma unroll
    for (int mt = 0; mt < 2; mt++)
        #pragma unroll
        for (int nt = 0; nt < 8; nt++)
            #pragma unroll
            for (int q = 0; q < 4; q++) acc[mt][nt][q] = 0.f;

    int ntiles = natt + 2;
    for (int kt = 0; kt < ntiles; kt++) {
        __syncthreads();
        if (kt < natt) {
            int j0 = kt * 32;
            if (gi >= j0 + 31) {
                float fi = __expf(ci - cas[kt]);
                const float* Srow = g_S + ((size_t)bc * CHUNK + gi) * CHUNK + j0 + sj;
                const float* gjp = gj_all + j0 + sj;
                #pragma unroll
                for (int q = 0; q < 4; q++) {
                    float4 sv = *(const float4*)(Srow + q * 4);
                    float tmp[4];
                    tmp[0] = to_tf32(sv.x * fi * gjp[q * 4 + 0]);
                    tmp[1] = to_tf32(sv.y * fi * gjp[q * 4 + 1]);
                    tmp[2] = to_tf32(sv.z * fi * gjp[q * 4 + 2]);
                    tmp[3] = to_tf32(sv.w * fi * gjp[q * 4 + 3]);
                    uint32_t cb4 = (uint32_t)(sj + q * 4) * 4;
                    uint32_t off = (uint32_t)si * 128 + (cb4 ^ (((uint32_t)si & 7) << 4));
                    *(float4*)((char*)As + off) = make_float4(tmp[0], tmp[1], tmp[2], tmp[3]);
                }
            } else if (gi >= j0) {
                #pragma unroll
                for (int q = 0; q < 4; q++) {
                    float tmp[4];
                    #pragma unroll
                    for (int r = 0; r < 4; r++) {
                        int j = j0 + sj + q * 4 + r;
                        float a = 0.f;
                        if (j <= gi)
                            a = g_S[((size_t)bc * CHUNK + gi) * CHUNK + j] *
                                __expf(ci - g_cum[cb + j]) *
                                g_dt[(size_t)(row0 + j) * NHEADS + h];
                        tmp[r] = to_tf32(a);
                    }
                    uint32_t cb4 = (uint32_t)(sj + q * 4) * 4;
                    uint32_t off = (uint32_t)si * 128 + (cb4 ^ (((uint32_t)si & 7) << 4));
                    *(float4*)((char*)As + off) = make_float4(tmp[0], tmp[1], tmp[2], tmp[3]);
                }
            } else {
                #pragma unroll
                for (int q = 0; q < 4; q++) {
                    uint32_t cb4 = (uint32_t)(sj + q * 4) * 4;
                    uint32_t off = (uint32_t)si * 128 + (cb4 ^ (((uint32_t)si & 7) << 4));
                    *(float4*)((char*)As + off) = make_float4(0.f, 0.f, 0.f, 0.f);
                }
            }
            int jw = wid;
            #pragma unroll
            for (int jp = 0; jp < 4; jp++) {
                int j = jw + 8 * jp;
                const float* xrow = g_xBC + (size_t)(row0 + j0 + j) * CONVDIM + h * HEADDIM;
                #pragma unroll
                for (int r = 0; r < 4; r++) {
                    int p = lane + 32 * r;
                    float v = to_tf32(xrow[p]);
                    uint32_t cb4 = (uint32_t)j * 4;
                    uint32_t off = (uint32_t)p * 128 + (cb4 ^ (((uint32_t)p & 7) << 4));
                    *(float*)((char*)Bs + off) = v;
                }
            }
        } else {
            int n0 = (kt - natt) * 32;
            const float* crow = g_xBC + (size_t)(row0 + gi) * CONVDIM + D_INNER + D_STATE;
            #pragma unroll
            for (int q = 0; q < 4; q++) {
                float tmp[4];
                #pragma unroll
                for (int r = 0; r < 4; r++)
                    tmp[r] = to_tf32(crow[n0 + sj + q * 4 + r] * ei);
                uint32_t cb4 = (uint32_t)(sj + q * 4) * 4;
                uint32_t off = (uint32_t)si * 128 + (cb4 ^ (((uint32_t)si & 7) << 4));
                *(float4*)((char*)As + off) = make_float4(tmp[0], tmp[1], tmp[2], tmp[3]);
            }
            int pr = tid >> 1;
            int nc = (tid & 1) * 16;
            const float* prow = g_ps + psb + (size_t)pr * D_STATE + n0;
            #pragma unroll
            for (int q = 0; q < 4; q++) {
                float4 v = *(const float4*)(prow + nc + q * 4);
                v.x = to_tf32(v.x); v.y = to_tf32(v.y);
                v.z = to_tf32(v.z); v.w = to_tf32(v.w);
                uint32_t cb4 = (uint32_t)(nc + q * 4) * 4;
                uint32_t off = (uint32_t)pr * 128 + (cb4 ^ (((uint32_t)pr & 7) << 4));
                *(float4*)((char*)Bs + off) = v;
            }
        }
        __syncthreads();
        #pragma unroll
        for (int ks = 0; ks < 4; ks++) {
            uint32_t afr[2][4];
            #pragma unroll
            for (int mt = 0; mt < 2; mt++) {
                uint32_t row = (uint32_t)(a_row + mt * 16);
                uint32_t c = (uint32_t)ks * 32 + a_kb;
                ldsm_x4(afr[mt], as_base + row * 128 + (c ^ ((row & 7) << 4)));
            }
            uint32_t bfr[4][4];
            #pragma unroll
            for (int nh = 0; nh < 4; nh++) {
                uint32_t row = (uint32_t)(b_row + nh * 16);
                uint32_t c = (uint32_t)ks * 32 + b_kb;
                ldsm_x4(bfr[nh], bs_base + row * 128 + (c ^ ((row & 7) << 4)));
            }
            #pragma unroll
            for (int mt = 0; mt < 2; mt++)
                #pragma unroll
                for (int nt = 0; nt < 8; nt++)
                    mma_tf32(acc[mt][nt], afr[mt], &bfr[nt >> 1][(nt & 1) * 2]);
        }
    }

    int g = lane >> 2, tg = lane & 3;
    #pragma unroll
    for (int mt = 0; mt < 2; mt++) {
        int orow = row0 + i_base + wm + mt * 16 + g;
        #pragma unroll
        for (int nt = 0; nt < 8; nt++) {
            int col = h * HEADDIM + wn + nt * 8 + tg * 2;
            *(float2*)(g_y + (size_t)orow * D_INNER + col) =
                make_float2(acc[mt][nt][0], acc[mt][nt][1]);
            *(float2*)(g_y + (size_t)(orow + 8) * D_INNER + col) =
                make_float2(acc[mt][nt][2], acc[mt][nt][3]);
        }
    }
}

// ---------------- reductions ----------------
__device__ __forceinline__ float blockReduceSum256(float v) {
    __shared__ float red[8];
    __shared__ float tot;
    int lane = threadIdx.x & 31, wid = threadIdx.x >> 5;
    #pragma unroll
    for (int o = 16; o; o >>= 1) v += __shfl_down_sync(0xffffffffu, v, o);
    if (lane == 0) red[wid] = v;
    __syncthreads();
    if (wid == 0) {
        float w = (lane < 8) ? red[lane] : 0.f;
        #pragma unroll
        for (int o = 4; o; o >>= 1) w += __shfl_down_sync(0xffffffffu, w, o);
        if (lane == 0) tot = w;
    }
    __syncthreads();
    return tot;
}

// ---------------- K1: l2-normalize weight rows (fp16 output) ----------------
__global__ __launch_bounds__(256) void k_normw(const float* __restrict__ W,
                                               __half* __restrict__ Wo, int K, float extra) {
    int r = blockIdx.x;
    const float* wr = W + (size_t)r * K;
    float s2 = 0.f;
    for (int i = threadIdx.x; i < K; i += 256) { float v = wr[i]; s2 += v * v; }
    float totv = blockReduceSum256(s2);
    float sc = extra / fmaxf(sqrtf(totv), 1e-6f);
    for (int i = threadIdx.x; i < K; i += 256)
        Wo[(size_t)r * K + i] = __float2half_rn(wr[i] * sc);
}

// ---------------- K2: layernorm (fp16 output) ----------------
__global__ __launch_bounds__(256) void k_layernorm(const float* __restrict__ u,
                                                   const float* __restrict__ w,
                                                   const float* __restrict__ b) {
    int row = blockIdx.x;
    const float* ur = u + (size_t)row * XDIM;
    float v[4]; float s = 0.f, s2 = 0.f;
    #pragma unroll
    for (int k = 0; k < 4; k++) {
        v[k] = ur[threadIdx.x + 256 * k];
        s += v[k]; s2 += v[k] * v[k];
    }
    float sum = blockReduceSum256(s);
    float sumsq = blockReduceSum256(s2);
    float mu = sum * (1.f / XDIM);
    float var = sumsq * (1.f / XDIM) - mu * mu;
    float inv = rsqrtf(var + 1e-5f);
    #pragma unroll
    for (int k = 0; k < 4; k++) {
        int d = threadIdx.x + 256 * k;
        g_lnh[(size_t)row * XDIM + d] = __float2half_rn((v[k] - mu) * inv * w[d] + b[d]);
    }
}

// ---------------- K4: depthwise causal conv + bias + silu ----------------
__global__ __launch_bounds__(256) void k_conv(const float* __restrict__ cw,
                                              const float* __restrict__ cb) {
    int gi = blockIdx.x * 256 + threadIdx.x;
    if (gi >= R_TOT * CONVDIM) return;
    int ch = gi % CONVDIM;
    int row = gi / CONVDIM;
    int l = row & (SEQLEN - 1);
    float acc = cb[ch];
    #pragma unroll
    for (int d = 0; d < 4; d++) {
        int ll = l - 3 + d;
        if (ll >= 0)
            acc += cw[ch * 4 + d] * g_zx[(size_t)(row - 3 + d) * DPROJP + D_INNER + ch];
    }
    g_xBC[(size_t)row * CONVDIM + ch] = acc / (1.f + __expf(-acc));
}

// ---------------- K5: dt softplus + per-chunk cumulative dA ----------------
__global__ __launch_bounds__(256) void k_dtcum(const float* __restrict__ dt_bias,
                                               const float* __restrict__ A_log) {
    int bch = blockIdx.x;
    int h = bch & 15, bc = bch >> 4;
    int t = threadIdx.x;
    int row = bc * CHUNK + t;
    float x = g_zx[(size_t)row * DPROJP + (D_INNER + CONVDIM) + h] + dt_bias[h];
    float dtv = (x > 20.f) ? x : log1pf(expf(x));
    g_dt[(size_t)row * NHEADS + h] = dtv;
    float dA = dtv * (-expf(A_log[h]));
    __shared__ float s[256];
    s[t] = dA;
    __syncthreads();
    #pragma unroll
    for (int off = 1; off < 256; off <<= 1) {
        float pv = (t >= off) ? s[t - off] : 0.f;
        __syncthreads();
        s[t] += pv;
        __syncthreads();
    }
    g_cum[(size_t)bch * CHUNK + t] = s[t];
    if (t == 255) g_cdec[bch] = __expf(s[255]);
}

// ---------------- K6a: scores S = C @ B^T ----------------
__global__ __launch_bounds__(256) void k_scores() {
    if (blockIdx.z > blockIdx.y) return;
    int bc = blockIdx.x, i0 = blockIdx.y * 64, j0 = blockIdx.z * 64;
    __shared__ float Ct[64][65];
    __shared__ float Bt[64][65];
    int row0 = bc * CHUNK;
    for (int idx = threadIdx.x; idx < 4096; idx += 256) {
        int n = idx & 63, r = idx >> 6;
        Ct[n][r] = g_xBC[(size_t)(row0 + i0 + r) * CONVDIM + D_INNER + 64 + n];
        Bt[n][r] = g_xBC[(size_t)(row0 + j0 + r) * CONVDIM + D_INNER + n];
    }
    __syncthreads();
    int ty = threadIdx.x >> 4, tx = threadIdx.x & 15;
    float acc[4][4];
    #pragma unroll
    for (int i = 0; i < 4; i++)
        #pragma unroll
        for (int j = 0; j < 4; j++) acc[i][j] = 0.f;
    #pragma unroll 4
    for (int n = 0; n < 64; n++) {
        float a[4], b[4];
        #pragma unroll
        for (int i = 0; i < 4; i++) a[i] = Ct[n][ty * 4 + i];
        #pragma unroll
        for (int j = 0; j < 4; j++) b[j] = Bt[n][tx * 4 + j];
        #pragma unroll
        for (int i = 0; i < 4; i++)
            #pragma unroll
            for (int j = 0; j < 4; j++) acc[i][j] += a[i] * b[j];
    }
    #pragma unroll
    for (int i = 0; i < 4; i++)
        *(float4*)(g_S + ((size_t)bc * CHUNK + i0 + ty * 4 + i) * CHUNK + j0 + tx * 4) =
            make_float4(acc[i][0], acc[i][1], acc[i][2], acc[i][3]);
}

// ---------------- K7: per-chunk states ----------------
__global__ __launch_bounds__(256) void k_states() {
    int bc = blockIdx.x, h = blockIdx.y;
    __shared__ __align__(16) float xs[16][128];
    __shared__ float4 Bs4[16][16];
    __shared__ float wsh[16];
    int row0 = bc * CHUNK;
    int cb = (bc * NHEADS + h) * CHUNK;
    int tid = threadIdx.x;
    float cum_last = g_cum[cb + 255];
    int p = tid >> 1, nq = tid & 1;
    float4 acc[8];
    #pragma unroll
    for (int k = 0; k < 8; k++) acc[k] = make_float4(0.f, 0.f, 0.f, 0.f);
    for (int tt = 0; tt < 16; tt++) {
        int t0 = tt * 16;
        __syncthreads();
        #pragma unroll
        for (int ps = 0; ps < 2; ps++) {
            int idx = tid + ps * 256;
            int jr = idx >> 5, c = idx & 31;
            ((float4*)xs[jr])[c] = ((const float4*)(g_xBC + (size_t)(row0 + t0 + jr) * CONVDIM + h * HEADDIM))[c];
        }
        {
            int jr = tid >> 4, c = tid & 15;
            Bs4[jr][c] = ((const float4*)(g_xBC + (size_t)(row0 + t0 + jr) * CONVDIM + D_INNER))[c];
        }
        if (tid < 16) {
            int t = t0 + tid;
            wsh[tid] = g_dt[(size_t)(row0 + t) * NHEADS + h] * __expf(cum_last - g_cum[cb + t]);
        }
        __syncthreads();
        #pragma unroll
        for (int t = 0; t < 16; t++) {
            float xv = xs[t][p] * wsh[t];
            #pragma unroll
            for (int k = 0; k < 8; k++) {
                float4 b = Bs4[t][nq + 2 * k];
                acc[k].x += xv * b.x; acc[k].y += xv * b.y;
                acc[k].z += xv * b.z; acc[k].w += xv * b.w;
            }
        }
    }
    float4* sp = (float4*)(g_st + ((size_t)(bc * NHEADS + h) * HEADDIM + p) * D_STATE);
    #pragma unroll
    for (int k = 0; k < 8; k++) sp[nq + 2 * k] = acc[k];
}

// ---------------- K8: serial inter-chunk scan ----------------
__global__ __launch_bounds__(256) void k_scan() {
    int b = blockIdx.x, h = blockIdx.y;
    int tid = threadIdx.x;
    float carry[32];
    #pragma unroll
    for (int k = 0; k < 32; k++) carry[k] = 0.f;
    for (int c = 0; c < NCPB; c++) {
        int bch = (b * NCPB + c) * NHEADS + h;
        float dec = g_cdec[bch];
        size_t base = (size_t)bch * HEADDIM * D_STATE;
        #pragma unroll
        for (int k = 0; k < 32; k++) {
            int e = tid + 256 * k;
            g_ps[base + e] = carry[k];
            carry[k] = carry[k] * dec + g_st[base + e];
        }
    }
}

// ---------------- K10: y += D*x, gate, RMS norm (fp16 output) ----------------
__global__ __launch_bounds__(256) void k_gate(const float* __restrict__ Dp,
                                              const float* __restrict__ rms_w) {
    int row = blockIdx.x;
    int tid = threadIdx.x;
    float gg[8];
    float s2 = 0.f;
    #pragma unroll
    for (int k = 0; k < 8; k++) {
        int d = tid + 256 * k;
        float xv = g_xBC[(size_t)row * CONVDIM + d];
        float v = g_y[(size_t)row * D_INNER + d] + Dp[d >> 7] * xv;
        float z = g_zx[(size_t)row * DPROJP + d];
        float sil = z / (1.f + __expf(-z));
        float g = v * sil;
        gg[k] = g;
        s2 += g * g;
    }
    float tot = blockReduceSum256(s2);
    float sc = rsqrtf(tot * (1.f / D_INNER) + 1e-5f);
    #pragma unroll
    for (int k = 0; k < 8; k++) {
        int d = tid + 256 * k;
        g_gh[(size_t)row * D_INNER + d] = __float2half_rn(gg[k] * sc * rms_w[d]);
    }
}

// ---------------- host launcher ----------------
extern "C" void kernel_launch(void* const* d_in, const int* in_sizes, int n_in,
                              void* d_out, int out_size) {
    const float* u          = (const float*)d_in[0];
    const float* in_proj_w  = (const float*)d_in[1];
    const float* conv_w     = (const float*)d_in[2];
    const float* conv_b     = (const float*)d_in[3];
    const float* dt_bias    = (const float*)d_in[4];
    const float* A_log      = (const float*)d_in[5];
    const float* Dp         = (const float*)d_in[6];
    const float* xnw        = (const float*)d_in[7];
    const float* xnb        = (const float*)d_in[8];
    const float* rms_w      = (const float*)d_in[9];
    const float* out_proj_w = (const float*)d_in[10];
    float* out = (float*)d_out;

    __half *pWinH, *pWoutH, *pLnH, *pGH;
    float *pZx;
    cudaGetSymbolAddress((void**)&pWinH,  g_Winh);
    cudaGetSymbolAddress((void**)&pWoutH, g_Wouth);
    cudaGetSymbolAddress((void**)&pLnH,   g_lnh);
    cudaGetSymbolAddress((void**)&pGH,    g_gh);
    cudaGetSymbolAddress((void**)&pZx,    g_zx);

    static int smem_set = 0;
    if (!smem_set) {
        cudaFuncSetAttribute(gemm_hc, cudaFuncAttributeMaxDynamicSharedMemorySize, GEMM_SMEM);
        smem_set = 1;
    }

    k_normw<<<DPROJ, 256>>>(in_proj_w, pWinH, XDIM, 0.03125f);
    k_normw<<<XDIM, 256>>>(out_proj_w, pWoutH, D_INNER, 1.0f);

    k_layernorm<<<R_TOT, 256>>>(u, xnw, xnb);

    // in_proj GEMM (fp16 HMMA k16): (8192 x 1024) @ (4352 x 1024)^T
    gemm_hc<<<dim3(DPROJP / GBN, R_TOT / GBM), 128, GEMM_SMEM>>>(pLnH, pWinH, pZx, XDIM, DPROJP);

    k_conv<<<(R_TOT * CONVDIM + 255) / 256, 256>>>(conv_w, conv_b);
    k_dtcum<<<NBC * NHEADS, 256>>>(dt_bias, A_log);

    k_scores<<<dim3(NBC, 4, 4), 256>>>();
    k_states<<<dim3(NBC, NHEADS), 256>>>();
    k_scan<<<dim3(NBATCH, NHEADS), 256>>>();
    k_yfused<<<dim3(NBC, NHEADS, 2), 256>>>();

    k_gate<<<R_TOT, 256>>>(Dp, rms_w);

    // out_proj GEMM (fp16 HMMA k16): (8192 x 2048) @ (1024 x 2048)^T
    gemm_hc<<<dim3(XDIM / GBN, R_TOT / GBM), 128, GEMM_SMEM>>>(pGH, pWoutH, out, D_INNER, XDIM);
}

// round 8
// speedup vs baseline: 5.0160x; 1.0703x over previous
#include <cuda_runtime.h>
#include <cuda_fp16.h>
#include <math.h>
#include <stdint.h>

// ---------------- problem constants ----------------
#define XDIM    1024
#define D_STATE 64
#define HEADDIM 128
#define D_INNER 2048
#define NHEADS  16
#define CONVDIM 2176              // D_INNER + 2*64
#define DPROJ   4240              // 2*2048 + 2*64 + 16
#define DPROJP  4352              // padded to 128-multiple for GEMM tiles
#define CHUNK   256
#define NBATCH  2
#define SEQLEN  4096
#define NCPB    16
#define NBC     32
#define R_TOT   8192

// ---------------- device scratch ----------------
__device__ __half g_lnh [(size_t)R_TOT * XDIM];
__device__ __half g_Winh[(size_t)DPROJP * XDIM];     // rows >= DPROJ stay zero (.bss)
__device__ __half g_Wouth[(size_t)XDIM * D_INNER];
__device__ __half g_gh  [(size_t)R_TOT * D_INNER];
__device__ float g_zx  [(size_t)R_TOT * DPROJP];
__device__ float g_xBC [(size_t)R_TOT * CONVDIM];
__device__ float g_dt  [(size_t)R_TOT * NHEADS];
__device__ float g_cum [(size_t)NBC * NHEADS * CHUNK];
__device__ float g_cdec[(size_t)NBC * NHEADS];
__device__ float g_S   [(size_t)NBC * CHUNK * CHUNK];
__device__ float g_y   [(size_t)R_TOT * D_INNER];
__device__ float g_st  [(size_t)NBC * NHEADS * HEADDIM * D_STATE];
__device__ float g_ps  [(size_t)NBC * NHEADS * HEADDIM * D_STATE];

// ---------------- PTX helpers (baseline PTX only) ----------------
__device__ __forceinline__ uint32_t smem_u32(const void* p) {
    uint32_t a;
    asm("{ .reg .u64 t; cvta.to.shared.u64 t, %1; cvt.u32.u64 %0, t; }" : "=r"(a) : "l"(p));
    return a;
}
__device__ __forceinline__ uint32_t pack2(float a, float b) {
    __half2 h = __floats2half2_rn(a, b);
    return *(uint32_t*)&h;
}
#define CP_ASYNC16(s, g) \
    asm volatile("cp.async.cg.shared.global [%0], [%1], 16;" :: "r"(s), "l"(g))
#define CP_COMMIT() asm volatile("cp.async.commit_group;" ::: "memory")
#define CP_WAIT(n)  asm volatile("cp.async.wait_group %0;" :: "n"(n) : "memory")

__device__ __forceinline__ void ldsm_x4(uint32_t* r, uint32_t addr) {
    asm volatile("ldmatrix.sync.aligned.m8n8.x4.shared.b16 {%0,%1,%2,%3}, [%4];"
        : "=r"(r[0]), "=r"(r[1]), "=r"(r[2]), "=r"(r[3]) : "r"(addr));
}
__device__ __forceinline__ void mma_fp16(float* d, const uint32_t* a, const uint32_t* b) {
    asm volatile("mma.sync.aligned.m16n8k16.row.col.f32.f16.f16.f32 "
        "{%0,%1,%2,%3},{%4,%5,%6,%7},{%8,%9},{%0,%1,%2,%3};"
        : "+f"(d[0]), "+f"(d[1]), "+f"(d[2]), "+f"(d[3])
        : "r"(a[0]), "r"(a[1]), "r"(a[2]), "r"(a[3]), "r"(b[0]), "r"(b[1]));
}

// ================= fp16 tensor-core GEMM: C[M,N] = A[M,K] * B[N,K]^T =================
#define GBM 128
#define GBN 128
#define GBK 64
#define GSTG 3
#define TB_A (GBM * GBK * 2)
#define TB_B (GBN * GBK * 2)
#define STAGE_B (TB_A + TB_B)
#define GEMM_SMEM (GSTG * STAGE_B)

__device__ __forceinline__ void gemm_load_tile_h(const __half* Ab, const __half* Bb,
                                                 int K, int t, uint32_t sb, int tid) {
    const __half* Ap = Ab + (size_t)t * GBK;
    const __half* Bp = Bb + (size_t)t * GBK;
    #pragma unroll
    for (int j = 0; j < 8; j++) {
        int c = tid + 128 * j;
        int row = c >> 3;
        uint32_t cc = (uint32_t)(c & 7) * 16;
        uint32_t off = (uint32_t)row * 128 + (cc ^ (((uint32_t)row & 7) << 4));
        CP_ASYNC16(sb + off, Ap + (size_t)row * K + (cc >> 1));
    }
    uint32_t sb2 = sb + TB_A;
    #pragma unroll
    for (int j = 0; j < 8; j++) {
        int c = tid + 128 * j;
        int row = c >> 3;
        uint32_t cc = (uint32_t)(c & 7) * 16;
        uint32_t off = (uint32_t)row * 128 + (cc ^ (((uint32_t)row & 7) << 4));
        CP_ASYNC16(sb2 + off, Bp + (size_t)row * K + (cc >> 1));
    }
    CP_COMMIT();
}

__global__ __launch_bounds__(128, 2) void gemm_hc(const __half* __restrict__ A,
                                                  const __half* __restrict__ B,
                                                  float* __restrict__ C,
                                                  int K, int ldc) {
    extern __shared__ char sm[];
    uint32_t sbase = smem_u32(sm);
    int tid = threadIdx.x, lane = tid & 31, wid = tid >> 5;
    int wm = (wid & 1) * 64;
    int wn = (wid >> 1) * 64;
    int m0 = blockIdx.y * GBM;
    int n0 = blockIdx.x * GBN;
    const __half* Ab = A + (size_t)m0 * K;
    const __half* Bb = B + (size_t)n0 * K;

    int a_row = wm + (lane & 15);
    uint32_t a_kb = (uint32_t)(lane >> 4) * 16;
    int b_row = wn + (lane & 7) + ((lane & 16) ? 8 : 0);
    uint32_t b_kb = (lane & 8) ? 16u : 0u;

    float acc[4][8][4];
    #pragma unroll
    for (int mt = 0; mt < 4; mt++)
        #pragma unroll
        for (int nt = 0; nt < 8; nt++)
            #pragma unroll
            for (int q = 0; q < 4; q++) acc[mt][nt][q] = 0.f;

    int T = K / GBK;
    gemm_load_tile_h(Ab, Bb, K, 0, sbase, tid);
    gemm_load_tile_h(Ab, Bb, K, 1, sbase + STAGE_B, tid);

    for (int t = 0; t < T; t++) {
        CP_WAIT(1);
        __syncthreads();
        if (t + 2 < T)
            gemm_load_tile_h(Ab, Bb, K, t + 2, sbase + ((t + 2) % GSTG) * STAGE_B, tid);
        uint32_t sa = sbase + (t % GSTG) * STAGE_B;
        uint32_t sb = sa + TB_A;

        #pragma unroll
        for (int ks = 0; ks < 4; ks++) {
            uint32_t afr[4][4];
            #pragma unroll
            for (int mt = 0; mt < 4; mt++) {
                uint32_t row = (uint32_t)(a_row + mt * 16);
                uint32_t c = (uint32_t)ks * 32 + a_kb;
                ldsm_x4(afr[mt], sa + row * 128 + (c ^ ((row & 7) << 4)));
            }
            uint32_t bfr[4][4];
            #pragma unroll
            for (int nh = 0; nh < 4; nh++) {
                uint32_t row = (uint32_t)(b_row + nh * 16);
                uint32_t c = (uint32_t)ks * 32 + b_kb;
                ldsm_x4(bfr[nh], sb + row * 128 + (c ^ ((row & 7) << 4)));
            }
            #pragma unroll
            for (int mt = 0; mt < 4; mt++)
                #pragma unroll
                for (int nt = 0; nt < 8; nt++)
                    mma_fp16(acc[mt][nt], afr[mt], &bfr[nt >> 1][(nt & 1) * 2]);
        }
    }

    int g = lane >> 2, tg = lane & 3;
    #pragma unroll
    for (int mt = 0; mt < 4; mt++) {
        int rowa = m0 + wm + mt * 16 + g;
        #pragma unroll
        for (int nt = 0; nt < 8; nt++) {
            int col = n0 + wn + nt * 8 + tg * 2;
            *(float2*)(C + (size_t)rowa * ldc + col) =
                make_float2(acc[mt][nt][0], acc[mt][nt][1]);
            *(float2*)(C + (size_t)(rowa + 8) * ldc + col) =
                make_float2(acc[mt][nt][2], acc[mt][nt][3]);
        }
    }
}

// ============ fused SSD y-kernel (fp16 fragments, fp32 accumulate) ============
// Y[128,128] = att @ X  +  Ce @ P^T, staged in K=64-half tiles (128B rows).
__global__ __launch_bounds__(256, 1) void k_yfused() {
    __shared__ __align__(16) __half As[128 * 64];   // 16 KB
    __shared__ __align__(16) __half Bs[128 * 64];   // 16 KB
    __shared__ float gj_all[256];
    __shared__ float cas[8];
    int bc = blockIdx.x, h = blockIdx.y, ih = blockIdx.z;
    int i_base = ih * 128;
    int row0 = bc * CHUNK;
    int cb = (bc * NHEADS + h) * CHUNK;
    size_t psb = (size_t)(bc * NHEADS + h) * HEADDIM * D_STATE;

    int tid = threadIdx.x, lane = tid & 31, wid = tid >> 5;
    int wm = (wid & 3) * 32;
    int wn = (wid >> 2) * 64;

    int si = tid >> 1;                 // staging row (0..127)
    int sj = (tid & 1) * 32;           // half-column offset within 64-wide tile
    int gi = i_base + si;
    float ci = g_cum[cb + gi];
    float ei = __expf(ci);

    uint32_t as_base = smem_u32(As);
    uint32_t bs_base = smem_u32(Bs);

    int a_row = wm + (lane & 15);
    uint32_t a_kb = (uint32_t)(lane >> 4) * 16;
    int b_row = wn + (lane & 7) + ((lane & 16) ? 8 : 0);
    uint32_t b_kb = (lane & 8) ? 16u : 0u;

    int natt64 = (ih + 1) * 2;         // K=64 att tiles
    int nattj = natt64 * 64;

    if (tid < nattj) {
        int j = tid;
        float ca = g_cum[cb + (j & ~31) + 31];
        gj_all[j] = __expf(ca - g_cum[cb + j]) *
                    g_dt[(size_t)(row0 + j) * NHEADS + h];
    }
    if (tid < natt64 * 2) cas[tid] = g_cum[cb + tid * 32 + 31];

    float acc[2][8][4];
    #pragma unroll
    for (int mt = 0; mt < 2; mt++)
        #pragma unroll
        for (int nt = 0; nt < 8; nt++)
            #pragma unroll
            for (int q = 0; q < 4; q++) acc[mt][nt][q] = 0.f;

    int ntiles = natt64 + 1;
    for (int kt = 0; kt < ntiles; kt++) {
        __syncthreads();
        if (kt < natt64) {
            int j0 = kt * 64;
            int jb = j0 + sj;          // this thread's 32-block start
            // --- A tile: att[i][j], 32 halves per thread ---
            if (gi >= jb + 31) {
                float fi = __expf(ci - cas[jb >> 5]);
                const float* Srow = g_S + ((size_t)bc * CHUNK + gi) * CHUNK + jb;
                const float* gjp = gj_all + jb;
                #pragma unroll
                for (int q = 0; q < 4; q++) {
                    float4 s0 = *(const float4*)(Srow + q * 8);
                    float4 s1 = *(const float4*)(Srow + q * 8 + 4);
                    uint4 u;
                    u.x = pack2(s0.x * fi * gjp[q*8+0], s0.y * fi * gjp[q*8+1]);
                    u.y = pack2(s0.z * fi * gjp[q*8+2], s0.w * fi * gjp[q*8+3]);
                    u.z = pack2(s1.x * fi * gjp[q*8+4], s1.y * fi * gjp[q*8+5]);
                    u.w = pack2(s1.z * fi * gjp[q*8+6], s1.w * fi * gjp[q*8+7]);
                    uint32_t cbyte = (uint32_t)(sj * 2 + q * 16);
                    uint32_t off = (uint32_t)si * 128 + (cbyte ^ (((uint32_t)si & 7) << 4));
                    *(uint4*)((char*)As + off) = u;
                }
            } else if (gi >= jb) {
                #pragma unroll
                for (int q = 0; q < 4; q++) {
                    float v[8];
                    #pragma unroll
                    for (int r = 0; r < 8; r++) {
                        int j = jb + q * 8 + r;
                        float a = 0.f;
                        if (j <= gi)
                            a = g_S[((size_t)bc * CHUNK + gi) * CHUNK + j] *
                                __expf(ci - g_cum[cb + j]) *
                                g_dt[(size_t)(row0 + j) * NHEADS + h];
                        v[r] = a;
                    }
                    uint4 u;
                    u.x = pack2(v[0], v[1]); u.y = pack2(v[2], v[3]);
                    u.z = pack2(v[4], v[5]); u.w = pack2(v[6], v[7]);
                    uint32_t cbyte = (uint32_t)(sj * 2 + q * 16);
                    uint32_t off = (uint32_t)si * 128 + (cbyte ^ (((uint32_t)si & 7) << 4));
                    *(uint4*)((char*)As + off) = u;
                }
            } else {
                #pragma unroll
                for (int q = 0; q < 4; q++) {
                    uint32_t cbyte = (uint32_t)(sj * 2 + q * 16);
                    uint32_t off = (uint32_t)si * 128 + (cbyte ^ (((uint32_t)si & 7) << 4));
                    *(uint4*)((char*)As + off) = make_uint4(0, 0, 0, 0);
                }
            }
            // --- B tile: Xt[p][j], packed half2 along j pairs ---
            #pragma unroll
            for (int jp = 0; jp < 4; jp++) {
                int pair = wid + 8 * jp;           // 0..31
                int j = j0 + 2 * pair;
                const float* x0 = g_xBC + (size_t)(row0 + j) * CONVDIM + h * HEADDIM;
                const float* x1 = x0 + CONVDIM;
                #pragma unroll
                for (int r = 0; r < 4; r++) {
                    int p = lane + 32 * r;
                    uint32_t cbyte = (uint32_t)pair * 4;
                    uint32_t off = (uint32_t)p * 128 + (cbyte ^ (((uint32_t)p & 7) << 4));
                    *(uint32_t*)((char*)Bs + off) = pack2(x0[p], x1[p]);
                }
            }
        } else {
            // --- state tile: A = Ce[i][n] (n=0..63), B = P[p][n] ---
            const float* crow = g_xBC + (size_t)(row0 + gi) * CONVDIM + D_INNER + D_STATE + sj;
            #pragma unroll
            for (int q = 0; q < 4; q++) {
                float4 c0 = *(const float4*)(crow + q * 8);
                float4 c1 = *(const float4*)(crow + q * 8 + 4);
                uint4 u;
                u.x = pack2(c0.x * ei, c0.y * ei);
                u.y = pack2(c0.z * ei, c0.w * ei);
                u.z = pack2(c1.x * ei, c1.y * ei);
                u.w = pack2(c1.z * ei, c1.w * ei);
                uint32_t cbyte = (uint32_t)(sj * 2 + q * 16);
                uint32_t off = (uint32_t)si * 128 + (cbyte ^ (((uint32_t)si & 7) << 4));
                *(uint4*)((char*)As + off) = u;
            }
            int pr = tid >> 1;
            int nc = (tid & 1) * 32;
            const float* prow = g_ps + psb + (size_t)pr * D_STATE + nc;
            #pragma unroll
            for (int q = 0; q < 4; q++) {
                float4 p0 = *(const float4*)(prow + q * 8);
                float4 p1 = *(const float4*)(prow + q * 8 + 4);
                uint4 u;
                u.x = pack2(p0.x, p0.y); u.y = pack2(p0.z, p0.w);
                u.z = pack2(p1.x, p1.y); u.w = pack2(p1.z, p1.w);
                uint32_t cbyte = (uint32_t)(nc * 2 + q * 16);
                uint32_t off = (uint32_t)pr * 128 + (cbyte ^ (((uint32_t)pr & 7) << 4));
                *(uint4*)((char*)Bs + off) = u;
            }
        }
        __syncthreads();
        // --- MMA over the staged K=64 tile (4 x k16) ---
        #pragma unroll
        for (int ks = 0; ks < 4; ks++) {
            uint32_t afr[2][4];
            #pragma unroll
            for (int mt = 0; mt < 2; mt++) {
                uint32_t row = (uint32_t)(a_row + mt * 16);
                uint32_t c = (uint32_t)ks * 32 + a_kb;
                ldsm_x4(afr[mt], as_base + row * 128 + (c ^ ((row & 7) << 4)));
            }
            uint32_t bfr[4][4];
            #pragma unroll
            for (int nh = 0; nh < 4; nh++) {
                uint32_t row = (uint32_t)(b_row + nh * 16);
                uint32_t c = (uint32_t)ks * 32 + b_kb;
                ldsm_x4(bfr[nh], bs_base + row * 128 + (c ^ ((row & 7) << 4)));
            }
            #pragma unroll
            for (int mt = 0; mt < 2; mt++)
                #pragma unroll
                for (int nt = 0; nt < 8; nt++)
                    mma_fp16(acc[mt][nt], afr[mt], &bfr[nt >> 1][(nt & 1) * 2]);
        }
    }

    int g = lane >> 2, tg = lane & 3;
    #pragma unroll
    for (int mt = 0; mt < 2; mt++) {
        int orow = row0 + i_base + wm + mt * 16 + g;
        #pragma unroll
        for (int nt = 0; nt < 8; nt++) {
            int col = h * HEADDIM + wn + nt * 8 + tg * 2;
            *(float2*)(g_y + (size_t)orow * D_INNER + col) =
                make_float2(acc[mt][nt][0], acc[mt][nt][1]);
            *(float2*)(g_y + (size_t)(orow + 8) * D_INNER + col) =
                make_float2(acc[mt][nt][2], acc[mt][nt][3]);
        }
    }
}

// ---------------- reductions ----------------
__device__ __forceinline__ float blockReduceSum256(float v) {
    __shared__ float red[8];
    __shared__ float tot;
    int lane = threadIdx.x & 31, wid = threadIdx.x >> 5;
    #pragma unroll
    for (int o = 16; o; o >>= 1) v += __shfl_down_sync(0xffffffffu, v, o);
    if (lane == 0) red[wid] = v;
    __syncthreads();
    if (wid == 0) {
        float w = (lane < 8) ? red[lane] : 0.f;
        #pragma unroll
        for (int o = 4; o; o >>= 1) w += __shfl_down_sync(0xffffffffu, w, o);
        if (lane == 0) tot = w;
    }
    __syncthreads();
    return tot;
}

// ---------------- K1: l2-normalize weight rows (fp16 output) ----------------
__global__ __launch_bounds__(256) void k_normw(const float* __restrict__ W,
                                               __half* __restrict__ Wo, int K, float extra) {
    int r = blockIdx.x;
    const float* wr = W + (size_t)r * K;
    float s2 = 0.f;
    for (int i = threadIdx.x; i < K; i += 256) { float v = wr[i]; s2 += v * v; }
    float totv = blockReduceSum256(s2);
    float sc = extra / fmaxf(sqrtf(totv), 1e-6f);
    for (int i = threadIdx.x; i < K; i += 256)
        Wo[(size_t)r * K + i] = __float2half_rn(wr[i] * sc);
}

// ---------------- K2: layernorm (fp16 output) ----------------
__global__ __launch_bounds__(256) void k_layernorm(const float* __restrict__ u,
                                                   const float* __restrict__ w,
                                                   const float* __restrict__ b) {
    int row = blockIdx.x;
    const float* ur = u + (size_t)row * XDIM;
    float v[4]; float s = 0.f, s2 = 0.f;
    #pragma unroll
    for (int k = 0; k < 4; k++) {
        v[k] = ur[threadIdx.x + 256 * k];
        s += v[k]; s2 += v[k] * v[k];
    }
    float sum = blockReduceSum256(s);
    float sumsq = blockReduceSum256(s2);
    float mu = sum * (1.f / XDIM);
    float var = sumsq * (1.f / XDIM) - mu * mu;
    float inv = rsqrtf(var + 1e-5f);
    #pragma unroll
    for (int k = 0; k < 4; k++) {
        int d = threadIdx.x + 256 * k;
        g_lnh[(size_t)row * XDIM + d] = __float2half_rn((v[k] - mu) * inv * w[d] + b[d]);
    }
}

// ---------------- K4: depthwise causal conv + bias + silu ----------------
__global__ __launch_bounds__(256) void k_conv(const float* __restrict__ cw,
                                              const float* __restrict__ cb) {
    int gi = blockIdx.x * 256 + threadIdx.x;
    if (gi >= R_TOT * CONVDIM) return;
    int ch = gi % CONVDIM;
    int row = gi / CONVDIM;
    int l = row & (SEQLEN - 1);
    float acc = cb[ch];
    #pragma unroll
    for (int d = 0; d < 4; d++) {
        int ll = l - 3 + d;
        if (ll >= 0)
            acc += cw[ch * 4 + d] * g_zx[(size_t)(row - 3 + d) * DPROJP + D_INNER + ch];
    }
    g_xBC[(size_t)row * CONVDIM + ch] = acc / (1.f + __expf(-acc));
}

// ---------------- K5: dt softplus + per-chunk cumulative dA ----------------
__global__ __launch_bounds__(256) void k_dtcum(const float* __restrict__ dt_bias,
                                               const float* __restrict__ A_log) {
    int bch = blockIdx.x;
    int h = bch & 15, bc = bch >> 4;
    int t = threadIdx.x;
    int row = bc * CHUNK + t;
    float x = g_zx[(size_t)row * DPROJP + (D_INNER + CONVDIM) + h] + dt_bias[h];
    float dtv = (x > 20.f) ? x : log1pf(expf(x));
    g_dt[(size_t)row * NHEADS + h] = dtv;
    float dA = dtv * (-expf(A_log[h]));
    __shared__ float s[256];
    s[t] = dA;
    __syncthreads();
    #pragma unroll
    for (int off = 1; off < 256; off <<= 1) {
        float pv = (t >= off) ? s[t - off] : 0.f;
        __syncthreads();
        s[t] += pv;
        __syncthreads();
    }
    g_cum[(size_t)bch * CHUNK + t] = s[t];
    if (t == 255) g_cdec[bch] = __expf(s[255]);
}

// ---------------- K6a: scores S = C @ B^T ----------------
__global__ __launch_bounds__(256) void k_scores() {
    if (blockIdx.z > blockIdx.y) return;
    int bc = blockIdx.x, i0 = blockIdx.y * 64, j0 = blockIdx.z * 64;
    __shared__ float Ct[64][65];
    __shared__ float Bt[64][65];
    int row0 = bc * CHUNK;
    for (int idx = threadIdx.x; idx < 4096; idx += 256) {
        int n = idx & 63, r = idx >> 6;
        Ct[n][r] = g_xBC[(size_t)(row0 + i0 + r) * CONVDIM + D_INNER + 64 + n];
        Bt[n][r] = g_xBC[(size_t)(row0 + j0 + r) * CONVDIM + D_INNER + n];
    }
    __syncthreads();
    int ty = threadIdx.x >> 4, tx = threadIdx.x & 15;
    float acc[4][4];
    #pragma unroll
    for (int i = 0; i < 4; i++)
        #pragma unroll
        for (int j = 0; j < 4; j++) acc[i][j] = 0.f;
    #pragma unroll 4
    for (int n = 0; n < 64; n++) {
        float a[4], b[4];
        #pragma unroll
        for (int i = 0; i < 4; i++) a[i] = Ct[n][ty * 4 + i];
        #pragma unroll
        for (int j = 0; j < 4; j++) b[j] = Bt[n][tx * 4 + j];
        #pragma unroll
        for (int i = 0; i < 4; i++)
            #pragma unroll
            for (int j = 0; j < 4; j++) acc[i][j] += a[i] * b[j];
    }
    #pragma unroll
    for (int i = 0; i < 4; i++)
        *(float4*)(g_S + ((size_t)bc * CHUNK + i0 + ty * 4 + i) * CHUNK + j0 + tx * 4) =
            make_float4(acc[i][0], acc[i][1], acc[i][2], acc[i][3]);
}

// ---------------- K7: per-chunk states ----------------
__global__ __launch_bounds__(256) void k_states() {
    int bc = blockIdx.x, h = blockIdx.y;
    __shared__ __align__(16) float xs[16][128];
    __shared__ float4 Bs4[16][16];
    __shared__ float wsh[16];
    int row0 = bc * CHUNK;
    int cb = (bc * NHEADS + h) * CHUNK;
    int tid = threadIdx.x;
    float cum_last = g_cum[cb + 255];
    int p = tid >> 1, nq = tid & 1;
    float4 acc[8];
    #pragma unroll
    for (int k = 0; k < 8; k++) acc[k] = make_float4(0.f, 0.f, 0.f, 0.f);
    for (int tt = 0; tt < 16; tt++) {
        int t0 = tt * 16;
        __syncthreads();
        #pragma unroll
        for (int ps = 0; ps < 2; ps++) {
            int idx = tid + ps * 256;
            int jr = idx >> 5, c = idx & 31;
            ((float4*)xs[jr])[c] = ((const float4*)(g_xBC + (size_t)(row0 + t0 + jr) * CONVDIM + h * HEADDIM))[c];
        }
        {
            int jr = tid >> 4, c = tid & 15;
            Bs4[jr][c] = ((const float4*)(g_xBC + (size_t)(row0 + t0 + jr) * CONVDIM + D_INNER))[c];
        }
        if (tid < 16) {
            int t = t0 + tid;
            wsh[tid] = g_dt[(size_t)(row0 + t) * NHEADS + h] * __expf(cum_last - g_cum[cb + t]);
        }
        __syncthreads();
        #pragma unroll
        for (int t = 0; t < 16; t++) {
            float xv = xs[t][p] * wsh[t];
            #pragma unroll
            for (int k = 0; k < 8; k++) {
                float4 b = Bs4[t][nq + 2 * k];
                acc[k].x += xv * b.x; acc[k].y += xv * b.y;
                acc[k].z += xv * b.z; acc[k].w += xv * b.w;
            }
        }
    }
    float4* sp = (float4*)(g_st + ((size_t)(bc * NHEADS + h) * HEADDIM + p) * D_STATE);
    #pragma unroll
    for (int k = 0; k < 8; k++) sp[nq + 2 * k] = acc[k];
}

// ---------------- K8: serial inter-chunk scan ----------------
__global__ __launch_bounds__(256) void k_scan() {
    int b = blockIdx.x, h = blockIdx.y;
    int tid = threadIdx.x;
    float carry[32];
    #pragma unroll
    for (int k = 0; k < 32; k++) carry[k] = 0.f;
    for (int c = 0; c < NCPB; c++) {
        int bch = (b * NCPB + c) * NHEADS + h;
        float dec = g_cdec[bch];
        size_t base = (size_t)bch * HEADDIM * D_STATE;
        #pragma unroll
        for (int k = 0; k < 32; k++) {
            int e = tid + 256 * k;
            g_ps[base + e] = carry[k];
            carry[k] = carry[k] * dec + g_st[base + e];
        }
    }
}

// ---------------- K10: y += D*x, gate, RMS norm (fp16 output) ----------------
__global__ __launch_bounds__(256) void k_gate(const float* __restrict__ Dp,
                                              const float* __restrict__ rms_w) {
    int row = blockIdx.x;
    int tid = threadIdx.x;
    float gg[8];
    float s2 = 0.f;
    #pragma unroll
    for (int k = 0; k < 8; k++) {
        int d = tid + 256 * k;
        float xv = g_xBC[(size_t)row * CONVDIM + d];
        float v = g_y[(size_t)row * D_INNER + d] + Dp[d >> 7] * xv;
        float z = g_zx[(size_t)row * DPROJP + d];
        float sil = z / (1.f + __expf(-z));
        float g = v * sil;
        gg[k] = g;
        s2 += g * g;
    }
    float tot = blockReduceSum256(s2);
    float sc = rsqrtf(tot * (1.f / D_INNER) + 1e-5f);
    #pragma unroll
    for (int k = 0; k < 8; k++) {
        int d = tid + 256 * k;
        g_gh[(size_t)row * D_INNER + d] = __float2half_rn(gg[k] * sc * rms_w[d]);
    }
}

// ---------------- host launcher ----------------
extern "C" void kernel_launch(void* const* d_in, const int* in_sizes, int n_in,
                              void* d_out, int out_size) {
    const float* u          = (const float*)d_in[0];
    const float* in_proj_w  = (const float*)d_in[1];
    const float* conv_w     = (const float*)d_in[2];
    const float* conv_b     = (const float*)d_in[3];
    const float* dt_bias    = (const float*)d_in[4];
    const float* A_log      = (const float*)d_in[5];
    const float* Dp         = (const float*)d_in[6];
    const float* xnw        = (const float*)d_in[7];
    const float* xnb        = (const float*)d_in[8];
    const float* rms_w      = (const float*)d_in[9];
    const float* out_proj_w = (const float*)d_in[10];
    float* out = (float*)d_out;

    __half *pWinH, *pWoutH, *pLnH, *pGH;
    float *pZx;
    cudaGetSymbolAddress((void**)&pWinH,  g_Winh);
    cudaGetSymbolAddress((void**)&pWoutH, g_Wouth);
    cudaGetSymbolAddress((void**)&pLnH,   g_lnh);
    cudaGetSymbolAddress((void**)&pGH,    g_gh);
    cudaGetSymbolAddress((void**)&pZx,    g_zx);

    static int smem_set = 0;
    if (!smem_set) {
        cudaFuncSetAttribute(gemm_hc, cudaFuncAttributeMaxDynamicSharedMemorySize, GEMM_SMEM);
        smem_set = 1;
    }

    k_normw<<<DPROJ, 256>>>(in_proj_w, pWinH, XDIM, 0.03125f);
    k_normw<<<XDIM, 256>>>(out_proj_w, pWoutH, D_INNER, 1.0f);

    k_layernorm<<<R_TOT, 256>>>(u, xnw, xnb);

    gemm_hc<<<dim3(DPROJP / GBN, R_TOT / GBM), 128, GEMM_SMEM>>>(pLnH, pWinH, pZx, XDIM, DPROJP);

    k_conv<<<(R_TOT * CONVDIM + 255) / 256, 256>>>(conv_w, conv_b);
    k_dtcum<<<NBC * NHEADS, 256>>>(dt_bias, A_log);

    k_scores<<<dim3(NBC, 4, 4), 256>>>();
    k_states<<<dim3(NBC, NHEADS), 256>>>();
    k_scan<<<dim3(NBATCH, NHEADS), 256>>>();
    k_yfused<<<dim3(NBC, NHEADS, 2), 256>>>();

    k_gate<<<R_TOT, 256>>>(Dp, rms_w);

    gemm_hc<<<dim3(XDIM / GBN, R_TOT / GBM), 128, GEMM_SMEM>>>(pGH, pWoutH, out, D_INNER, XDIM);
}

// round 9
// speedup vs baseline: 5.4767x; 1.0919x over previous
#include <cuda_runtime.h>
#include <cuda_fp16.h>
#include <math.h>
#include <stdint.h>

// ---------------- problem constants ----------------
#define XDIM    1024
#define D_STATE 64
#define HEADDIM 128
#define D_INNER 2048
#define NHEADS  16
#define CONVDIM 2176              // D_INNER + 2*64
#define DPROJ   4240              // 2*2048 + 2*64 + 16
#define DPROJP  4352              // padded to 128-multiple for GEMM tiles
#define CHUNK   256
#define NBATCH  2
#define SEQLEN  4096
#define NCPB    16
#define NBC     32
#define R_TOT   8192

// ---------------- device scratch ----------------
__device__ __half g_lnh [(size_t)R_TOT * XDIM];
__device__ __half g_Winh[(size_t)DPROJP * XDIM];     // rows >= DPROJ stay zero (.bss)
__device__ __half g_Wouth[(size_t)XDIM * D_INNER];
__device__ __half g_gh  [(size_t)R_TOT * D_INNER];
__device__ __half g_xBCh[(size_t)R_TOT * CONVDIM];   // fp16 mirror of conv output
__device__ float g_zx  [(size_t)R_TOT * DPROJP];
__device__ float g_xBC [(size_t)R_TOT * CONVDIM];
__device__ float g_dt  [(size_t)R_TOT * NHEADS];
__device__ float g_cum [(size_t)NBC * NHEADS * CHUNK];
__device__ float g_cdec[(size_t)NBC * NHEADS];
__device__ float g_S   [(size_t)NBC * CHUNK * CHUNK];
__device__ float g_y   [(size_t)R_TOT * D_INNER];
__device__ float g_st  [(size_t)NBC * NHEADS * HEADDIM * D_STATE];
__device__ float g_ps  [(size_t)NBC * NHEADS * HEADDIM * D_STATE];

// ---------------- PTX helpers (baseline PTX only) ----------------
__device__ __forceinline__ uint32_t smem_u32(const void* p) {
    uint32_t a;
    asm("{ .reg .u64 t; cvta.to.shared.u64 t, %1; cvt.u32.u64 %0, t; }" : "=r"(a) : "l"(p));
    return a;
}
__device__ __forceinline__ uint32_t pack2(float a, float b) {
    __half2 h = __floats2half2_rn(a, b);
    return *(uint32_t*)&h;
}
__device__ __forceinline__ uint32_t pack2h(__half a, __half b) {
    __half2 h = __halves2half2(a, b);
    return *(uint32_t*)&h;
}
#define CP_ASYNC16(s, g) \
    asm volatile("cp.async.cg.shared.global [%0], [%1], 16;" :: "r"(s), "l"(g))
#define CP_COMMIT() asm volatile("cp.async.commit_group;" ::: "memory")
#define CP_WAIT(n)  asm volatile("cp.async.wait_group %0;" :: "n"(n) : "memory")

__device__ __forceinline__ void ldsm_x4(uint32_t* r, uint32_t addr) {
    asm volatile("ldmatrix.sync.aligned.m8n8.x4.shared.b16 {%0,%1,%2,%3}, [%4];"
        : "=r"(r[0]), "=r"(r[1]), "=r"(r[2]), "=r"(r[3]) : "r"(addr));
}
__device__ __forceinline__ void mma_fp16(float* d, const uint32_t* a, const uint32_t* b) {
    asm volatile("mma.sync.aligned.m16n8k16.row.col.f32.f16.f16.f32 "
        "{%0,%1,%2,%3},{%4,%5,%6,%7},{%8,%9},{%0,%1,%2,%3};"
        : "+f"(d[0]), "+f"(d[1]), "+f"(d[2]), "+f"(d[3])
        : "r"(a[0]), "r"(a[1]), "r"(a[2]), "r"(a[3]), "r"(b[0]), "r"(b[1]));
}

// ================= fp16 tensor-core GEMM: C[M,N] = A[M,K] * B[N,K]^T =================
#define GBM 128
#define GBN 128
#define GBK 64
#define GSTG 3
#define TB_A (GBM * GBK * 2)
#define TB_B (GBN * GBK * 2)
#define STAGE_B (TB_A + TB_B)
#define GEMM_SMEM (GSTG * STAGE_B)

__device__ __forceinline__ void gemm_load_tile_h(const __half* Ab, const __half* Bb,
                                                 int K, int t, uint32_t sb, int tid) {
    const __half* Ap = Ab + (size_t)t * GBK;
    const __half* Bp = Bb + (size_t)t * GBK;
    #pragma unroll
    for (int j = 0; j < 8; j++) {
        int c = tid + 128 * j;
        int row = c >> 3;
        uint32_t cc = (uint32_t)(c & 7) * 16;
        uint32_t off = (uint32_t)row * 128 + (cc ^ (((uint32_t)row & 7) << 4));
        CP_ASYNC16(sb + off, Ap + (size_t)row * K + (cc >> 1));
    }
    uint32_t sb2 = sb + TB_A;
    #pragma unroll
    for (int j = 0; j < 8; j++) {
        int c = tid + 128 * j;
        int row = c >> 3;
        uint32_t cc = (uint32_t)(c & 7) * 16;
        uint32_t off = (uint32_t)row * 128 + (cc ^ (((uint32_t)row & 7) << 4));
        CP_ASYNC16(sb2 + off, Bp + (size_t)row * K + (cc >> 1));
    }
    CP_COMMIT();
}

__global__ __launch_bounds__(128, 2) void gemm_hc(const __half* __restrict__ A,
                                                  const __half* __restrict__ B,
                                                  float* __restrict__ C,
                                                  int K, int ldc) {
    extern __shared__ char sm[];
    uint32_t sbase = smem_u32(sm);
    int tid = threadIdx.x, lane = tid & 31, wid = tid >> 5;
    int wm = (wid & 1) * 64;
    int wn = (wid >> 1) * 64;
    int m0 = blockIdx.y * GBM;
    int n0 = blockIdx.x * GBN;
    const __half* Ab = A + (size_t)m0 * K;
    const __half* Bb = B + (size_t)n0 * K;

    int a_row = wm + (lane & 15);
    uint32_t a_kb = (uint32_t)(lane >> 4) * 16;
    int b_row = wn + (lane & 7) + ((lane & 16) ? 8 : 0);
    uint32_t b_kb = (lane & 8) ? 16u : 0u;

    float acc[4][8][4];
    #pragma unroll
    for (int mt = 0; mt < 4; mt++)
        #pragma unroll
        for (int nt = 0; nt < 8; nt++)
            #pragma unroll
            for (int q = 0; q < 4; q++) acc[mt][nt][q] = 0.f;

    int T = K / GBK;
    gemm_load_tile_h(Ab, Bb, K, 0, sbase, tid);
    gemm_load_tile_h(Ab, Bb, K, 1, sbase + STAGE_B, tid);

    for (int t = 0; t < T; t++) {
        CP_WAIT(1);
        __syncthreads();
        if (t + 2 < T)
            gemm_load_tile_h(Ab, Bb, K, t + 2, sbase + ((t + 2) % GSTG) * STAGE_B, tid);
        uint32_t sa = sbase + (t % GSTG) * STAGE_B;
        uint32_t sb = sa + TB_A;

        #pragma unroll
        for (int ks = 0; ks < 4; ks++) {
            uint32_t afr[4][4];
            #pragma unroll
            for (int mt = 0; mt < 4; mt++) {
                uint32_t row = (uint32_t)(a_row + mt * 16);
                uint32_t c = (uint32_t)ks * 32 + a_kb;
                ldsm_x4(afr[mt], sa + row * 128 + (c ^ ((row & 7) << 4)));
            }
            uint32_t bfr[4][4];
            #pragma unroll
            for (int nh = 0; nh < 4; nh++) {
                uint32_t row = (uint32_t)(b_row + nh * 16);
                uint32_t c = (uint32_t)ks * 32 + b_kb;
                ldsm_x4(bfr[nh], sb + row * 128 + (c ^ ((row & 7) << 4)));
            }
            #pragma unroll
            for (int mt = 0; mt < 4; mt++)
                #pragma unroll
                for (int nt = 0; nt < 8; nt++)
                    mma_fp16(acc[mt][nt], afr[mt], &bfr[nt >> 1][(nt & 1) * 2]);
        }
    }

    int g = lane >> 2, tg = lane & 3;
    #pragma unroll
    for (int mt = 0; mt < 4; mt++) {
        int rowa = m0 + wm + mt * 16 + g;
        #pragma unroll
        for (int nt = 0; nt < 8; nt++) {
            int col = n0 + wn + nt * 8 + tg * 2;
            *(float2*)(C + (size_t)rowa * ldc + col) =
                make_float2(acc[mt][nt][0], acc[mt][nt][1]);
            *(float2*)(C + (size_t)(rowa + 8) * ldc + col) =
                make_float2(acc[mt][nt][2], acc[mt][nt][3]);
        }
    }
}

// ============ K6a (fp16 MMA): S tile = C[i0..i0+127] @ B[j0..j0+127]^T, K=64 ============
__global__ __launch_bounds__(256, 1) void k_scores_h() {
    __shared__ __align__(16) __half As[128 * 64];
    __shared__ __align__(16) __half Bs[128 * 64];
    int bc = blockIdx.x;
    int tile = blockIdx.y;              // 0:(0,0) 1:(1,0) 2:(1,1)
    int i0 = (tile != 0) ? 128 : 0;
    int j0 = (tile == 2) ? 128 : 0;
    int row0 = bc * CHUNK;
    int tid = threadIdx.x, lane = tid & 31, wid = tid >> 5;

    uint32_t as_base = smem_u32(As);
    uint32_t bs_base = smem_u32(Bs);
    const __half* Cb = g_xBCh + (size_t)(row0 + i0) * CONVDIM + D_INNER + D_STATE;
    const __half* Bb = g_xBCh + (size_t)(row0 + j0) * CONVDIM + D_INNER;
    #pragma unroll
    for (int j = 0; j < 4; j++) {
        int c = tid + 256 * j;
        int row = c >> 3;
        uint32_t cc = (uint32_t)(c & 7) * 16;
        uint32_t off = (uint32_t)row * 128 + (cc ^ (((uint32_t)row & 7) << 4));
        CP_ASYNC16(as_base + off, Cb + (size_t)row * CONVDIM + (cc >> 1));
        CP_ASYNC16(bs_base + off, Bb + (size_t)row * CONVDIM + (cc >> 1));
    }
    CP_COMMIT();
    CP_WAIT(0);
    __syncthreads();

    int wm = (wid & 3) * 32;
    int wn = (wid >> 2) * 64;
    int a_row = wm + (lane & 15);
    uint32_t a_kb = (uint32_t)(lane >> 4) * 16;
    int b_row = wn + (lane & 7) + ((lane & 16) ? 8 : 0);
    uint32_t b_kb = (lane & 8) ? 16u : 0u;

    float acc[2][8][4];
    #pragma unroll
    for (int mt = 0; mt < 2; mt++)
        #pragma unroll
        for (int nt = 0; nt < 8; nt++)
            #pragma unroll
            for (int q = 0; q < 4; q++) acc[mt][nt][q] = 0.f;

    #pragma unroll
    for (int ks = 0; ks < 4; ks++) {
        uint32_t afr[2][4];
        #pragma unroll
        for (int mt = 0; mt < 2; mt++) {
            uint32_t row = (uint32_t)(a_row + mt * 16);
            uint32_t c = (uint32_t)ks * 32 + a_kb;
            ldsm_x4(afr[mt], as_base + row * 128 + (c ^ ((row & 7) << 4)));
        }
        uint32_t bfr[4][4];
        #pragma unroll
        for (int nh = 0; nh < 4; nh++) {
            uint32_t row = (uint32_t)(b_row + nh * 16);
            uint32_t c = (uint32_t)ks * 32 + b_kb;
            ldsm_x4(bfr[nh], bs_base + row * 128 + (c ^ ((row & 7) << 4)));
        }
        #pragma unroll
        for (int mt = 0; mt < 2; mt++)
            #pragma unroll
            for (int nt = 0; nt < 8; nt++)
                mma_fp16(acc[mt][nt], afr[mt], &bfr[nt >> 1][(nt & 1) * 2]);
    }

    int g = lane >> 2, tg = lane & 3;
    #pragma unroll
    for (int mt = 0; mt < 2; mt++) {
        int irow = i0 + wm + mt * 16 + g;
        #pragma unroll
        for (int nt = 0; nt < 8; nt++) {
            int col = j0 + wn + nt * 8 + tg * 2;
            *(float2*)(g_S + ((size_t)bc * CHUNK + irow) * CHUNK + col) =
                make_float2(acc[mt][nt][0], acc[mt][nt][1]);
            *(float2*)(g_S + ((size_t)bc * CHUNK + irow + 8) * CHUNK + col) =
                make_float2(acc[mt][nt][2], acc[mt][nt][3]);
        }
    }
}

// ============ K7 (fp16 MMA): states[p][n] = sum_t (x[t][p]*w_t) * B[t][n] ============
__global__ __launch_bounds__(256, 1) void k_states_h() {
    __shared__ __align__(16) __half As[128 * 64];   // [p][t] tile
    __shared__ __align__(16) __half Bs[64 * 64];    // [n][t] tile
    __shared__ float wsh[256];
    int bc = blockIdx.x, h = blockIdx.y;
    int row0 = bc * CHUNK;
    int cb = (bc * NHEADS + h) * CHUNK;
    int tid = threadIdx.x, lane = tid & 31, wid = tid >> 5;

    float cum_last = g_cum[cb + 255];
    wsh[tid] = g_dt[(size_t)(row0 + tid) * NHEADS + h] *
               __expf(cum_last - g_cum[cb + tid]);

    uint32_t as_base = smem_u32(As);
    uint32_t bs_base = smem_u32(Bs);

    int wm = (wid & 3) * 32;
    int wn = (wid >> 2) * 32;
    int a_row = wm + (lane & 15);
    uint32_t a_kb = (uint32_t)(lane >> 4) * 16;
    int b_row = wn + (lane & 7) + ((lane & 16) ? 8 : 0);
    uint32_t b_kb = (lane & 8) ? 16u : 0u;

    float acc[2][4][4];
    #pragma unroll
    for (int mt = 0; mt < 2; mt++)
        #pragma unroll
        for (int nt = 0; nt < 4; nt++)
            #pragma unroll
            for (int q = 0; q < 4; q++) acc[mt][nt][q] = 0.f;

    for (int kt = 0; kt < 4; kt++) {
        int t0 = kt * 64;
        __syncthreads();
        // A tile: [p][t] = x[t][p] * w_t (transposed stage, t-pairs packed)
        #pragma unroll
        for (int jp = 0; jp < 4; jp++) {
            int pair = wid + 8 * jp;                // 0..31
            int t = t0 + 2 * pair;
            const __half* x0 = g_xBCh + (size_t)(row0 + t) * CONVDIM + h * HEADDIM;
            const __half* x1 = x0 + CONVDIM;
            float w0 = wsh[t], w1 = wsh[t + 1];
            #pragma unroll
            for (int r = 0; r < 4; r++) {
                int p = lane + 32 * r;
                uint32_t cbyte = (uint32_t)pair * 4;
                uint32_t off = (uint32_t)p * 128 + (cbyte ^ (((uint32_t)p & 7) << 4));
                *(uint32_t*)((char*)As + off) =
                    pack2(__half2float(x0[p]) * w0, __half2float(x1[p]) * w1);
            }
        }
        // B tile: [n][t] = B[t][n] (transposed stage)
        #pragma unroll
        for (int q = 0; q < 8; q++) {
            int idx = tid + 256 * q;
            int n = idx >> 5, pair = idx & 31;
            int t = t0 + 2 * pair;
            const __half* b0 = g_xBCh + (size_t)(row0 + t) * CONVDIM + D_INNER;
            uint32_t cbyte = (uint32_t)pair * 4;
            uint32_t off = (uint32_t)n * 128 + (cbyte ^ (((uint32_t)n & 7) << 4));
            *(uint32_t*)((char*)Bs + off) = pack2h(b0[n], b0[CONVDIM + n]);
        }
        __syncthreads();
        #pragma unroll
        for (int ks = 0; ks < 4; ks++) {
            uint32_t afr[2][4];
            #pragma unroll
            for (int mt = 0; mt < 2; mt++) {
                uint32_t row = (uint32_t)(a_row + mt * 16);
                uint32_t c = (uint32_t)ks * 32 + a_kb;
                ldsm_x4(afr[mt], as_base + row * 128 + (c ^ ((row & 7) << 4)));
            }
            uint32_t bfr[2][4];
            #pragma unroll
            for (int nh = 0; nh < 2; nh++) {
                uint32_t row = (uint32_t)(b_row + nh * 16);
                uint32_t c = (uint32_t)ks * 32 + b_kb;
                ldsm_x4(bfr[nh], bs_base + row * 128 + (c ^ ((row & 7) << 4)));
            }
            #pragma unroll
            for (int mt = 0; mt < 2; mt++)
                #pragma unroll
                for (int nt = 0; nt < 4; nt++)
                    mma_fp16(acc[mt][nt], afr[mt], &bfr[nt >> 1][(nt & 1) * 2]);
        }
    }

    size_t base = (size_t)(bc * NHEADS + h) * HEADDIM * D_STATE;
    int g = lane >> 2, tg = lane & 3;
    #pragma unroll
    for (int mt = 0; mt < 2; mt++) {
        int prow = wm + mt * 16 + g;
        #pragma unroll
        for (int nt = 0; nt < 4; nt++) {
            int col = wn + nt * 8 + tg * 2;
            *(float2*)(g_st + base + (size_t)prow * D_STATE + col) =
                make_float2(acc[mt][nt][0], acc[mt][nt][1]);
            *(float2*)(g_st + base + (size_t)(prow + 8) * D_STATE + col) =
                make_float2(acc[mt][nt][2], acc[mt][nt][3]);
        }
    }
}

// ============ fused SSD y-kernel (fp16 fragments, fp32 accumulate) ============
__global__ __launch_bounds__(256, 1) void k_yfused() {
    __shared__ __align__(16) __half As[128 * 64];
    __shared__ __align__(16) __half Bs[128 * 64];
    __shared__ float gj_all[256];
    __shared__ float cas[8];
    int bc = blockIdx.x, h = blockIdx.y, ih = blockIdx.z;
    int i_base = ih * 128;
    int row0 = bc * CHUNK;
    int cb = (bc * NHEADS + h) * CHUNK;
    size_t psb = (size_t)(bc * NHEADS + h) * HEADDIM * D_STATE;

    int tid = threadIdx.x, lane = tid & 31, wid = tid >> 5;
    int wm = (wid & 3) * 32;
    int wn = (wid >> 2) * 64;

    int si = tid >> 1;
    int sj = (tid & 1) * 32;
    int gi = i_base + si;
    float ci = g_cum[cb + gi];
    float ei = __expf(ci);

    uint32_t as_base = smem_u32(As);
    uint32_t bs_base = smem_u32(Bs);

    int a_row = wm + (lane & 15);
    uint32_t a_kb = (uint32_t)(lane >> 4) * 16;
    int b_row = wn + (lane & 7) + ((lane & 16) ? 8 : 0);
    uint32_t b_kb = (lane & 8) ? 16u : 0u;

    int natt64 = (ih + 1) * 2;
    int nattj = natt64 * 64;

    if (tid < nattj) {
        int j = tid;
        float ca = g_cum[cb + (j & ~31) + 31];
        gj_all[j] = __expf(ca - g_cum[cb + j]) *
                    g_dt[(size_t)(row0 + j) * NHEADS + h];
    }
    if (tid < natt64 * 2) cas[tid] = g_cum[cb + tid * 32 + 31];

    float acc[2][8][4];
    #pragma unroll
    for (int mt = 0; mt < 2; mt++)
        #pragma unroll
        for (int nt = 0; nt < 8; nt++)
            #pragma unroll
            for (int q = 0; q < 4; q++) acc[mt][nt][q] = 0.f;

    int ntiles = natt64 + 1;
    for (int kt = 0; kt < ntiles; kt++) {
        __syncthreads();
        if (kt < natt64) {
            int j0 = kt * 64;
            int jb = j0 + sj;
            if (gi >= jb + 31) {
                float fi = __expf(ci - cas[jb >> 5]);
                const float* Srow = g_S + ((size_t)bc * CHUNK + gi) * CHUNK + jb;
                const float* gjp = gj_all + jb;
                #pragma unroll
                for (int q = 0; q < 4; q++) {
                    float4 s0 = *(const float4*)(Srow + q * 8);
                    float4 s1 = *(const float4*)(Srow + q * 8 + 4);
                    uint4 u;
                    u.x = pack2(s0.x * fi * gjp[q*8+0], s0.y * fi * gjp[q*8+1]);
                    u.y = pack2(s0.z * fi * gjp[q*8+2], s0.w * fi * gjp[q*8+3]);
                    u.z = pack2(s1.x * fi * gjp[q*8+4], s1.y * fi * gjp[q*8+5]);
                    u.w = pack2(s1.z * fi * gjp[q*8+6], s1.w * fi * gjp[q*8+7]);
                    uint32_t cbyte = (uint32_t)(sj * 2 + q * 16);
                    uint32_t off = (uint32_t)si * 128 + (cbyte ^ (((uint32_t)si & 7) << 4));
                    *(uint4*)((char*)As + off) = u;
                }
            } else if (gi >= jb) {
                #pragma unroll
                for (int q = 0; q < 4; q++) {
                    float v[8];
                    #pragma unroll
                    for (int r = 0; r < 8; r++) {
                        int j = jb + q * 8 + r;
                        float a = 0.f;
                        if (j <= gi)
                            a = g_S[((size_t)bc * CHUNK + gi) * CHUNK + j] *
                                __expf(ci - g_cum[cb + j]) *
                                g_dt[(size_t)(row0 + j) * NHEADS + h];
                        v[r] = a;
                    }
                    uint4 u;
                    u.x = pack2(v[0], v[1]); u.y = pack2(v[2], v[3]);
                    u.z = pack2(v[4], v[5]); u.w = pack2(v[6], v[7]);
                    uint32_t cbyte = (uint32_t)(sj * 2 + q * 16);
                    uint32_t off = (uint32_t)si * 128 + (cbyte ^ (((uint32_t)si & 7) << 4));
                    *(uint4*)((char*)As + off) = u;
                }
            } else {
                #pragma unroll
                for (int q = 0; q < 4; q++) {
                    uint32_t cbyte = (uint32_t)(sj * 2 + q * 16);
                    uint32_t off = (uint32_t)si * 128 + (cbyte ^ (((uint32_t)si & 7) << 4));
                    *(uint4*)((char*)As + off) = make_uint4(0, 0, 0, 0);
                }
            }
            #pragma unroll
            for (int jp = 0; jp < 4; jp++) {
                int pair = wid + 8 * jp;
                int j = j0 + 2 * pair;
                const __half* x0 = g_xBCh + (size_t)(row0 + j) * CONVDIM + h * HEADDIM;
                const __half* x1 = x0 + CONVDIM;
                #pragma unroll
                for (int r = 0; r < 4; r++) {
                    int p = lane + 32 * r;
                    uint32_t cbyte = (uint32_t)pair * 4;
                    uint32_t off = (uint32_t)p * 128 + (cbyte ^ (((uint32_t)p & 7) << 4));
                    *(uint32_t*)((char*)Bs + off) = pack2h(x0[p], x1[p]);
                }
            }
        } else {
            const float* crow = g_xBC + (size_t)(row0 + gi) * CONVDIM + D_INNER + D_STATE + sj;
            #pragma unroll
            for (int q = 0; q < 4; q++) {
                float4 c0 = *(const float4*)(crow + q * 8);
                float4 c1 = *(const float4*)(crow + q * 8 + 4);
                uint4 u;
                u.x = pack2(c0.x * ei, c0.y * ei);
                u.y = pack2(c0.z * ei, c0.w * ei);
                u.z = pack2(c1.x * ei, c1.y * ei);
                u.w = pack2(c1.z * ei, c1.w * ei);
                uint32_t cbyte = (uint32_t)(sj * 2 + q * 16);
                uint32_t off = (uint32_t)si * 128 + (cbyte ^ (((uint32_t)si & 7) << 4));
                *(uint4*)((char*)As + off) = u;
            }
            int pr = tid >> 1;
            int nc = (tid & 1) * 32;
            const float* prow = g_ps + psb + (size_t)pr * D_STATE + nc;
            #pragma unroll
            for (int q = 0; q < 4; q++) {
                float4 p0 = *(const float4*)(prow + q * 8);
                float4 p1 = *(const float4*)(prow + q * 8 + 4);
                uint4 u;
                u.x = pack2(p0.x, p0.y); u.y = pack2(p0.z, p0.w);
                u.z = pack2(p1.x, p1.y); u.w = pack2(p1.z, p1.w);
                uint32_t cbyte = (uint32_t)(nc * 2 + q * 16);
                uint32_t off = (uint32_t)pr * 128 + (cbyte ^ (((uint32_t)pr & 7) << 4));
                *(uint4*)((char*)Bs + off) = u;
            }
        }
        __syncthreads();
        #pragma unroll
        for (int ks = 0; ks < 4; ks++) {
            uint32_t afr[2][4];
            #pragma unroll
            for (int mt = 0; mt < 2; mt++) {
                uint32_t row = (uint32_t)(a_row + mt * 16);
                uint32_t c = (uint32_t)ks * 32 + a_kb;
                ldsm_x4(afr[mt], as_base + row * 128 + (c ^ ((row & 7) << 4)));
            }
            uint32_t bfr[4][4];
            #pragma unroll
            for (int nh = 0; nh < 4; nh++) {
                uint32_t row = (uint32_t)(b_row + nh * 16);
                uint32_t c = (uint32_t)ks * 32 + b_kb;
                ldsm_x4(bfr[nh], bs_base + row * 128 + (c ^ ((row & 7) << 4)));
            }
            #pragma unroll
            for (int mt = 0; mt < 2; mt++)
                #pragma unroll
                for (int nt = 0; nt < 8; nt++)
                    mma_fp16(acc[mt][nt], afr[mt], &bfr[nt >> 1][(nt & 1) * 2]);
        }
    }

    int g = lane >> 2, tg = lane & 3;
    #pragma unroll
    for (int mt = 0; mt < 2; mt++) {
        int orow = row0 + i_base + wm + mt * 16 + g;
        #pragma unroll
        for (int nt = 0; nt < 8; nt++) {
            int col = h * HEADDIM + wn + nt * 8 + tg * 2;
            *(float2*)(g_y + (size_t)orow * D_INNER + col) =
                make_float2(acc[mt][nt][0], acc[mt][nt][1]);
            *(float2*)(g_y + (size_t)(orow + 8) * D_INNER + col) =
                make_float2(acc[mt][nt][2], acc[mt][nt][3]);
        }
    }
}

// ---------------- reductions ----------------
__device__ __forceinline__ float blockReduceSum256(float v) {
    __shared__ float red[8];
    __shared__ float tot;
    int lane = threadIdx.x & 31, wid = threadIdx.x >> 5;
    #pragma unroll
    for (int o = 16; o; o >>= 1) v += __shfl_down_sync(0xffffffffu, v, o);
    if (lane == 0) red[wid] = v;
    __syncthreads();
    if (wid == 0) {
        float w = (lane < 8) ? red[lane] : 0.f;
        #pragma unroll
        for (int o = 4; o; o >>= 1) w += __shfl_down_sync(0xffffffffu, w, o);
        if (lane == 0) tot = w;
    }
    __syncthreads();
    return tot;
}

// ---------------- K1: l2-normalize weight rows (fp16 output) ----------------
__global__ __launch_bounds__(256) void k_normw(const float* __restrict__ W,
                                               __half* __restrict__ Wo, int K, float extra) {
    int r = blockIdx.x;
    const float* wr = W + (size_t)r * K;
    float s2 = 0.f;
    for (int i = threadIdx.x; i < K; i += 256) { float v = wr[i]; s2 += v * v; }
    float totv = blockReduceSum256(s2);
    float sc = extra / fmaxf(sqrtf(totv), 1e-6f);
    for (int i = threadIdx.x; i < K; i += 256)
        Wo[(size_t)r * K + i] = __float2half_rn(wr[i] * sc);
}

// ---------------- K2: layernorm (fp16 output) ----------------
__global__ __launch_bounds__(256) void k_layernorm(const float* __restrict__ u,
                                                   const float* __restrict__ w,
                                                   const float* __restrict__ b) {
    int row = blockIdx.x;
    const float* ur = u + (size_t)row * XDIM;
    float v[4]; float s = 0.f, s2 = 0.f;
    #pragma unroll
    for (int k = 0; k < 4; k++) {
        v[k] = ur[threadIdx.x + 256 * k];
        s += v[k]; s2 += v[k] * v[k];
    }
    float sum = blockReduceSum256(s);
    float sumsq = blockReduceSum256(s2);
    float mu = sum * (1.f / XDIM);
    float var = sumsq * (1.f / XDIM) - mu * mu;
    float inv = rsqrtf(var + 1e-5f);
    #pragma unroll
    for (int k = 0; k < 4; k++) {
        int d = threadIdx.x + 256 * k;
        g_lnh[(size_t)row * XDIM + d] = __float2half_rn((v[k] - mu) * inv * w[d] + b[d]);
    }
}

// ---------------- K4: depthwise causal conv + bias + silu (fp32 + fp16 outputs) ----------------
__global__ __launch_bounds__(256) void k_conv(const float* __restrict__ cw,
                                              const float* __restrict__ cb) {
    int gi = blockIdx.x * 256 + threadIdx.x;
    if (gi >= R_TOT * CONVDIM) return;
    int ch = gi % CONVDIM;
    int row = gi / CONVDIM;
    int l = row & (SEQLEN - 1);
    float acc = cb[ch];
    #pragma unroll
    for (int d = 0; d < 4; d++) {
        int ll = l - 3 + d;
        if (ll >= 0)
            acc += cw[ch * 4 + d] * g_zx[(size_t)(row - 3 + d) * DPROJP + D_INNER + ch];
    }
    float v = acc / (1.f + __expf(-acc));
    g_xBC[(size_t)row * CONVDIM + ch] = v;
    g_xBCh[(size_t)row * CONVDIM + ch] = __float2half_rn(v);
}

// ---------------- K5: dt softplus + per-chunk cumulative dA ----------------
__global__ __launch_bounds__(256) void k_dtcum(const float* __restrict__ dt_bias,
                                               const float* __restrict__ A_log) {
    int bch = blockIdx.x;
    int h = bch & 15, bc = bch >> 4;
    int t = threadIdx.x;
    int row = bc * CHUNK + t;
    float x = g_zx[(size_t)row * DPROJP + (D_INNER + CONVDIM) + h] + dt_bias[h];
    float dtv = (x > 20.f) ? x : log1pf(expf(x));
    g_dt[(size_t)row * NHEADS + h] = dtv;
    float dA = dtv * (-expf(A_log[h]));
    __shared__ float s[256];
    s[t] = dA;
    __syncthreads();
    #pragma unroll
    for (int off = 1; off < 256; off <<= 1) {
        float pv = (t >= off) ? s[t - off] : 0.f;
        __syncthreads();
        s[t] += pv;
        __syncthreads();
    }
    g_cum[(size_t)bch * CHUNK + t] = s[t];
    if (t == 255) g_cdec[bch] = __expf(s[255]);
}

// ---------------- K8: serial inter-chunk scan ----------------
__global__ __launch_bounds__(256) void k_scan() {
    int b = blockIdx.x, h = blockIdx.y;
    int tid = threadIdx.x;
    float carry[32];
    #pragma unroll
    for (int k = 0; k < 32; k++) carry[k] = 0.f;
    for (int c = 0; c < NCPB; c++) {
        int bch = (b * NCPB + c) * NHEADS + h;
        float dec = g_cdec[bch];
        size_t base = (size_t)bch * HEADDIM * D_STATE;
        #pragma unroll
        for (int k = 0; k < 32; k++) {
            int e = tid + 256 * k;
            g_ps[base + e] = carry[k];
            carry[k] = carry[k] * dec + g_st[base + e];
        }
    }
}

// ---------------- K10: y += D*x, gate, RMS norm (fp16 output) ----------------
__global__ __launch_bounds__(256) void k_gate(const float* __restrict__ Dp,
                                              const float* __restrict__ rms_w) {
    int row = blockIdx.x;
    int tid = threadIdx.x;
    float gg[8];
    float s2 = 0.f;
    #pragma unroll
    for (int k = 0; k < 8; k++) {
        int d = tid + 256 * k;
        float xv = g_xBC[(size_t)row * CONVDIM + d];
        float v = g_y[(size_t)row * D_INNER + d] + Dp[d >> 7] * xv;
        float z = g_zx[(size_t)row * DPROJP + d];
        float sil = z / (1.f + __expf(-z));
        float g = v * sil;
        gg[k] = g;
        s2 += g * g;
    }
    float tot = blockReduceSum256(s2);
    float sc = rsqrtf(tot * (1.f / D_INNER) + 1e-5f);
    #pragma unroll
    for (int k = 0; k < 8; k++) {
        int d = tid + 256 * k;
        g_gh[(size_t)row * D_INNER + d] = __float2half_rn(gg[k] * sc * rms_w[d]);
    }
}

// ---------------- host launcher ----------------
extern "C" void kernel_launch(void* const* d_in, const int* in_sizes, int n_in,
                              void* d_out, int out_size) {
    const float* u          = (const float*)d_in[0];
    const float* in_proj_w  = (const float*)d_in[1];
    const float* conv_w     = (const float*)d_in[2];
    const float* conv_b     = (const float*)d_in[3];
    const float* dt_bias    = (const float*)d_in[4];
    const float* A_log      = (const float*)d_in[5];
    const float* Dp         = (const float*)d_in[6];
    const float* xnw        = (const float*)d_in[7];
    const float* xnb        = (const float*)d_in[8];
    const float* rms_w      = (const float*)d_in[9];
    const float* out_proj_w = (const float*)d_in[10];
    float* out = (float*)d_out;

    __half *pWinH, *pWoutH, *pLnH, *pGH;
    float *pZx;
    cudaGetSymbolAddress((void**)&pWinH,  g_Winh);
    cudaGetSymbolAddress((void**)&pWoutH, g_Wouth);
    cudaGetSymbolAddress((void**)&pLnH,   g_lnh);
    cudaGetSymbolAddress((void**)&pGH,    g_gh);
    cudaGetSymbolAddress((void**)&pZx,    g_zx);

    static int smem_set = 0;
    if (!smem_set) {
        cudaFuncSetAttribute(gemm_hc, cudaFuncAttributeMaxDynamicSharedMemorySize, GEMM_SMEM);
        smem_set = 1;
    }

    k_normw<<<DPROJ, 256>>>(in_proj_w, pWinH, XDIM, 0.03125f);
    k_normw<<<XDIM, 256>>>(out_proj_w, pWoutH, D_INNER, 1.0f);

    k_layernorm<<<R_TOT, 256>>>(u, xnw, xnb);

    gemm_hc<<<dim3(DPROJP / GBN, R_TOT / GBM), 128, GEMM_SMEM>>>(pLnH, pWinH, pZx, XDIM, DPROJP);

    k_conv<<<(R_TOT * CONVDIM + 255) / 256, 256>>>(conv_w, conv_b);
    k_dtcum<<<NBC * NHEADS, 256>>>(dt_bias, A_log);

    k_scores_h<<<dim3(NBC, 3), 256>>>();
    k_states_h<<<dim3(NBC, NHEADS), 256>>>();
    k_scan<<<dim3(NBATCH, NHEADS), 256>>>();
    k_yfused<<<dim3(NBC, NHEADS, 2), 256>>>();

    k_gate<<<R_TOT, 256>>>(Dp, rms_w);

    gemm_hc<<<dim3(XDIM / GBN, R_TOT / GBM), 128, GEMM_SMEM>>>(pGH, pWoutH, out, D_INNER, XDIM);
}

// round 10
// speedup vs baseline: 5.7663x; 1.0529x over previous
#include <cuda_runtime.h>
#include <cuda_fp16.h>
#include <math.h>
#include <stdint.h>

// ---------------- problem constants ----------------
#define XDIM    1024
#define D_STATE 64
#define HEADDIM 128
#define D_INNER 2048
#define NHEADS  16
#define CONVDIM 2176              // D_INNER + 2*64
#define DPROJ   4240              // 2*2048 + 2*64 + 16
#define DPROJP  4352              // padded to 128-multiple for GEMM tiles
#define CHUNK   256
#define NBATCH  2
#define SEQLEN  4096
#define NCPB    16
#define NBC     32
#define R_TOT   8192

// ---------------- device scratch ----------------
__device__ __half g_lnh [(size_t)R_TOT * XDIM];
__device__ __half g_Winh[(size_t)DPROJP * XDIM];     // rows >= DPROJ stay zero (.bss)
__device__ __half g_Wouth[(size_t)XDIM * D_INNER];
__device__ __half g_gh  [(size_t)R_TOT * D_INNER];
__device__ __half g_xBCh[(size_t)R_TOT * CONVDIM];   // fp16 conv output (only copy)
__device__ __half g_yh  [(size_t)R_TOT * D_INNER];   // fp16 y
__device__ float g_zx  [(size_t)R_TOT * DPROJP];
__device__ float g_dt  [(size_t)R_TOT * NHEADS];
__device__ float g_cum [(size_t)NBC * NHEADS * CHUNK];
__device__ float g_cdec[(size_t)NBC * NHEADS];
__device__ float g_S   [(size_t)NBC * CHUNK * CHUNK];
__device__ float g_st  [(size_t)NBC * NHEADS * HEADDIM * D_STATE];
__device__ float g_ps  [(size_t)NBC * NHEADS * HEADDIM * D_STATE];

// ---------------- PTX helpers (baseline PTX only) ----------------
__device__ __forceinline__ uint32_t smem_u32(const void* p) {
    uint32_t a;
    asm("{ .reg .u64 t; cvta.to.shared.u64 t, %1; cvt.u32.u64 %0, t; }" : "=r"(a) : "l"(p));
    return a;
}
__device__ __forceinline__ uint32_t pack2(float a, float b) {
    __half2 h = __floats2half2_rn(a, b);
    return *(uint32_t*)&h;
}
__device__ __forceinline__ uint32_t pack2h(__half a, __half b) {
    __half2 h = __halves2half2(a, b);
    return *(uint32_t*)&h;
}
#define CP_ASYNC16(s, g) \
    asm volatile("cp.async.cg.shared.global [%0], [%1], 16;" :: "r"(s), "l"(g))
#define CP_COMMIT() asm volatile("cp.async.commit_group;" ::: "memory")
#define CP_WAIT(n)  asm volatile("cp.async.wait_group %0;" :: "n"(n) : "memory")

__device__ __forceinline__ void ldsm_x4(uint32_t* r, uint32_t addr) {
    asm volatile("ldmatrix.sync.aligned.m8n8.x4.shared.b16 {%0,%1,%2,%3}, [%4];"
        : "=r"(r[0]), "=r"(r[1]), "=r"(r[2]), "=r"(r[3]) : "r"(addr));
}
__device__ __forceinline__ void mma_fp16(float* d, const uint32_t* a, const uint32_t* b) {
    asm volatile("mma.sync.aligned.m16n8k16.row.col.f32.f16.f16.f32 "
        "{%0,%1,%2,%3},{%4,%5,%6,%7},{%8,%9},{%0,%1,%2,%3};"
        : "+f"(d[0]), "+f"(d[1]), "+f"(d[2]), "+f"(d[3])
        : "r"(a[0]), "r"(a[1]), "r"(a[2]), "r"(a[3]), "r"(b[0]), "r"(b[1]));
}

// ================= fp16 tensor-core GEMM: C[M,N] = A[M,K] * B[N,K]^T =================
#define GBM 128
#define GBN 128
#define GBK 64
#define GSTG 3
#define TB_A (GBM * GBK * 2)
#define TB_B (GBN * GBK * 2)
#define STAGE_B (TB_A + TB_B)
#define GEMM_SMEM (GSTG * STAGE_B)

__device__ __forceinline__ void gemm_load_tile_h(const __half* Ab, const __half* Bb,
                                                 int K, int t, uint32_t sb, int tid) {
    const __half* Ap = Ab + (size_t)t * GBK;
    const __half* Bp = Bb + (size_t)t * GBK;
    #pragma unroll
    for (int j = 0; j < 8; j++) {
        int c = tid + 128 * j;
        int row = c >> 3;
        uint32_t cc = (uint32_t)(c & 7) * 16;
        uint32_t off = (uint32_t)row * 128 + (cc ^ (((uint32_t)row & 7) << 4));
        CP_ASYNC16(sb + off, Ap + (size_t)row * K + (cc >> 1));
    }
    uint32_t sb2 = sb + TB_A;
    #pragma unroll
    for (int j = 0; j < 8; j++) {
        int c = tid + 128 * j;
        int row = c >> 3;
        uint32_t cc = (uint32_t)(c & 7) * 16;
        uint32_t off = (uint32_t)row * 128 + (cc ^ (((uint32_t)row & 7) << 4));
        CP_ASYNC16(sb2 + off, Bp + (size_t)row * K + (cc >> 1));
    }
    CP_COMMIT();
}

__global__ __launch_bounds__(128, 2) void gemm_hc(const __half* __restrict__ A,
                                                  const __half* __restrict__ B,
                                                  float* __restrict__ C,
                                                  int K, int ldc) {
    extern __shared__ char sm[];
    uint32_t sbase = smem_u32(sm);
    int tid = threadIdx.x, lane = tid & 31, wid = tid >> 5;
    int wm = (wid & 1) * 64;
    int wn = (wid >> 1) * 64;
    int m0 = blockIdx.y * GBM;
    int n0 = blockIdx.x * GBN;
    const __half* Ab = A + (size_t)m0 * K;
    const __half* Bb = B + (size_t)n0 * K;

    int a_row = wm + (lane & 15);
    uint32_t a_kb = (uint32_t)(lane >> 4) * 16;
    int b_row = wn + (lane & 7) + ((lane & 16) ? 8 : 0);
    uint32_t b_kb = (lane & 8) ? 16u : 0u;

    float acc[4][8][4];
    #pragma unroll
    for (int mt = 0; mt < 4; mt++)
        #pragma unroll
        for (int nt = 0; nt < 8; nt++)
            #pragma unroll
            for (int q = 0; q < 4; q++) acc[mt][nt][q] = 0.f;

    int T = K / GBK;
    gemm_load_tile_h(Ab, Bb, K, 0, sbase, tid);
    gemm_load_tile_h(Ab, Bb, K, 1, sbase + STAGE_B, tid);

    for (int t = 0; t < T; t++) {
        CP_WAIT(1);
        __syncthreads();
        if (t + 2 < T)
            gemm_load_tile_h(Ab, Bb, K, t + 2, sbase + ((t + 2) % GSTG) * STAGE_B, tid);
        uint32_t sa = sbase + (t % GSTG) * STAGE_B;
        uint32_t sb = sa + TB_A;

        #pragma unroll
        for (int ks = 0; ks < 4; ks++) {
            uint32_t afr[4][4];
            #pragma unroll
            for (int mt = 0; mt < 4; mt++) {
                uint32_t row = (uint32_t)(a_row + mt * 16);
                uint32_t c = (uint32_t)ks * 32 + a_kb;
                ldsm_x4(afr[mt], sa + row * 128 + (c ^ ((row & 7) << 4)));
            }
            uint32_t bfr[4][4];
            #pragma unroll
            for (int nh = 0; nh < 4; nh++) {
                uint32_t row = (uint32_t)(b_row + nh * 16);
                uint32_t c = (uint32_t)ks * 32 + b_kb;
                ldsm_x4(bfr[nh], sb + row * 128 + (c ^ ((row & 7) << 4)));
            }
            #pragma unroll
            for (int mt = 0; mt < 4; mt++)
                #pragma unroll
                for (int nt = 0; nt < 8; nt++)
                    mma_fp16(acc[mt][nt], afr[mt], &bfr[nt >> 1][(nt & 1) * 2]);
        }
    }

    int g = lane >> 2, tg = lane & 3;
    #pragma unroll
    for (int mt = 0; mt < 4; mt++) {
        int rowa = m0 + wm + mt * 16 + g;
        #pragma unroll
        for (int nt = 0; nt < 8; nt++) {
            int col = n0 + wn + nt * 8 + tg * 2;
            *(float2*)(C + (size_t)rowa * ldc + col) =
                make_float2(acc[mt][nt][0], acc[mt][nt][1]);
            *(float2*)(C + (size_t)(rowa + 8) * ldc + col) =
                make_float2(acc[mt][nt][2], acc[mt][nt][3]);
        }
    }
}

// ============ K6a (fp16 MMA): S tile = C @ B^T, K=64 ============
__global__ __launch_bounds__(256, 1) void k_scores_h() {
    __shared__ __align__(16) __half As[128 * 64];
    __shared__ __align__(16) __half Bs[128 * 64];
    int bc = blockIdx.x;
    int tile = blockIdx.y;              // 0:(0,0) 1:(1,0) 2:(1,1)
    int i0 = (tile != 0) ? 128 : 0;
    int j0 = (tile == 2) ? 128 : 0;
    int row0 = bc * CHUNK;
    int tid = threadIdx.x, lane = tid & 31, wid = tid >> 5;

    uint32_t as_base = smem_u32(As);
    uint32_t bs_base = smem_u32(Bs);
    const __half* Cb = g_xBCh + (size_t)(row0 + i0) * CONVDIM + D_INNER + D_STATE;
    const __half* Bb = g_xBCh + (size_t)(row0 + j0) * CONVDIM + D_INNER;
    #pragma unroll
    for (int j = 0; j < 4; j++) {
        int c = tid + 256 * j;
        int row = c >> 3;
        uint32_t cc = (uint32_t)(c & 7) * 16;
        uint32_t off = (uint32_t)row * 128 + (cc ^ (((uint32_t)row & 7) << 4));
        CP_ASYNC16(as_base + off, Cb + (size_t)row * CONVDIM + (cc >> 1));
        CP_ASYNC16(bs_base + off, Bb + (size_t)row * CONVDIM + (cc >> 1));
    }
    CP_COMMIT();
    CP_WAIT(0);
    __syncthreads();

    int wm = (wid & 3) * 32;
    int wn = (wid >> 2) * 64;
    int a_row = wm + (lane & 15);
    uint32_t a_kb = (uint32_t)(lane >> 4) * 16;
    int b_row = wn + (lane & 7) + ((lane & 16) ? 8 : 0);
    uint32_t b_kb = (lane & 8) ? 16u : 0u;

    float acc[2][8][4];
    #pragma unroll
    for (int mt = 0; mt < 2; mt++)
        #pragma unroll
        for (int nt = 0; nt < 8; nt++)
            #pragma unroll
            for (int q = 0; q < 4; q++) acc[mt][nt][q] = 0.f;

    #pragma unroll
    for (int ks = 0; ks < 4; ks++) {
        uint32_t afr[2][4];
        #pragma unroll
        for (int mt = 0; mt < 2; mt++) {
            uint32_t row = (uint32_t)(a_row + mt * 16);
            uint32_t c = (uint32_t)ks * 32 + a_kb;
            ldsm_x4(afr[mt], as_base + row * 128 + (c ^ ((row & 7) << 4)));
        }
        uint32_t bfr[4][4];
        #pragma unroll
        for (int nh = 0; nh < 4; nh++) {
            uint32_t row = (uint32_t)(b_row + nh * 16);
            uint32_t c = (uint32_t)ks * 32 + b_kb;
            ldsm_x4(bfr[nh], bs_base + row * 128 + (c ^ ((row & 7) << 4)));
        }
        #pragma unroll
        for (int mt = 0; mt < 2; mt++)
            #pragma unroll
            for (int nt = 0; nt < 8; nt++)
                mma_fp16(acc[mt][nt], afr[mt], &bfr[nt >> 1][(nt & 1) * 2]);
    }

    int g = lane >> 2, tg = lane & 3;
    #pragma unroll
    for (int mt = 0; mt < 2; mt++) {
        int irow = i0 + wm + mt * 16 + g;
        #pragma unroll
        for (int nt = 0; nt < 8; nt++) {
            int col = j0 + wn + nt * 8 + tg * 2;
            *(float2*)(g_S + ((size_t)bc * CHUNK + irow) * CHUNK + col) =
                make_float2(acc[mt][nt][0], acc[mt][nt][1]);
            *(float2*)(g_S + ((size_t)bc * CHUNK + irow + 8) * CHUNK + col) =
                make_float2(acc[mt][nt][2], acc[mt][nt][3]);
        }
    }
}

// ============ K7 (fp16 MMA): states[p][n] = sum_t (x[t][p]*w_t) * B[t][n] ============
__global__ __launch_bounds__(256, 1) void k_states_h() {
    __shared__ __align__(16) __half As[128 * 64];
    __shared__ __align__(16) __half Bs[64 * 64];
    __shared__ float wsh[256];
    int bc = blockIdx.x, h = blockIdx.y;
    int row0 = bc * CHUNK;
    int cb = (bc * NHEADS + h) * CHUNK;
    int tid = threadIdx.x, lane = tid & 31, wid = tid >> 5;

    float cum_last = g_cum[cb + 255];
    wsh[tid] = g_dt[(size_t)(row0 + tid) * NHEADS + h] *
               __expf(cum_last - g_cum[cb + tid]);

    uint32_t as_base = smem_u32(As);
    uint32_t bs_base = smem_u32(Bs);

    int wm = (wid & 3) * 32;
    int wn = (wid >> 2) * 32;
    int a_row = wm + (lane & 15);
    uint32_t a_kb = (uint32_t)(lane >> 4) * 16;
    int b_row = wn + (lane & 7) + ((lane & 16) ? 8 : 0);
    uint32_t b_kb = (lane & 8) ? 16u : 0u;

    float acc[2][4][4];
    #pragma unroll
    for (int mt = 0; mt < 2; mt++)
        #pragma unroll
        for (int nt = 0; nt < 4; nt++)
            #pragma unroll
            for (int q = 0; q < 4; q++) acc[mt][nt][q] = 0.f;

    for (int kt = 0; kt < 4; kt++) {
        int t0 = kt * 64;
        __syncthreads();
        #pragma unroll
        for (int jp = 0; jp < 4; jp++) {
            int pair = wid + 8 * jp;
            int t = t0 + 2 * pair;
            const __half* x0 = g_xBCh + (size_t)(row0 + t) * CONVDIM + h * HEADDIM;
            const __half* x1 = x0 + CONVDIM;
            float w0 = wsh[t], w1 = wsh[t + 1];
            #pragma unroll
            for (int r = 0; r < 4; r++) {
                int p = lane + 32 * r;
                uint32_t cbyte = (uint32_t)pair * 4;
                uint32_t off = (uint32_t)p * 128 + (cbyte ^ (((uint32_t)p & 7) << 4));
                *(uint32_t*)((char*)As + off) =
                    pack2(__half2float(x0[p]) * w0, __half2float(x1[p]) * w1);
            }
        }
        #pragma unroll
        for (int q = 0; q < 8; q++) {
            int idx = tid + 256 * q;
            int n = idx >> 5, pair = idx & 31;
            int t = t0 + 2 * pair;
            const __half* b0 = g_xBCh + (size_t)(row0 + t) * CONVDIM + D_INNER;
            uint32_t cbyte = (uint32_t)pair * 4;
            uint32_t off = (uint32_t)n * 128 + (cbyte ^ (((uint32_t)n & 7) << 4));
            *(uint32_t*)((char*)Bs + off) = pack2h(b0[n], b0[CONVDIM + n]);
        }
        __syncthreads();
        #pragma unroll
        for (int ks = 0; ks < 4; ks++) {
            uint32_t afr[2][4];
            #pragma unroll
            for (int mt = 0; mt < 2; mt++) {
                uint32_t row = (uint32_t)(a_row + mt * 16);
                uint32_t c = (uint32_t)ks * 32 + a_kb;
                ldsm_x4(afr[mt], as_base + row * 128 + (c ^ ((row & 7) << 4)));
            }
            uint32_t bfr[2][4];
            #pragma unroll
            for (int nh = 0; nh < 2; nh++) {
                uint32_t row = (uint32_t)(b_row + nh * 16);
                uint32_t c = (uint32_t)ks * 32 + b_kb;
                ldsm_x4(bfr[nh], bs_base + row * 128 + (c ^ ((row & 7) << 4)));
            }
            #pragma unroll
            for (int mt = 0; mt < 2; mt++)
                #pragma unroll
                for (int nt = 0; nt < 4; nt++)
                    mma_fp16(acc[mt][nt], afr[mt], &bfr[nt >> 1][(nt & 1) * 2]);
        }
    }

    size_t base = (size_t)(bc * NHEADS + h) * HEADDIM * D_STATE;
    int g = lane >> 2, tg = lane & 3;
    #pragma unroll
    for (int mt = 0; mt < 2; mt++) {
        int prow = wm + mt * 16 + g;
        #pragma unroll
        for (int nt = 0; nt < 4; nt++) {
            int col = wn + nt * 8 + tg * 2;
            *(float2*)(g_st + base + (size_t)prow * D_STATE + col) =
                make_float2(acc[mt][nt][0], acc[mt][nt][1]);
            *(float2*)(g_st + base + (size_t)(prow + 8) * D_STATE + col) =
                make_float2(acc[mt][nt][2], acc[mt][nt][3]);
        }
    }
}

// ============ fused SSD y-kernel (fp16 fragments, fp32 accumulate, fp16 y out) ============
__global__ __launch_bounds__(256, 1) void k_yfused() {
    __shared__ __align__(16) __half As[128 * 64];
    __shared__ __align__(16) __half Bs[128 * 64];
    __shared__ float gj_all[256];
    __shared__ float cas[8];
    int bc = blockIdx.x, h = blockIdx.y, ih = blockIdx.z;
    int i_base = ih * 128;
    int row0 = bc * CHUNK;
    int cb = (bc * NHEADS + h) * CHUNK;
    size_t psb = (size_t)(bc * NHEADS + h) * HEADDIM * D_STATE;

    int tid = threadIdx.x, lane = tid & 31, wid = tid >> 5;
    int wm = (wid & 3) * 32;
    int wn = (wid >> 2) * 64;

    int si = tid >> 1;
    int sj = (tid & 1) * 32;
    int gi = i_base + si;
    float ci = g_cum[cb + gi];
    float ei = __expf(ci);

    uint32_t as_base = smem_u32(As);
    uint32_t bs_base = smem_u32(Bs);

    int a_row = wm + (lane & 15);
    uint32_t a_kb = (uint32_t)(lane >> 4) * 16;
    int b_row = wn + (lane & 7) + ((lane & 16) ? 8 : 0);
    uint32_t b_kb = (lane & 8) ? 16u : 0u;

    int natt64 = (ih + 1) * 2;
    int nattj = natt64 * 64;

    if (tid < nattj) {
        int j = tid;
        float ca = g_cum[cb + (j & ~31) + 31];
        gj_all[j] = __expf(ca - g_cum[cb + j]) *
                    g_dt[(size_t)(row0 + j) * NHEADS + h];
    }
    if (tid < natt64 * 2) cas[tid] = g_cum[cb + tid * 32 + 31];

    float acc[2][8][4];
    #pragma unroll
    for (int mt = 0; mt < 2; mt++)
        #pragma unroll
        for (int nt = 0; nt < 8; nt++)
            #pragma unroll
            for (int q = 0; q < 4; q++) acc[mt][nt][q] = 0.f;

    int ntiles = natt64 + 1;
    for (int kt = 0; kt < ntiles; kt++) {
        __syncthreads();
        if (kt < natt64) {
            int j0 = kt * 64;
            int jb = j0 + sj;
            if (gi >= jb + 31) {
                float fi = __expf(ci - cas[jb >> 5]);
                const float* Srow = g_S + ((size_t)bc * CHUNK + gi) * CHUNK + jb;
                const float* gjp = gj_all + jb;
                #pragma unroll
                for (int q = 0; q < 4; q++) {
                    float4 s0 = *(const float4*)(Srow + q * 8);
                    float4 s1 = *(const float4*)(Srow + q * 8 + 4);
                    uint4 u;
                    u.x = pack2(s0.x * fi * gjp[q*8+0], s0.y * fi * gjp[q*8+1]);
                    u.y = pack2(s0.z * fi * gjp[q*8+2], s0.w * fi * gjp[q*8+3]);
                    u.z = pack2(s1.x * fi * gjp[q*8+4], s1.y * fi * gjp[q*8+5]);
                    u.w = pack2(s1.z * fi * gjp[q*8+6], s1.w * fi * gjp[q*8+7]);
                    uint32_t cbyte = (uint32_t)(sj * 2 + q * 16);
                    uint32_t off = (uint32_t)si * 128 + (cbyte ^ (((uint32_t)si & 7) << 4));
                    *(uint4*)((char*)As + off) = u;
                }
            } else if (gi >= jb) {
                #pragma unroll
                for (int q = 0; q < 4; q++) {
                    float v[8];
                    #pragma unroll
                    for (int r = 0; r < 8; r++) {
                        int j = jb + q * 8 + r;
                        float a = 0.f;
                        if (j <= gi)
                            a = g_S[((size_t)bc * CHUNK + gi) * CHUNK + j] *
                                __expf(ci - g_cum[cb + j]) *
                                g_dt[(size_t)(row0 + j) * NHEADS + h];
                        v[r] = a;
                    }
                    uint4 u;
                    u.x = pack2(v[0], v[1]); u.y = pack2(v[2], v[3]);
                    u.z = pack2(v[4], v[5]); u.w = pack2(v[6], v[7]);
                    uint32_t cbyte = (uint32_t)(sj * 2 + q * 16);
                    uint32_t off = (uint32_t)si * 128 + (cbyte ^ (((uint32_t)si & 7) << 4));
                    *(uint4*)((char*)As + off) = u;
                }
            } else {
                #pragma unroll
                for (int q = 0; q < 4; q++) {
                    uint32_t cbyte = (uint32_t)(sj * 2 + q * 16);
                    uint32_t off = (uint32_t)si * 128 + (cbyte ^ (((uint32_t)si & 7) << 4));
                    *(uint4*)((char*)As + off) = make_uint4(0, 0, 0, 0);
                }
            }
            #pragma unroll
            for (int jp = 0; jp < 4; jp++) {
                int pair = wid + 8 * jp;
                int j = j0 + 2 * pair;
                const __half* x0 = g_xBCh + (size_t)(row0 + j) * CONVDIM + h * HEADDIM;
                const __half* x1 = x0 + CONVDIM;
                #pragma unroll
                for (int r = 0; r < 4; r++) {
                    int p = lane + 32 * r;
                    uint32_t cbyte = (uint32_t)pair * 4;
                    uint32_t off = (uint32_t)p * 128 + (cbyte ^ (((uint32_t)p & 7) << 4));
                    *(uint32_t*)((char*)Bs + off) = pack2h(x0[p], x1[p]);
                }
            }
        } else {
            // state tile: A = Ce[i][n] from fp16 C, B = P[p][n]
            const __half2* crow = (const __half2*)(g_xBCh + (size_t)(row0 + gi) * CONVDIM
                                                   + D_INNER + D_STATE + sj);
            #pragma unroll
            for (int q = 0; q < 4; q++) {
                uint4 hv = *(const uint4*)(crow + q * 4);
                float2 f0 = __half22float2(*(__half2*)&hv.x);
                float2 f1 = __half22float2(*(__half2*)&hv.y);
                float2 f2 = __half22float2(*(__half2*)&hv.z);
                float2 f3 = __half22float2(*(__half2*)&hv.w);
                uint4 u;
                u.x = pack2(f0.x * ei, f0.y * ei);
                u.y = pack2(f1.x * ei, f1.y * ei);
                u.z = pack2(f2.x * ei, f2.y * ei);
                u.w = pack2(f3.x * ei, f3.y * ei);
                uint32_t cbyte = (uint32_t)(sj * 2 + q * 16);
                uint32_t off = (uint32_t)si * 128 + (cbyte ^ (((uint32_t)si & 7) << 4));
                *(uint4*)((char*)As + off) = u;
            }
            int pr = tid >> 1;
            int nc = (tid & 1) * 32;
            const float* prow = g_ps + psb + (size_t)pr * D_STATE + nc;
            #pragma unroll
            for (int q = 0; q < 4; q++) {
                float4 p0 = *(const float4*)(prow + q * 8);
                float4 p1 = *(const float4*)(prow + q * 8 + 4);
                uint4 u;
                u.x = pack2(p0.x, p0.y); u.y = pack2(p0.z, p0.w);
                u.z = pack2(p1.x, p1.y); u.w = pack2(p1.z, p1.w);
                uint32_t cbyte = (uint32_t)(nc * 2 + q * 16);
                uint32_t off = (uint32_t)pr * 128 + (cbyte ^ (((uint32_t)pr & 7) << 4));
                *(uint4*)((char*)Bs + off) = u;
            }
        }
        __syncthreads();
        #pragma unroll
        for (int ks = 0; ks < 4; ks++) {
            uint32_t afr[2][4];
            #pragma unroll
            for (int mt = 0; mt < 2; mt++) {
                uint32_t row = (uint32_t)(a_row + mt * 16);
                uint32_t c = (uint32_t)ks * 32 + a_kb;
                ldsm_x4(afr[mt], as_base + row * 128 + (c ^ ((row & 7) << 4)));
            }
            uint32_t bfr[4][4];
            #pragma unroll
            for (int nh = 0; nh < 4; nh++) {
                uint32_t row = (uint32_t)(b_row + nh * 16);
                uint32_t c = (uint32_t)ks * 32 + b_kb;
                ldsm_x4(bfr[nh], bs_base + row * 128 + (c ^ ((row & 7) << 4)));
            }
            #pragma unroll
            for (int mt = 0; mt < 2; mt++)
                #pragma unroll
                for (int nt = 0; nt < 8; nt++)
                    mma_fp16(acc[mt][nt], afr[mt], &bfr[nt >> 1][(nt & 1) * 2]);
        }
    }

    int g = lane >> 2, tg = lane & 3;
    #pragma unroll
    for (int mt = 0; mt < 2; mt++) {
        int orow = row0 + i_base + wm + mt * 16 + g;
        #pragma unroll
        for (int nt = 0; nt < 8; nt++) {
            int col = h * HEADDIM + wn + nt * 8 + tg * 2;
            *(uint32_t*)(g_yh + (size_t)orow * D_INNER + col) =
                pack2(acc[mt][nt][0], acc[mt][nt][1]);
            *(uint32_t*)(g_yh + (size_t)(orow + 8) * D_INNER + col) =
                pack2(acc[mt][nt][2], acc[mt][nt][3]);
        }
    }
}

// ---------------- reductions ----------------
__device__ __forceinline__ float blockReduceSum256(float v) {
    __shared__ float red[8];
    __shared__ float tot;
    int lane = threadIdx.x & 31, wid = threadIdx.x >> 5;
    #pragma unroll
    for (int o = 16; o; o >>= 1) v += __shfl_down_sync(0xffffffffu, v, o);
    if (lane == 0) red[wid] = v;
    __syncthreads();
    if (wid == 0) {
        float w = (lane < 8) ? red[lane] : 0.f;
        #pragma unroll
        for (int o = 4; o; o >>= 1) w += __shfl_down_sync(0xffffffffu, w, o);
        if (lane == 0) tot = w;
    }
    __syncthreads();
    return tot;
}

// ---------------- K1: l2-normalize weight rows (fp16 output) ----------------
__global__ __launch_bounds__(256) void k_normw(const float* __restrict__ W,
                                               __half* __restrict__ Wo, int K, float extra) {
    int r = blockIdx.x;
    const float* wr = W + (size_t)r * K;
    float s2 = 0.f;
    for (int i = threadIdx.x; i < K; i += 256) { float v = wr[i]; s2 += v * v; }
    float totv = blockReduceSum256(s2);
    float sc = extra / fmaxf(sqrtf(totv), 1e-6f);
    for (int i = threadIdx.x; i < K; i += 256)
        Wo[(size_t)r * K + i] = __float2half_rn(wr[i] * sc);
}

// ---------------- K2: layernorm (fp16 output) ----------------
__global__ __launch_bounds__(256) void k_layernorm(const float* __restrict__ u,
                                                   const float* __restrict__ w,
                                                   const float* __restrict__ b) {
    int row = blockIdx.x;
    const float* ur = u + (size_t)row * XDIM;
    float v[4]; float s = 0.f, s2 = 0.f;
    #pragma unroll
    for (int k = 0; k < 4; k++) {
        v[k] = ur[threadIdx.x + 256 * k];
        s += v[k]; s2 += v[k] * v[k];
    }
    float sum = blockReduceSum256(s);
    float sumsq = blockReduceSum256(s2);
    float mu = sum * (1.f / XDIM);
    float var = sumsq * (1.f / XDIM) - mu * mu;
    float inv = rsqrtf(var + 1e-5f);
    #pragma unroll
    for (int k = 0; k < 4; k++) {
        int d = threadIdx.x + 256 * k;
        g_lnh[(size_t)row * XDIM + d] = __float2half_rn((v[k] - mu) * inv * w[d] + b[d]);
    }
}

// ---------------- K4: depthwise causal conv + bias + silu (fp16 output) ----------------
__global__ __launch_bounds__(256) void k_conv(const float* __restrict__ cw,
                                              const float* __restrict__ cb) {
    int gi = blockIdx.x * 256 + threadIdx.x;
    if (gi >= R_TOT * CONVDIM) return;
    int ch = gi % CONVDIM;
    int row = gi / CONVDIM;
    int l = row & (SEQLEN - 1);
    float acc = cb[ch];
    #pragma unroll
    for (int d = 0; d < 4; d++) {
        int ll = l - 3 + d;
        if (ll >= 0)
            acc += cw[ch * 4 + d] * g_zx[(size_t)(row - 3 + d) * DPROJP + D_INNER + ch];
    }
    float v = acc / (1.f + __expf(-acc));
    g_xBCh[(size_t)row * CONVDIM + ch] = __float2half_rn(v);
}

// ---------------- K5: dt softplus + per-chunk cumulative dA ----------------
__global__ __launch_bounds__(256) void k_dtcum(const float* __restrict__ dt_bias,
                                               const float* __restrict__ A_log) {
    int bch = blockIdx.x;
    int h = bch & 15, bc = bch >> 4;
    int t = threadIdx.x;
    int row = bc * CHUNK + t;
    float x = g_zx[(size_t)row * DPROJP + (D_INNER + CONVDIM) + h] + dt_bias[h];
    float dtv = (x > 20.f) ? x : log1pf(expf(x));
    g_dt[(size_t)row * NHEADS + h] = dtv;
    float dA = dtv * (-expf(A_log[h]));
    __shared__ float s[256];
    s[t] = dA;
    __syncthreads();
    #pragma unroll
    for (int off = 1; off < 256; off <<= 1) {
        float pv = (t >= off) ? s[t - off] : 0.f;
        __syncthreads();
        s[t] += pv;
        __syncthreads();
    }
    g_cum[(size_t)bch * CHUNK + t] = s[t];
    if (t == 255) g_cdec[bch] = __expf(s[255]);
}

// ---------------- K8: inter-chunk scan (parallel over elements, serial over chunks) ----------------
__global__ __launch_bounds__(256) void k_scan() {
    int b = blockIdx.x, h = blockIdx.y, z = blockIdx.z;
    int tid = threadIdx.x;
    int e0 = z * 1024 + tid * 4;      // this thread's 4 elements within [0, 8192)
    float4 carry = make_float4(0.f, 0.f, 0.f, 0.f);
    for (int c = 0; c < NCPB; c++) {
        int bch = (b * NCPB + c) * NHEADS + h;
        float dec = g_cdec[bch];
        size_t base = (size_t)bch * HEADDIM * D_STATE + e0;
        *(float4*)(g_ps + base) = carry;
        float4 st = *(const float4*)(g_st + base);
        carry.x = carry.x * dec + st.x;
        carry.y = carry.y * dec + st.y;
        carry.z = carry.z * dec + st.z;
        carry.w = carry.w * dec + st.w;
    }
}

// ---------------- K10: y += D*x, gate, RMS norm (fp16 in/out) ----------------
__global__ __launch_bounds__(256) void k_gate(const float* __restrict__ Dp,
                                              const float* __restrict__ rms_w) {
    int row = blockIdx.x;
    int tid = threadIdx.x;
    float gg[8];
    float s2 = 0.f;
    #pragma unroll
    for (int k = 0; k < 8; k++) {
        int d = tid + 256 * k;
        float xv = __half2float(g_xBCh[(size_t)row * CONVDIM + d]);
        float yv = __half2float(g_yh[(size_t)row * D_INNER + d]);
        float v = yv + Dp[d >> 7] * xv;
        float z = g_zx[(size_t)row * DPROJP + d];
        float sil = z / (1.f + __expf(-z));
        float g = v * sil;
        gg[k] = g;
        s2 += g * g;
    }
    float tot = blockReduceSum256(s2);
    float sc = rsqrtf(tot * (1.f / D_INNER) + 1e-5f);
    #pragma unroll
    for (int k = 0; k < 8; k++) {
        int d = tid + 256 * k;
        g_gh[(size_t)row * D_INNER + d] = __float2half_rn(gg[k] * sc * rms_w[d]);
    }
}

// ---------------- host launcher ----------------
extern "C" void kernel_launch(void* const* d_in, const int* in_sizes, int n_in,
                              void* d_out, int out_size) {
    const float* u          = (const float*)d_in[0];
    const float* in_proj_w  = (const float*)d_in[1];
    const float* conv_w     = (const float*)d_in[2];
    const float* conv_b     = (const float*)d_in[3];
    const float* dt_bias    = (const float*)d_in[4];
    const float* A_log      = (const float*)d_in[5];
    const float* Dp         = (const float*)d_in[6];
    const float* xnw        = (const float*)d_in[7];
    const float* xnb        = (const float*)d_in[8];
    const float* rms_w      = (const float*)d_in[9];
    const float* out_proj_w = (const float*)d_in[10];
    float* out = (float*)d_out;

    __half *pWinH, *pWoutH, *pLnH, *pGH;
    float *pZx;
    cudaGetSymbolAddress((void**)&pWinH,  g_Winh);
    cudaGetSymbolAddress((void**)&pWoutH, g_Wouth);
    cudaGetSymbolAddress((void**)&pLnH,   g_lnh);
    cudaGetSymbolAddress((void**)&pGH,    g_gh);
    cudaGetSymbolAddress((void**)&pZx,    g_zx);

    static int smem_set = 0;
    if (!smem_set) {
        cudaFuncSetAttribute(gemm_hc, cudaFuncAttributeMaxDynamicSharedMemorySize, GEMM_SMEM);
        smem_set = 1;
    }

    k_normw<<<DPROJ, 256>>>(in_proj_w, pWinH, XDIM, 0.03125f);
    k_normw<<<XDIM, 256>>>(out_proj_w, pWoutH, D_INNER, 1.0f);

    k_layernorm<<<R_TOT, 256>>>(u, xnw, xnb);

    gemm_hc<<<dim3(DPROJP / GBN, R_TOT / GBM), 128, GEMM_SMEM>>>(pLnH, pWinH, pZx, XDIM, DPROJP);

    k_conv<<<(R_TOT * CONVDIM + 255) / 256, 256>>>(conv_w, conv_b);
    k_dtcum<<<NBC * NHEADS, 256>>>(dt_bias, A_log);

    k_scores_h<<<dim3(NBC, 3), 256>>>();
    k_states_h<<<dim3(NBC, NHEADS), 256>>>();
    k_scan<<<dim3(NBATCH, NHEADS, 8), 256>>>();
    k_yfused<<<dim3(NBC, NHEADS, 2), 256>>>();

    k_gate<<<R_TOT, 256>>>(Dp, rms_w);

    gemm_hc<<<dim3(XDIM / GBN, R_TOT / GBM), 128, GEMM_SMEM>>>(pGH, pWoutH, out, D_INNER, XDIM);
}

// round 11
// speedup vs baseline: 6.3411x; 1.0997x over previous
#include <cuda_runtime.h>
#include <cuda_fp16.h>
#include <math.h>
#include <stdint.h>

// ---------------- problem constants ----------------
#define XDIM    1024
#define D_STATE 64
#define HEADDIM 128
#define D_INNER 2048
#define NHEADS  16
#define CONVDIM 2176              // D_INNER + 2*64
#define DPROJ   4240              // 2*2048 + 2*64 + 16
#define DPROJP  4352              // padded to 128-multiple for GEMM tiles
#define CHUNK   256
#define NBATCH  2
#define SEQLEN  4096
#define NCPB    16
#define NBC     32
#define R_TOT   8192

// ---------------- device scratch ----------------
__device__ __half g_lnh [(size_t)R_TOT * XDIM];
__device__ __half g_Winh[(size_t)DPROJP * XDIM];     // rows >= DPROJ stay zero (.bss)
__device__ __half g_Wouth[(size_t)XDIM * D_INNER];
__device__ __half g_gh  [(size_t)R_TOT * D_INNER];
__device__ __half g_xBCh[(size_t)R_TOT * CONVDIM];   // fp16 conv output
__device__ __half g_yh  [(size_t)R_TOT * D_INNER];   // fp16 y
__device__ __half g_Sh  [(size_t)NBC * CHUNK * CHUNK];  // fp16 scores
__device__ float g_zx  [(size_t)R_TOT * DPROJP];
__device__ float g_dt  [(size_t)R_TOT * NHEADS];
__device__ float g_cum [(size_t)NBC * NHEADS * CHUNK];
__device__ float g_cdec[(size_t)NBC * NHEADS];
__device__ float g_st  [(size_t)NBC * NHEADS * HEADDIM * D_STATE];
__device__ float g_ps  [(size_t)NBC * NHEADS * HEADDIM * D_STATE];

// ---------------- PTX helpers (baseline PTX only) ----------------
__device__ __forceinline__ uint32_t smem_u32(const void* p) {
    uint32_t a;
    asm("{ .reg .u64 t; cvta.to.shared.u64 t, %1; cvt.u32.u64 %0, t; }" : "=r"(a) : "l"(p));
    return a;
}
__device__ __forceinline__ uint32_t pack2(float a, float b) {
    __half2 h = __floats2half2_rn(a, b);
    return *(uint32_t*)&h;
}
__device__ __forceinline__ uint32_t pack2h(__half a, __half b) {
    __half2 h = __halves2half2(a, b);
    return *(uint32_t*)&h;
}
#define CP_ASYNC16(s, g) \
    asm volatile("cp.async.cg.shared.global [%0], [%1], 16;" :: "r"(s), "l"(g))
#define CP_COMMIT() asm volatile("cp.async.commit_group;" ::: "memory")
#define CP_WAIT(n)  asm volatile("cp.async.wait_group %0;" :: "n"(n) : "memory")

__device__ __forceinline__ void ldsm_x4(uint32_t* r, uint32_t addr) {
    asm volatile("ldmatrix.sync.aligned.m8n8.x4.shared.b16 {%0,%1,%2,%3}, [%4];"
        : "=r"(r[0]), "=r"(r[1]), "=r"(r[2]), "=r"(r[3]) : "r"(addr));
}
__device__ __forceinline__ void mma_fp16(float* d, const uint32_t* a, const uint32_t* b) {
    asm volatile("mma.sync.aligned.m16n8k16.row.col.f32.f16.f16.f32 "
        "{%0,%1,%2,%3},{%4,%5,%6,%7},{%8,%9},{%0,%1,%2,%3};"
        : "+f"(d[0]), "+f"(d[1]), "+f"(d[2]), "+f"(d[3])
        : "r"(a[0]), "r"(a[1]), "r"(a[2]), "r"(a[3]), "r"(b[0]), "r"(b[1]));
}

// ================= fp16 tensor-core GEMM: C[M,N] = A[M,K] * B[N,K]^T =================
#define GBM 128
#define GBN 128
#define GBK 64
#define GSTG 3
#define TB_A (GBM * GBK * 2)
#define TB_B (GBN * GBK * 2)
#define STAGE_B (TB_A + TB_B)
#define GEMM_SMEM (GSTG * STAGE_B)

__device__ __forceinline__ void gemm_load_tile_h(const __half* Ab, const __half* Bb,
                                                 int K, int t, uint32_t sb, int tid) {
    const __half* Ap = Ab + (size_t)t * GBK;
    const __half* Bp = Bb + (size_t)t * GBK;
    #pragma unroll
    for (int j = 0; j < 8; j++) {
        int c = tid + 128 * j;
        int row = c >> 3;
        uint32_t cc = (uint32_t)(c & 7) * 16;
        uint32_t off = (uint32_t)row * 128 + (cc ^ (((uint32_t)row & 7) << 4));
        CP_ASYNC16(sb + off, Ap + (size_t)row * K + (cc >> 1));
    }
    uint32_t sb2 = sb + TB_A;
    #pragma unroll
    for (int j = 0; j < 8; j++) {
        int c = tid + 128 * j;
        int row = c >> 3;
        uint32_t cc = (uint32_t)(c & 7) * 16;
        uint32_t off = (uint32_t)row * 128 + (cc ^ (((uint32_t)row & 7) << 4));
        CP_ASYNC16(sb2 + off, Bp + (size_t)row * K + (cc >> 1));
    }
    CP_COMMIT();
}

__global__ __launch_bounds__(128, 2) void gemm_hc(const __half* __restrict__ A,
                                                  const __half* __restrict__ B,
                                                  float* __restrict__ C,
                                                  int K, int ldc) {
    extern __shared__ char sm[];
    uint32_t sbase = smem_u32(sm);
    int tid = threadIdx.x, lane = tid & 31, wid = tid >> 5;
    int wm = (wid & 1) * 64;
    int wn = (wid >> 1) * 64;
    int m0 = blockIdx.y * GBM;
    int n0 = blockIdx.x * GBN;
    const __half* Ab = A + (size_t)m0 * K;
    const __half* Bb = B + (size_t)n0 * K;

    int a_row = wm + (lane & 15);
    uint32_t a_kb = (uint32_t)(lane >> 4) * 16;
    int b_row = wn + (lane & 7) + ((lane & 16) ? 8 : 0);
    uint32_t b_kb = (lane & 8) ? 16u : 0u;

    float acc[4][8][4];
    #pragma unroll
    for (int mt = 0; mt < 4; mt++)
        #pragma unroll
        for (int nt = 0; nt < 8; nt++)
            #pragma unroll
            for (int q = 0; q < 4; q++) acc[mt][nt][q] = 0.f;

    int T = K / GBK;
    gemm_load_tile_h(Ab, Bb, K, 0, sbase, tid);
    gemm_load_tile_h(Ab, Bb, K, 1, sbase + STAGE_B, tid);

    for (int t = 0; t < T; t++) {
        CP_WAIT(1);
        __syncthreads();
        if (t + 2 < T)
            gemm_load_tile_h(Ab, Bb, K, t + 2, sbase + ((t + 2) % GSTG) * STAGE_B, tid);
        uint32_t sa = sbase + (t % GSTG) * STAGE_B;
        uint32_t sb = sa + TB_A;

        #pragma unroll
        for (int ks = 0; ks < 4; ks++) {
            uint32_t afr[4][4];
            #pragma unroll
            for (int mt = 0; mt < 4; mt++) {
                uint32_t row = (uint32_t)(a_row + mt * 16);
                uint32_t c = (uint32_t)ks * 32 + a_kb;
                ldsm_x4(afr[mt], sa + row * 128 + (c ^ ((row & 7) << 4)));
            }
            uint32_t bfr[4][4];
            #pragma unroll
            for (int nh = 0; nh < 4; nh++) {
                uint32_t row = (uint32_t)(b_row + nh * 16);
                uint32_t c = (uint32_t)ks * 32 + b_kb;
                ldsm_x4(bfr[nh], sb + row * 128 + (c ^ ((row & 7) << 4)));
            }
            #pragma unroll
            for (int mt = 0; mt < 4; mt++)
                #pragma unroll
                for (int nt = 0; nt < 8; nt++)
                    mma_fp16(acc[mt][nt], afr[mt], &bfr[nt >> 1][(nt & 1) * 2]);
        }
    }

    int g = lane >> 2, tg = lane & 3;
    #pragma unroll
    for (int mt = 0; mt < 4; mt++) {
        int rowa = m0 + wm + mt * 16 + g;
        #pragma unroll
        for (int nt = 0; nt < 8; nt++) {
            int col = n0 + wn + nt * 8 + tg * 2;
            *(float2*)(C + (size_t)rowa * ldc + col) =
                make_float2(acc[mt][nt][0], acc[mt][nt][1]);
            *(float2*)(C + (size_t)(rowa + 8) * ldc + col) =
                make_float2(acc[mt][nt][2], acc[mt][nt][3]);
        }
    }
}

// ============ K6a (fp16 MMA): S tile = C @ B^T, K=64 (fp16 S out) ============
__global__ __launch_bounds__(256, 1) void k_scores_h() {
    __shared__ __align__(16) __half As[128 * 64];
    __shared__ __align__(16) __half Bs[128 * 64];
    int bc = blockIdx.x;
    int tile = blockIdx.y;              // 0:(0,0) 1:(1,0) 2:(1,1)
    int i0 = (tile != 0) ? 128 : 0;
    int j0 = (tile == 2) ? 128 : 0;
    int row0 = bc * CHUNK;
    int tid = threadIdx.x, lane = tid & 31, wid = tid >> 5;

    uint32_t as_base = smem_u32(As);
    uint32_t bs_base = smem_u32(Bs);
    const __half* Cb = g_xBCh + (size_t)(row0 + i0) * CONVDIM + D_INNER + D_STATE;
    const __half* Bb = g_xBCh + (size_t)(row0 + j0) * CONVDIM + D_INNER;
    #pragma unroll
    for (int j = 0; j < 4; j++) {
        int c = tid + 256 * j;
        int row = c >> 3;
        uint32_t cc = (uint32_t)(c & 7) * 16;
        uint32_t off = (uint32_t)row * 128 + (cc ^ (((uint32_t)row & 7) << 4));
        CP_ASYNC16(as_base + off, Cb + (size_t)row * CONVDIM + (cc >> 1));
        CP_ASYNC16(bs_base + off, Bb + (size_t)row * CONVDIM + (cc >> 1));
    }
    CP_COMMIT();
    CP_WAIT(0);
    __syncthreads();

    int wm = (wid & 3) * 32;
    int wn = (wid >> 2) * 64;
    int a_row = wm + (lane & 15);
    uint32_t a_kb = (uint32_t)(lane >> 4) * 16;
    int b_row = wn + (lane & 7) + ((lane & 16) ? 8 : 0);
    uint32_t b_kb = (lane & 8) ? 16u : 0u;

    float acc[2][8][4];
    #pragma unroll
    for (int mt = 0; mt < 2; mt++)
        #pragma unroll
        for (int nt = 0; nt < 8; nt++)
            #pragma unroll
            for (int q = 0; q < 4; q++) acc[mt][nt][q] = 0.f;

    #pragma unroll
    for (int ks = 0; ks < 4; ks++) {
        uint32_t afr[2][4];
        #pragma unroll
        for (int mt = 0; mt < 2; mt++) {
            uint32_t row = (uint32_t)(a_row + mt * 16);
            uint32_t c = (uint32_t)ks * 32 + a_kb;
            ldsm_x4(afr[mt], as_base + row * 128 + (c ^ ((row & 7) << 4)));
        }
        uint32_t bfr[4][4];
        #pragma unroll
        for (int nh = 0; nh < 4; nh++) {
            uint32_t row = (uint32_t)(b_row + nh * 16);
            uint32_t c = (uint32_t)ks * 32 + b_kb;
            ldsm_x4(bfr[nh], bs_base + row * 128 + (c ^ ((row & 7) << 4)));
        }
        #pragma unroll
        for (int mt = 0; mt < 2; mt++)
            #pragma unroll
            for (int nt = 0; nt < 8; nt++)
                mma_fp16(acc[mt][nt], afr[mt], &bfr[nt >> 1][(nt & 1) * 2]);
    }

    int g = lane >> 2, tg = lane & 3;
    #pragma unroll
    for (int mt = 0; mt < 2; mt++) {
        int irow = i0 + wm + mt * 16 + g;
        #pragma unroll
        for (int nt = 0; nt < 8; nt++) {
            int col = j0 + wn + nt * 8 + tg * 2;
            *(uint32_t*)(g_Sh + ((size_t)bc * CHUNK + irow) * CHUNK + col) =
                pack2(acc[mt][nt][0], acc[mt][nt][1]);
            *(uint32_t*)(g_Sh + ((size_t)bc * CHUNK + irow + 8) * CHUNK + col) =
                pack2(acc[mt][nt][2], acc[mt][nt][3]);
        }
    }
}

// ============ K7 (fp16 MMA): states[p][n] = sum_t (x[t][p]*w_t) * B[t][n] ============
__global__ __launch_bounds__(256, 1) void k_states_h() {
    __shared__ __align__(16) __half As[128 * 64];
    __shared__ __align__(16) __half Bs[64 * 64];
    __shared__ float wsh[256];
    int bc = blockIdx.x, h = blockIdx.y;
    int row0 = bc * CHUNK;
    int cb = (bc * NHEADS + h) * CHUNK;
    int tid = threadIdx.x, lane = tid & 31, wid = tid >> 5;

    float cum_last = g_cum[cb + 255];
    wsh[tid] = g_dt[(size_t)(row0 + tid) * NHEADS + h] *
               __expf(cum_last - g_cum[cb + tid]);

    uint32_t as_base = smem_u32(As);
    uint32_t bs_base = smem_u32(Bs);

    int wm = (wid & 3) * 32;
    int wn = (wid >> 2) * 32;
    int a_row = wm + (lane & 15);
    uint32_t a_kb = (uint32_t)(lane >> 4) * 16;
    int b_row = wn + (lane & 7) + ((lane & 16) ? 8 : 0);
    uint32_t b_kb = (lane & 8) ? 16u : 0u;

    float acc[2][4][4];
    #pragma unroll
    for (int mt = 0; mt < 2; mt++)
        #pragma unroll
        for (int nt = 0; nt < 4; nt++)
            #pragma unroll
            for (int q = 0; q < 4; q++) acc[mt][nt][q] = 0.f;

    for (int kt = 0; kt < 4; kt++) {
        int t0 = kt * 64;
        __syncthreads();
        #pragma unroll
        for (int jp = 0; jp < 4; jp++) {
            int pair = wid + 8 * jp;
            int t = t0 + 2 * pair;
            const __half* x0 = g_xBCh + (size_t)(row0 + t) * CONVDIM + h * HEADDIM;
            const __half* x1 = x0 + CONVDIM;
            float w0 = wsh[t], w1 = wsh[t + 1];
            #pragma unroll
            for (int r = 0; r < 4; r++) {
                int p = lane + 32 * r;
                uint32_t cbyte = (uint32_t)pair * 4;
                uint32_t off = (uint32_t)p * 128 + (cbyte ^ (((uint32_t)p & 7) << 4));
                *(uint32_t*)((char*)As + off) =
                    pack2(__half2float(x0[p]) * w0, __half2float(x1[p]) * w1);
            }
        }
        #pragma unroll
        for (int q = 0; q < 8; q++) {
            int idx = tid + 256 * q;
            int n = idx >> 5, pair = idx & 31;
            int t = t0 + 2 * pair;
            const __half* b0 = g_xBCh + (size_t)(row0 + t) * CONVDIM + D_INNER;
            uint32_t cbyte = (uint32_t)pair * 4;
            uint32_t off = (uint32_t)n * 128 + (cbyte ^ (((uint32_t)n & 7) << 4));
            *(uint32_t*)((char*)Bs + off) = pack2h(b0[n], b0[CONVDIM + n]);
        }
        __syncthreads();
        #pragma unroll
        for (int ks = 0; ks < 4; ks++) {
            uint32_t afr[2][4];
            #pragma unroll
            for (int mt = 0; mt < 2; mt++) {
                uint32_t row = (uint32_t)(a_row + mt * 16);
                uint32_t c = (uint32_t)ks * 32 + a_kb;
                ldsm_x4(afr[mt], as_base + row * 128 + (c ^ ((row & 7) << 4)));
            }
            uint32_t bfr[2][4];
            #pragma unroll
            for (int nh = 0; nh < 2; nh++) {
                uint32_t row = (uint32_t)(b_row + nh * 16);
                uint32_t c = (uint32_t)ks * 32 + b_kb;
                ldsm_x4(bfr[nh], bs_base + row * 128 + (c ^ ((row & 7) << 4)));
            }
            #pragma unroll
            for (int mt = 0; mt < 2; mt++)
                #pragma unroll
                for (int nt = 0; nt < 4; nt++)
                    mma_fp16(acc[mt][nt], afr[mt], &bfr[nt >> 1][(nt & 1) * 2]);
        }
    }

    size_t base = (size_t)(bc * NHEADS + h) * HEADDIM * D_STATE;
    int g = lane >> 2, tg = lane & 3;
    #pragma unroll
    for (int mt = 0; mt < 2; mt++) {
        int prow = wm + mt * 16 + g;
        #pragma unroll
        for (int nt = 0; nt < 4; nt++) {
            int col = wn + nt * 8 + tg * 2;
            *(float2*)(g_st + base + (size_t)prow * D_STATE + col) =
                make_float2(acc[mt][nt][0], acc[mt][nt][1]);
            *(float2*)(g_st + base + (size_t)(prow + 8) * D_STATE + col) =
                make_float2(acc[mt][nt][2], acc[mt][nt][3]);
        }
    }
}

// ============ fused SSD y-kernel (fp16 fragments, fp32 accumulate, fp16 y out) ============
__global__ __launch_bounds__(256, 1) void k_yfused() {
    __shared__ __align__(16) __half As[128 * 64];
    __shared__ __align__(16) __half Bs[128 * 64];
    __shared__ float gj_all[256];
    __shared__ float cas[8];
    int bc = blockIdx.x, h = blockIdx.y, ih = blockIdx.z;
    int i_base = ih * 128;
    int row0 = bc * CHUNK;
    int cb = (bc * NHEADS + h) * CHUNK;
    size_t psb = (size_t)(bc * NHEADS + h) * HEADDIM * D_STATE;

    int tid = threadIdx.x, lane = tid & 31, wid = tid >> 5;
    int wm = (wid & 3) * 32;
    int wn = (wid >> 2) * 64;

    int si = tid >> 1;
    int sj = (tid & 1) * 32;
    int gi = i_base + si;
    float ci = g_cum[cb + gi];
    float ei = __expf(ci);

    uint32_t as_base = smem_u32(As);
    uint32_t bs_base = smem_u32(Bs);

    int a_row = wm + (lane & 15);
    uint32_t a_kb = (uint32_t)(lane >> 4) * 16;
    int b_row = wn + (lane & 7) + ((lane & 16) ? 8 : 0);
    uint32_t b_kb = (lane & 8) ? 16u : 0u;

    int natt64 = (ih + 1) * 2;
    int nattj = natt64 * 64;

    if (tid < nattj) {
        int j = tid;
        float ca = g_cum[cb + (j & ~31) + 31];
        gj_all[j] = __expf(ca - g_cum[cb + j]) *
                    g_dt[(size_t)(row0 + j) * NHEADS + h];
    }
    if (tid < natt64 * 2) cas[tid] = g_cum[cb + tid * 32 + 31];

    float acc[2][8][4];
    #pragma unroll
    for (int mt = 0; mt < 2; mt++)
        #pragma unroll
        for (int nt = 0; nt < 8; nt++)
            #pragma unroll
            for (int q = 0; q < 4; q++) acc[mt][nt][q] = 0.f;

    int ntiles = natt64 + 1;
    for (int kt = 0; kt < ntiles; kt++) {
        __syncthreads();
        if (kt < natt64) {
            int j0 = kt * 64;
            int jb = j0 + sj;
            if (gi >= jb + 31) {
                float fi = __expf(ci - cas[jb >> 5]);
                const __half* Srow = g_Sh + ((size_t)bc * CHUNK + gi) * CHUNK + jb;
                const float* gjp = gj_all + jb;
                #pragma unroll
                for (int q = 0; q < 4; q++) {
                    uint4 sv = *(const uint4*)(Srow + q * 8);   // 8 halves
                    float2 f0 = __half22float2(*(__half2*)&sv.x);
                    float2 f1 = __half22float2(*(__half2*)&sv.y);
                    float2 f2 = __half22float2(*(__half2*)&sv.z);
                    float2 f3 = __half22float2(*(__half2*)&sv.w);
                    uint4 u;
                    u.x = pack2(f0.x * fi * gjp[q*8+0], f0.y * fi * gjp[q*8+1]);
                    u.y = pack2(f1.x * fi * gjp[q*8+2], f1.y * fi * gjp[q*8+3]);
                    u.z = pack2(f2.x * fi * gjp[q*8+4], f2.y * fi * gjp[q*8+5]);
                    u.w = pack2(f3.x * fi * gjp[q*8+6], f3.y * fi * gjp[q*8+7]);
                    uint32_t cbyte = (uint32_t)(sj * 2 + q * 16);
                    uint32_t off = (uint32_t)si * 128 + (cbyte ^ (((uint32_t)si & 7) << 4));
                    *(uint4*)((char*)As + off) = u;
                }
            } else if (gi >= jb) {
                #pragma unroll
                for (int q = 0; q < 4; q++) {
                    float v[8];
                    #pragma unroll
                    for (int r = 0; r < 8; r++) {
                        int j = jb + q * 8 + r;
                        float a = 0.f;
                        if (j <= gi)
                            a = __half2float(g_Sh[((size_t)bc * CHUNK + gi) * CHUNK + j]) *
                                __expf(ci - g_cum[cb + j]) *
                                g_dt[(size_t)(row0 + j) * NHEADS + h];
                        v[r] = a;
                    }
                    uint4 u;
                    u.x = pack2(v[0], v[1]); u.y = pack2(v[2], v[3]);
                    u.z = pack2(v[4], v[5]); u.w = pack2(v[6], v[7]);
                    uint32_t cbyte = (uint32_t)(sj * 2 + q * 16);
                    uint32_t off = (uint32_t)si * 128 + (cbyte ^ (((uint32_t)si & 7) << 4));
                    *(uint4*)((char*)As + off) = u;
                }
            } else {
                #pragma unroll
                for (int q = 0; q < 4; q++) {
                    uint32_t cbyte = (uint32_t)(sj * 2 + q * 16);
                    uint32_t off = (uint32_t)si * 128 + (cbyte ^ (((uint32_t)si & 7) << 4));
                    *(uint4*)((char*)As + off) = make_uint4(0, 0, 0, 0);
                }
            }
            #pragma unroll
            for (int jp = 0; jp < 4; jp++) {
                int pair = wid + 8 * jp;
                int j = j0 + 2 * pair;
                const __half* x0 = g_xBCh + (size_t)(row0 + j) * CONVDIM + h * HEADDIM;
                const __half* x1 = x0 + CONVDIM;
                #pragma unroll
                for (int r = 0; r < 4; r++) {
                    int p = lane + 32 * r;
                    uint32_t cbyte = (uint32_t)pair * 4;
                    uint32_t off = (uint32_t)p * 128 + (cbyte ^ (((uint32_t)p & 7) << 4));
                    *(uint32_t*)((char*)Bs + off) = pack2h(x0[p], x1[p]);
                }
            }
        } else {
            // state tile: A = Ce[i][n] from fp16 C, B = P[p][n]
            const __half2* crow = (const __half2*)(g_xBCh + (size_t)(row0 + gi) * CONVDIM
                                                   + D_INNER + D_STATE + sj);
            #pragma unroll
            for (int q = 0; q < 4; q++) {
                uint4 hv = *(const uint4*)(crow + q * 4);
                float2 f0 = __half22float2(*(__half2*)&hv.x);
                float2 f1 = __half22float2(*(__half2*)&hv.y);
                float2 f2 = __half22float2(*(__half2*)&hv.z);
                float2 f3 = __half22float2(*(__half2*)&hv.w);
                uint4 u;
                u.x = pack2(f0.x * ei, f0.y * ei);
                u.y = pack2(f1.x * ei, f1.y * ei);
                u.z = pack2(f2.x * ei, f2.y * ei);
                u.w = pack2(f3.x * ei, f3.y * ei);
                uint32_t cbyte = (uint32_t)(sj * 2 + q * 16);
                uint32_t off = (uint32_t)si * 128 + (cbyte ^ (((uint32_t)si & 7) << 4));
                *(uint4*)((char*)As + off) = u;
            }
            int pr = tid >> 1;
            int nc = (tid & 1) * 32;
            const float* prow = g_ps + psb + (size_t)pr * D_STATE + nc;
            #pragma unroll
            for (int q = 0; q < 4; q++) {
                float4 p0 = *(const float4*)(prow + q * 8);
                float4 p1 = *(const float4*)(prow + q * 8 + 4);
                uint4 u;
                u.x = pack2(p0.x, p0.y); u.y = pack2(p0.z, p0.w);
                u.z = pack2(p1.x, p1.y); u.w = pack2(p1.z, p1.w);
                uint32_t cbyte = (uint32_t)(nc * 2 + q * 16);
                uint32_t off = (uint32_t)pr * 128 + (cbyte ^ (((uint32_t)pr & 7) << 4));
                *(uint4*)((char*)Bs + off) = u;
            }
        }
        __syncthreads();
        #pragma unroll
        for (int ks = 0; ks < 4; ks++) {
            uint32_t afr[2][4];
            #pragma unroll
            for (int mt = 0; mt < 2; mt++) {
                uint32_t row = (uint32_t)(a_row + mt * 16);
                uint32_t c = (uint32_t)ks * 32 + a_kb;
                ldsm_x4(afr[mt], as_base + row * 128 + (c ^ ((row & 7) << 4)));
            }
            uint32_t bfr[4][4];
            #pragma unroll
            for (int nh = 0; nh < 4; nh++) {
                uint32_t row = (uint32_t)(b_row + nh * 16);
                uint32_t c = (uint32_t)ks * 32 + b_kb;
                ldsm_x4(bfr[nh], bs_base + row * 128 + (c ^ ((row & 7) << 4)));
            }
            #pragma unroll
            for (int mt = 0; mt < 2; mt++)
                #pragma unroll
                for (int nt = 0; nt < 8; nt++)
                    mma_fp16(acc[mt][nt], afr[mt], &bfr[nt >> 1][(nt & 1) * 2]);
        }
    }

    int g = lane >> 2, tg = lane & 3;
    #pragma unroll
    for (int mt = 0; mt < 2; mt++) {
        int orow = row0 + i_base + wm + mt * 16 + g;
        #pragma unroll
        for (int nt = 0; nt < 8; nt++) {
            int col = h * HEADDIM + wn + nt * 8 + tg * 2;
            *(uint32_t*)(g_yh + (size_t)orow * D_INNER + col) =
                pack2(acc[mt][nt][0], acc[mt][nt][1]);
            *(uint32_t*)(g_yh + (size_t)(orow + 8) * D_INNER + col) =
                pack2(acc[mt][nt][2], acc[mt][nt][3]);
        }
    }
}

// ---------------- reductions ----------------
__device__ __forceinline__ float blockReduceSum256(float v) {
    __shared__ float red[8];
    __shared__ float tot;
    int lane = threadIdx.x & 31, wid = threadIdx.x >> 5;
    #pragma unroll
    for (int o = 16; o; o >>= 1) v += __shfl_down_sync(0xffffffffu, v, o);
    if (lane == 0) red[wid] = v;
    __syncthreads();
    if (wid == 0) {
        float w = (lane < 8) ? red[lane] : 0.f;
        #pragma unroll
        for (int o = 4; o; o >>= 1) w += __shfl_down_sync(0xffffffffu, w, o);
        if (lane == 0) tot = w;
    }
    __syncthreads();
    return tot;
}

// ---------------- K1: l2-normalize weight rows (fp16 output) ----------------
__global__ __launch_bounds__(256) void k_normw(const float* __restrict__ W,
                                               __half* __restrict__ Wo, int K, float extra) {
    int r = blockIdx.x;
    const float* wr = W + (size_t)r * K;
    float s2 = 0.f;
    for (int i = threadIdx.x; i < K; i += 256) { float v = wr[i]; s2 += v * v; }
    float totv = blockReduceSum256(s2);
    float sc = extra / fmaxf(sqrtf(totv), 1e-6f);
    for (int i = threadIdx.x; i < K; i += 256)
        Wo[(size_t)r * K + i] = __float2half_rn(wr[i] * sc);
}

// ---------------- K2: layernorm (fp16 output) ----------------
__global__ __launch_bounds__(256) void k_layernorm(const float* __restrict__ u,
                                                   const float* __restrict__ w,
                                                   const float* __restrict__ b) {
    int row = blockIdx.x;
    const float* ur = u + (size_t)row * XDIM;
    float v[4]; float s = 0.f, s2 = 0.f;
    #pragma unroll
    for (int k = 0; k < 4; k++) {
        v[k] = ur[threadIdx.x + 256 * k];
        s += v[k]; s2 += v[k] * v[k];
    }
    float sum = blockReduceSum256(s);
    float sumsq = blockReduceSum256(s2);
    float mu = sum * (1.f / XDIM);
    float var = sumsq * (1.f / XDIM) - mu * mu;
    float inv = rsqrtf(var + 1e-5f);
    #pragma unroll
    for (int k = 0; k < 4; k++) {
        int d = threadIdx.x + 256 * k;
        g_lnh[(size_t)row * XDIM + d] = __float2half_rn((v[k] - mu) * inv * w[d] + b[d]);
    }
}

// ---------------- K4: depthwise causal conv + bias + silu (register-reuse, 8 rows/thread) ----------------
__global__ __launch_bounds__(128) void k_conv(const float* __restrict__ cw,
                                              const float* __restrict__ cb) {
    int ch = blockIdx.x * 128 + threadIdx.x;
    if (ch >= CONVDIM) return;
    int row0 = blockIdx.y * 8;
    int l0 = row0 & (SEQLEN - 1);
    float w0 = cw[ch * 4 + 0], w1 = cw[ch * 4 + 1];
    float w2 = cw[ch * 4 + 2], w3 = cw[ch * 4 + 3];
    float bias = cb[ch];
    float v[11];
    #pragma unroll
    for (int k = 0; k < 11; k++) {
        int l = l0 - 3 + k;
        v[k] = (l >= 0) ? g_zx[(size_t)(row0 - 3 + k) * DPROJP + D_INNER + ch] : 0.f;
    }
    #pragma unroll
    for (int r = 0; r < 8; r++) {
        float acc = bias + w0 * v[r] + w1 * v[r + 1] + w2 * v[r + 2] + w3 * v[r + 3];
        float s = acc / (1.f + __expf(-acc));
        g_xBCh[(size_t)(row0 + r) * CONVDIM + ch] = __float2half_rn(s);
    }
}

// ---------------- K5: dt softplus + per-chunk cumulative dA ----------------
__global__ __launch_bounds__(256) void k_dtcum(const float* __restrict__ dt_bias,
                                               const float* __restrict__ A_log) {
    int bch = blockIdx.x;
    int h = bch & 15, bc = bch >> 4;
    int t = threadIdx.x;
    int row = bc * CHUNK + t;
    float x = g_zx[(size_t)row * DPROJP + (D_INNER + CONVDIM) + h] + dt_bias[h];
    float dtv = (x > 20.f) ? x : log1pf(expf(x));
    g_dt[(size_t)row * NHEADS + h] = dtv;
    float dA = dtv * (-expf(A_log[h]));
    __shared__ float s[256];
    s[t] = dA;
    __syncthreads();
    #pragma unroll
    for (int off = 1; off < 256; off <<= 1) {
        float pv = (t >= off) ? s[t - off] : 0.f;
        __syncthreads();
        s[t] += pv;
        __syncthreads();
    }
    g_cum[(size_t)bch * CHUNK + t] = s[t];
    if (t == 255) g_cdec[bch] = __expf(s[255]);
}

// ---------------- K8: inter-chunk scan (parallel over elements, serial over chunks) ----------------
__global__ __launch_bounds__(256) void k_scan() {
    int b = blockIdx.x, h = blockIdx.y, z = blockIdx.z;
    int tid = threadIdx.x;
    int e0 = z * 1024 + tid * 4;
    float4 carry = make_float4(0.f, 0.f, 0.f, 0.f);
    for (int c = 0; c < NCPB; c++) {
        int bch = (b * NCPB + c) * NHEADS + h;
        float dec = g_cdec[bch];
        size_t base = (size_t)bch * HEADDIM * D_STATE + e0;
        *(float4*)(g_ps + base) = carry;
        float4 st = *(const float4*)(g_st + base);
        carry.x = carry.x * dec + st.x;
        carry.y = carry.y * dec + st.y;
        carry.z = carry.z * dec + st.z;
        carry.w = carry.w * dec + st.w;
    }
}

// ---------------- K10: y += D*x, gate, RMS norm (fp16 in/out) ----------------
__global__ __launch_bounds__(256) void k_gate(const float* __restrict__ Dp,
                                              const float* __restrict__ rms_w) {
    int row = blockIdx.x;
    int tid = threadIdx.x;
    float gg[8];
    float s2 = 0.f;
    #pragma unroll
    for (int k = 0; k < 8; k++) {
        int d = tid + 256 * k;
        float xv = __half2float(g_xBCh[(size_t)row * CONVDIM + d]);
        float yv = __half2float(g_yh[(size_t)row * D_INNER + d]);
        float v = yv + Dp[d >> 7] * xv;
        float z = g_zx[(size_t)row * DPROJP + d];
        float sil = z / (1.f + __expf(-z));
        float g = v * sil;
        gg[k] = g;
        s2 += g * g;
    }
    float tot = blockReduceSum256(s2);
    float sc = rsqrtf(tot * (1.f / D_INNER) + 1e-5f);
    #pragma unroll
    for (int k = 0; k < 8; k++) {
        int d = tid + 256 * k;
        g_gh[(size_t)row * D_INNER + d] = __float2half_rn(gg[k] * sc * rms_w[d]);
    }
}

// ---------------- host launcher ----------------
extern "C" void kernel_launch(void* const* d_in, const int* in_sizes, int n_in,
                              void* d_out, int out_size) {
    const float* u          = (const float*)d_in[0];
    const float* in_proj_w  = (const float*)d_in[1];
    const float* conv_w     = (const float*)d_in[2];
    const float* conv_b     = (const float*)d_in[3];
    const float* dt_bias    = (const float*)d_in[4];
    const float* A_log      = (const float*)d_in[5];
    const float* Dp         = (const float*)d_in[6];
    const float* xnw        = (const float*)d_in[7];
    const float* xnb        = (const float*)d_in[8];
    const float* rms_w      = (const float*)d_in[9];
    const float* out_proj_w = (const float*)d_in[10];
    float* out = (float*)d_out;

    __half *pWinH, *pWoutH, *pLnH, *pGH;
    float *pZx;
    cudaGetSymbolAddress((void**)&pWinH,  g_Winh);
    cudaGetSymbolAddress((void**)&pWoutH, g_Wouth);
    cudaGetSymbolAddress((void**)&pLnH,   g_lnh);
    cudaGetSymbolAddress((void**)&pGH,    g_gh);
    cudaGetSymbolAddress((void**)&pZx,    g_zx);

    static int smem_set = 0;
    if (!smem_set) {
        cudaFuncSetAttribute(gemm_hc, cudaFuncAttributeMaxDynamicSharedMemorySize, GEMM_SMEM);
        smem_set = 1;
    }

    k_normw<<<DPROJ, 256>>>(in_proj_w, pWinH, XDIM, 0.03125f);
    k_normw<<<XDIM, 256>>>(out_proj_w, pWoutH, D_INNER, 1.0f);

    k_layernorm<<<R_TOT, 256>>>(u, xnw, xnb);

    gemm_hc<<<dim3(DPROJP / GBN, R_TOT / GBM), 128, GEMM_SMEM>>>(pLnH, pWinH, pZx, XDIM, DPROJP);

    k_conv<<<dim3((CONVDIM + 127) / 128, R_TOT / 8), 128>>>(conv_w, conv_b);
    k_dtcum<<<NBC * NHEADS, 256>>>(dt_bias, A_log);

    k_scores_h<<<dim3(NBC, 3), 256>>>();
    k_states_h<<<dim3(NBC, NHEADS), 256>>>();
    k_scan<<<dim3(NBATCH, NHEADS, 8), 256>>>();
    k_yfused<<<dim3(NBC, NHEADS, 2), 256>>>();

    k_gate<<<R_TOT, 256>>>(Dp, rms_w);

    gemm_hc<<<dim3(XDIM / GBN, R_TOT / GBM), 128, GEMM_SMEM>>>(pGH, pWoutH, out, D_INNER, XDIM);
}

// round 12
// speedup vs baseline: 6.5476x; 1.0326x over previous
#include <cuda_runtime.h>
#include <cuda_fp16.h>
#include <math.h>
#include <stdint.h>

// ---------------- problem constants ----------------
#define XDIM    1024
#define D_STATE 64
#define HEADDIM 128
#define D_INNER 2048
#define NHEADS  16
#define CONVDIM 2176              // D_INNER + 2*64
#define DPROJ   4240              // 2*2048 + 2*64 + 16
#define DPROJP  4352              // padded to 128-multiple for GEMM tiles
#define DT_BASE 4224              // D_INNER + CONVDIM
#define CHUNK   256
#define NBATCH  2
#define SEQLEN  4096
#define NCPB    16
#define NBC     32
#define R_TOT   8192

// ---------------- device scratch ----------------
__device__ __half g_lnh [(size_t)R_TOT * XDIM];
__device__ __half g_Winh[(size_t)DPROJP * XDIM];     // rows >= DPROJ stay zero (.bss)
__device__ __half g_Wouth[(size_t)XDIM * D_INNER];
__device__ __half g_gh  [(size_t)R_TOT * D_INNER];
__device__ __half g_zxh [(size_t)R_TOT * DPROJP];    // fp16 in_proj output
__device__ __half g_xBCh[(size_t)R_TOT * CONVDIM];   // fp16 conv output
__device__ __half g_yh  [(size_t)R_TOT * D_INNER];   // fp16 y
__device__ __half g_Sh  [(size_t)NBC * CHUNK * CHUNK];  // fp16 scores
__device__ __half g_psh [(size_t)NBC * NHEADS * HEADDIM * D_STATE];  // fp16 prev states
__device__ float g_dtraw[(size_t)R_TOT * NHEADS];    // fp32 dt_raw side-channel
__device__ float g_dt  [(size_t)R_TOT * NHEADS];
__device__ float g_cum [(size_t)NBC * NHEADS * CHUNK];
__device__ float g_cdec[(size_t)NBC * NHEADS];
__device__ float g_st  [(size_t)NBC * NHEADS * HEADDIM * D_STATE];

// ---------------- PTX helpers (baseline PTX only) ----------------
__device__ __forceinline__ uint32_t smem_u32(const void* p) {
    uint32_t a;
    asm("{ .reg .u64 t; cvta.to.shared.u64 t, %1; cvt.u32.u64 %0, t; }" : "=r"(a) : "l"(p));
    return a;
}
__device__ __forceinline__ uint32_t pack2(float a, float b) {
    __half2 h = __floats2half2_rn(a, b);
    return *(uint32_t*)&h;
}
__device__ __forceinline__ uint32_t pack2h(__half a, __half b) {
    __half2 h = __halves2half2(a, b);
    return *(uint32_t*)&h;
}
#define CP_ASYNC16(s, g) \
    asm volatile("cp.async.cg.shared.global [%0], [%1], 16;" :: "r"(s), "l"(g))
#define CP_COMMIT() asm volatile("cp.async.commit_group;" ::: "memory")
#define CP_WAIT(n)  asm volatile("cp.async.wait_group %0;" :: "n"(n) : "memory")

__device__ __forceinline__ void ldsm_x4(uint32_t* r, uint32_t addr) {
    asm volatile("ldmatrix.sync.aligned.m8n8.x4.shared.b16 {%0,%1,%2,%3}, [%4];"
        : "=r"(r[0]), "=r"(r[1]), "=r"(r[2]), "=r"(r[3]) : "r"(addr));
}
__device__ __forceinline__ void mma_fp16(float* d, const uint32_t* a, const uint32_t* b) {
    asm volatile("mma.sync.aligned.m16n8k16.row.col.f32.f16.f16.f32 "
        "{%0,%1,%2,%3},{%4,%5,%6,%7},{%8,%9},{%0,%1,%2,%3};"
        : "+f"(d[0]), "+f"(d[1]), "+f"(d[2]), "+f"(d[3])
        : "r"(a[0]), "r"(a[1]), "r"(a[2]), "r"(a[3]), "r"(b[0]), "r"(b[1]));
}

// ================= fp16 tensor-core GEMM =================
#define GBM 128
#define GBN 128
#define GBK 64
#define GSTG 3
#define TB_A (GBM * GBK * 2)
#define TB_B (GBN * GBK * 2)
#define STAGE_B (TB_A + TB_B)
#define GEMM_SMEM (GSTG * STAGE_B)

__device__ __forceinline__ void gemm_load_tile_h(const __half* Ab, const __half* Bb,
                                                 int K, int t, uint32_t sb, int tid) {
    const __half* Ap = Ab + (size_t)t * GBK;
    const __half* Bp = Bb + (size_t)t * GBK;
    #pragma unroll
    for (int j = 0; j < 8; j++) {
        int c = tid + 128 * j;
        int row = c >> 3;
        uint32_t cc = (uint32_t)(c & 7) * 16;
        uint32_t off = (uint32_t)row * 128 + (cc ^ (((uint32_t)row & 7) << 4));
        CP_ASYNC16(sb + off, Ap + (size_t)row * K + (cc >> 1));
    }
    uint32_t sb2 = sb + TB_A;
    #pragma unroll
    for (int j = 0; j < 8; j++) {
        int c = tid + 128 * j;
        int row = c >> 3;
        uint32_t cc = (uint32_t)(c & 7) * 16;
        uint32_t off = (uint32_t)row * 128 + (cc ^ (((uint32_t)row & 7) << 4));
        CP_ASYNC16(sb2 + off, Bp + (size_t)row * K + (cc >> 1));
    }
    CP_COMMIT();
}

// core mainloop shared by both epilogue variants
#define GEMM_MAIN(acc, A, B, K)                                                     \
    int T = (K) / GBK;                                                              \
    gemm_load_tile_h(A, B, K, 0, sbase, tid);                                       \
    gemm_load_tile_h(A, B, K, 1, sbase + STAGE_B, tid);                             \
    for (int t = 0; t < T; t++) {                                                   \
        CP_WAIT(1);                                                                 \
        __syncthreads();                                                            \
        if (t + 2 < T)                                                              \
            gemm_load_tile_h(A, B, K, t + 2, sbase + ((t + 2) % GSTG) * STAGE_B, tid); \
        uint32_t sa = sbase + (t % GSTG) * STAGE_B;                                 \
        uint32_t sb = sa + TB_A;                                                    \
        _Pragma("unroll")                                                           \
        for (int ks = 0; ks < 4; ks++) {                                            \
            uint32_t afr[4][4];                                                     \
            _Pragma("unroll")                                                       \
            for (int mt = 0; mt < 4; mt++) {                                        \
                uint32_t row = (uint32_t)(a_row + mt * 16);                         \
                uint32_t c = (uint32_t)ks * 32 + a_kb;                              \
                ldsm_x4(afr[mt], sa + row * 128 + (c ^ ((row & 7) << 4)));          \
            }                                                                       \
            uint32_t bfr[4][4];                                                     \
            _Pragma("unroll")                                                       \
            for (int nh = 0; nh < 4; nh++) {                                        \
                uint32_t row = (uint32_t)(b_row + nh * 16);                         \
                uint32_t c = (uint32_t)ks * 32 + b_kb;                              \
                ldsm_x4(bfr[nh], sb + row * 128 + (c ^ ((row & 7) << 4)));          \
            }                                                                       \
            _Pragma("unroll")                                                       \
            for (int mt = 0; mt < 4; mt++)                                          \
                _Pragma("unroll")                                                   \
                for (int nt = 0; nt < 8; nt++)                                      \
                    mma_fp16(acc[mt][nt], afr[mt], &bfr[nt >> 1][(nt & 1) * 2]);    \
        }                                                                           \
    }

// fp32-output GEMM (out_proj)
__global__ __launch_bounds__(128, 2) void gemm_hc(const __half* __restrict__ A,
                                                  const __half* __restrict__ B,
                                                  float* __restrict__ C,
                                                  int K, int ldc) {
    extern __shared__ char sm[];
    uint32_t sbase = smem_u32(sm);
    int tid = threadIdx.x, lane = tid & 31, wid = tid >> 5;
    int wm = (wid & 1) * 64, wn = (wid >> 1) * 64;
    int m0 = blockIdx.y * GBM, n0 = blockIdx.x * GBN;
    const __half* Ab = A + (size_t)m0 * K;
    const __half* Bb = B + (size_t)n0 * K;
    int a_row = wm + (lane & 15);
    uint32_t a_kb = (uint32_t)(lane >> 4) * 16;
    int b_row = wn + (lane & 7) + ((lane & 16) ? 8 : 0);
    uint32_t b_kb = (lane & 8) ? 16u : 0u;

    float acc[4][8][4];
    #pragma unroll
    for (int mt = 0; mt < 4; mt++)
        #pragma unroll
        for (int nt = 0; nt < 8; nt++)
            #pragma unroll
            for (int q = 0; q < 4; q++) acc[mt][nt][q] = 0.f;

    GEMM_MAIN(acc, Ab, Bb, K)

    int g = lane >> 2, tg = lane & 3;
    #pragma unroll
    for (int mt = 0; mt < 4; mt++) {
        int rowa = m0 + wm + mt * 16 + g;
        #pragma unroll
        for (int nt = 0; nt < 8; nt++) {
            int col = n0 + wn + nt * 8 + tg * 2;
            *(float2*)(C + (size_t)rowa * ldc + col) =
                make_float2(acc[mt][nt][0], acc[mt][nt][1]);
            *(float2*)(C + (size_t)(rowa + 8) * ldc + col) =
                make_float2(acc[mt][nt][2], acc[mt][nt][3]);
        }
    }
}

// fp16-output GEMM (in_proj) with fp32 dt side-channel
__global__ __launch_bounds__(128, 2) void gemm_hc_h(const __half* __restrict__ A,
                                                    const __half* __restrict__ B,
                                                    __half* __restrict__ C,
                                                    int K, int ldc) {
    extern __shared__ char sm[];
    uint32_t sbase = smem_u32(sm);
    int tid = threadIdx.x, lane = tid & 31, wid = tid >> 5;
    int wm = (wid & 1) * 64, wn = (wid >> 1) * 64;
    int m0 = blockIdx.y * GBM, n0 = blockIdx.x * GBN;
    const __half* Ab = A + (size_t)m0 * K;
    const __half* Bb = B + (size_t)n0 * K;
    int a_row = wm + (lane & 15);
    uint32_t a_kb = (uint32_t)(lane >> 4) * 16;
    int b_row = wn + (lane & 7) + ((lane & 16) ? 8 : 0);
    uint32_t b_kb = (lane & 8) ? 16u : 0u;

    float acc[4][8][4];
    #pragma unroll
    for (int mt = 0; mt < 4; mt++)
        #pragma unroll
        for (int nt = 0; nt < 8; nt++)
            #pragma unroll
            for (int q = 0; q < 4; q++) acc[mt][nt][q] = 0.f;

    GEMM_MAIN(acc, Ab, Bb, K)

    int g = lane >> 2, tg = lane & 3;
    #pragma unroll
    for (int mt = 0; mt < 4; mt++) {
        int rowa = m0 + wm + mt * 16 + g;
        #pragma unroll
        for (int nt = 0; nt < 8; nt++) {
            int col = n0 + wn + nt * 8 + tg * 2;
            *(uint32_t*)(C + (size_t)rowa * ldc + col) =
                pack2(acc[mt][nt][0], acc[mt][nt][1]);
            *(uint32_t*)(C + (size_t)(rowa + 8) * ldc + col) =
                pack2(acc[mt][nt][2], acc[mt][nt][3]);
            if (col >= DT_BASE && col < DPROJ) {
                int d = col - DT_BASE;
                g_dtraw[(size_t)rowa * NHEADS + d]     = acc[mt][nt][0];
                g_dtraw[(size_t)rowa * NHEADS + d + 1] = acc[mt][nt][1];
                g_dtraw[(size_t)(rowa + 8) * NHEADS + d]     = acc[mt][nt][2];
                g_dtraw[(size_t)(rowa + 8) * NHEADS + d + 1] = acc[mt][nt][3];
            }
        }
    }
}

// ============ K6a (fp16 MMA): S tile = C @ B^T, K=64 (fp16 S out) ============
__global__ __launch_bounds__(256, 1) void k_scores_h() {
    __shared__ __align__(16) __half As[128 * 64];
    __shared__ __align__(16) __half Bs[128 * 64];
    int bc = blockIdx.x;
    int tile = blockIdx.y;
    int i0 = (tile != 0) ? 128 : 0;
    int j0 = (tile == 2) ? 128 : 0;
    int row0 = bc * CHUNK;
    int tid = threadIdx.x, lane = tid & 31, wid = tid >> 5;

    uint32_t as_base = smem_u32(As);
    uint32_t bs_base = smem_u32(Bs);
    const __half* Cb = g_xBCh + (size_t)(row0 + i0) * CONVDIM + D_INNER + D_STATE;
    const __half* Bb = g_xBCh + (size_t)(row0 + j0) * CONVDIM + D_INNER;
    #pragma unroll
    for (int j = 0; j < 4; j++) {
        int c = tid + 256 * j;
        int row = c >> 3;
        uint32_t cc = (uint32_t)(c & 7) * 16;
        uint32_t off = (uint32_t)row * 128 + (cc ^ (((uint32_t)row & 7) << 4));
        CP_ASYNC16(as_base + off, Cb + (size_t)row * CONVDIM + (cc >> 1));
        CP_ASYNC16(bs_base + off, Bb + (size_t)row * CONVDIM + (cc >> 1));
    }
    CP_COMMIT();
    CP_WAIT(0);
    __syncthreads();

    int wm = (wid & 3) * 32;
    int wn = (wid >> 2) * 64;
    int a_row = wm + (lane & 15);
    uint32_t a_kb = (uint32_t)(lane >> 4) * 16;
    int b_row = wn + (lane & 7) + ((lane & 16) ? 8 : 0);
    uint32_t b_kb = (lane & 8) ? 16u : 0u;

    float acc[2][8][4];
    #pragma unroll
    for (int mt = 0; mt < 2; mt++)
        #pragma unroll
        for (int nt = 0; nt < 8; nt++)
            #pragma unroll
            for (int q = 0; q < 4; q++) acc[mt][nt][q] = 0.f;

    #pragma unroll
    for (int ks = 0; ks < 4; ks++) {
        uint32_t afr[2][4];
        #pragma unroll
        for (int mt = 0; mt < 2; mt++) {
            uint32_t row = (uint32_t)(a_row + mt * 16);
            uint32_t c = (uint32_t)ks * 32 + a_kb;
            ldsm_x4(afr[mt], as_base + row * 128 + (c ^ ((row & 7) << 4)));
        }
        uint32_t bfr[4][4];
        #pragma unroll
        for (int nh = 0; nh < 4; nh++) {
            uint32_t row = (uint32_t)(b_row + nh * 16);
            uint32_t c = (uint32_t)ks * 32 + b_kb;
            ldsm_x4(bfr[nh], bs_base + row * 128 + (c ^ ((row & 7) << 4)));
        }
        #pragma unroll
        for (int mt = 0; mt < 2; mt++)
            #pragma unroll
            for (int nt = 0; nt < 8; nt++)
                mma_fp16(acc[mt][nt], afr[mt], &bfr[nt >> 1][(nt & 1) * 2]);
    }

    int g = lane >> 2, tg = lane & 3;
    #pragma unroll
    for (int mt = 0; mt < 2; mt++) {
        int irow = i0 + wm + mt * 16 + g;
        #pragma unroll
        for (int nt = 0; nt < 8; nt++) {
            int col = j0 + wn + nt * 8 + tg * 2;
            *(uint32_t*)(g_Sh + ((size_t)bc * CHUNK + irow) * CHUNK + col) =
                pack2(acc[mt][nt][0], acc[mt][nt][1]);
            *(uint32_t*)(g_Sh + ((size_t)bc * CHUNK + irow + 8) * CHUNK + col) =
                pack2(acc[mt][nt][2], acc[mt][nt][3]);
        }
    }
}

// ============ K7 (fp16 MMA): states[p][n] = sum_t (x[t][p]*w_t) * B[t][n] ============
__global__ __launch_bounds__(256, 1) void k_states_h() {
    __shared__ __align__(16) __half As[128 * 64];
    __shared__ __align__(16) __half Bs[64 * 64];
    __shared__ float wsh[256];
    int bc = blockIdx.x, h = blockIdx.y;
    int row0 = bc * CHUNK;
    int cb = (bc * NHEADS + h) * CHUNK;
    int tid = threadIdx.x, lane = tid & 31, wid = tid >> 5;

    float cum_last = g_cum[cb + 255];
    wsh[tid] = g_dt[(size_t)(row0 + tid) * NHEADS + h] *
               __expf(cum_last - g_cum[cb + tid]);

    uint32_t as_base = smem_u32(As);
    uint32_t bs_base = smem_u32(Bs);

    int wm = (wid & 3) * 32;
    int wn = (wid >> 2) * 32;
    int a_row = wm + (lane & 15);
    uint32_t a_kb = (uint32_t)(lane >> 4) * 16;
    int b_row = wn + (lane & 7) + ((lane & 16) ? 8 : 0);
    uint32_t b_kb = (lane & 8) ? 16u : 0u;

    float acc[2][4][4];
    #pragma unroll
    for (int mt = 0; mt < 2; mt++)
        #pragma unroll
        for (int nt = 0; nt < 4; nt++)
            #pragma unroll
            for (int q = 0; q < 4; q++) acc[mt][nt][q] = 0.f;

    for (int kt = 0; kt < 4; kt++) {
        int t0 = kt * 64;
        __syncthreads();
        #pragma unroll
        for (int jp = 0; jp < 4; jp++) {
            int pair = wid + 8 * jp;
            int t = t0 + 2 * pair;
            const __half* x0 = g_xBCh + (size_t)(row0 + t) * CONVDIM + h * HEADDIM;
            const __half* x1 = x0 + CONVDIM;
            float w0 = wsh[t], w1 = wsh[t + 1];
            #pragma unroll
            for (int r = 0; r < 4; r++) {
                int p = lane + 32 * r;
                uint32_t cbyte = (uint32_t)pair * 4;
                uint32_t off = (uint32_t)p * 128 + (cbyte ^ (((uint32_t)p & 7) << 4));
                *(uint32_t*)((char*)As + off) =
                    pack2(__half2float(x0[p]) * w0, __half2float(x1[p]) * w1);
            }
        }
        #pragma unroll
        for (int q = 0; q < 8; q++) {
            int idx = tid + 256 * q;
            int n = idx >> 5, pair = idx & 31;
            int t = t0 + 2 * pair;
            const __half* b0 = g_xBCh + (size_t)(row0 + t) * CONVDIM + D_INNER;
            uint32_t cbyte = (uint32_t)pair * 4;
            uint32_t off = (uint32_t)n * 128 + (cbyte ^ (((uint32_t)n & 7) << 4));
            *(uint32_t*)((char*)Bs + off) = pack2h(b0[n], b0[CONVDIM + n]);
        }
        __syncthreads();
        #pragma unroll
        for (int ks = 0; ks < 4; ks++) {
            uint32_t afr[2][4];
            #pragma unroll
            for (int mt = 0; mt < 2; mt++) {
                uint32_t row = (uint32_t)(a_row + mt * 16);
                uint32_t c = (uint32_t)ks * 32 + a_kb;
                ldsm_x4(afr[mt], as_base + row * 128 + (c ^ ((row & 7) << 4)));
            }
            uint32_t bfr[2][4];
            #pragma unroll
            for (int nh = 0; nh < 2; nh++) {
                uint32_t row = (uint32_t)(b_row + nh * 16);
                uint32_t c = (uint32_t)ks * 32 + b_kb;
                ldsm_x4(bfr[nh], bs_base + row * 128 + (c ^ ((row & 7) << 4)));
            }
            #pragma unroll
            for (int mt = 0; mt < 2; mt++)
                #pragma unroll
                for (int nt = 0; nt < 4; nt++)
                    mma_fp16(acc[mt][nt], afr[mt], &bfr[nt >> 1][(nt & 1) * 2]);
        }
    }

    size_t base = (size_t)(bc * NHEADS + h) * HEADDIM * D_STATE;
    int g = lane >> 2, tg = lane & 3;
    #pragma unroll
    for (int mt = 0; mt < 2; mt++) {
        int prow = wm + mt * 16 + g;
        #pragma unroll
        for (int nt = 0; nt < 4; nt++) {
            int col = wn + nt * 8 + tg * 2;
            *(float2*)(g_st + base + (size_t)prow * D_STATE + col) =
                make_float2(acc[mt][nt][0], acc[mt][nt][1]);
            *(float2*)(g_st + base + (size_t)(prow + 8) * D_STATE + col) =
                make_float2(acc[mt][nt][2], acc[mt][nt][3]);
        }
    }
}

// ============ fused SSD y-kernel (fp16 fragments, fp32 accumulate, fp16 y out) ============
__global__ __launch_bounds__(256, 1) void k_yfused() {
    __shared__ __align__(16) __half As[128 * 64];
    __shared__ __align__(16) __half Bs[128 * 64];
    __shared__ float gj_all[256];
    __shared__ float cas[8];
    int bc = blockIdx.x, h = blockIdx.y, ih = blockIdx.z;
    int i_base = ih * 128;
    int row0 = bc * CHUNK;
    int cb = (bc * NHEADS + h) * CHUNK;
    size_t psb = (size_t)(bc * NHEADS + h) * HEADDIM * D_STATE;

    int tid = threadIdx.x, lane = tid & 31, wid = tid >> 5;
    int wm = (wid & 3) * 32;
    int wn = (wid >> 2) * 64;

    int si = tid >> 1;
    int sj = (tid & 1) * 32;
    int gi = i_base + si;
    float ci = g_cum[cb + gi];
    float ei = __expf(ci);

    uint32_t as_base = smem_u32(As);
    uint32_t bs_base = smem_u32(Bs);

    int a_row = wm + (lane & 15);
    uint32_t a_kb = (uint32_t)(lane >> 4) * 16;
    int b_row = wn + (lane & 7) + ((lane & 16) ? 8 : 0);
    uint32_t b_kb = (lane & 8) ? 16u : 0u;

    int natt64 = (ih + 1) * 2;
    int nattj = natt64 * 64;

    if (tid < nattj) {
        int j = tid;
        float ca = g_cum[cb + (j & ~31) + 31];
        gj_all[j] = __expf(ca - g_cum[cb + j]) *
                    g_dt[(size_t)(row0 + j) * NHEADS + h];
    }
    if (tid < natt64 * 2) cas[tid] = g_cum[cb + tid * 32 + 31];

    float acc[2][8][4];
    #pragma unroll
    for (int mt = 0; mt < 2; mt++)
        #pragma unroll
        for (int nt = 0; nt < 8; nt++)
            #pragma unroll
            for (int q = 0; q < 4; q++) acc[mt][nt][q] = 0.f;

    int ntiles = natt64 + 1;
    for (int kt = 0; kt < ntiles; kt++) {
        __syncthreads();
        if (kt < natt64) {
            int j0 = kt * 64;
            int jb = j0 + sj;
            if (gi >= jb + 31) {
                float fi = __expf(ci - cas[jb >> 5]);
                const __half* Srow = g_Sh + ((size_t)bc * CHUNK + gi) * CHUNK + jb;
                const float* gjp = gj_all + jb;
                #pragma unroll
                for (int q = 0; q < 4; q++) {
                    uint4 sv = *(const uint4*)(Srow + q * 8);
                    float2 f0 = __half22float2(*(__half2*)&sv.x);
                    float2 f1 = __half22float2(*(__half2*)&sv.y);
                    float2 f2 = __half22float2(*(__half2*)&sv.z);
                    float2 f3 = __half22float2(*(__half2*)&sv.w);
                    uint4 u;
                    u.x = pack2(f0.x * fi * gjp[q*8+0], f0.y * fi * gjp[q*8+1]);
                    u.y = pack2(f1.x * fi * gjp[q*8+2], f1.y * fi * gjp[q*8+3]);
                    u.z = pack2(f2.x * fi * gjp[q*8+4], f2.y * fi * gjp[q*8+5]);
                    u.w = pack2(f3.x * fi * gjp[q*8+6], f3.y * fi * gjp[q*8+7]);
                    uint32_t cbyte = (uint32_t)(sj * 2 + q * 16);
                    uint32_t off = (uint32_t)si * 128 + (cbyte ^ (((uint32_t)si & 7) << 4));
                    *(uint4*)((char*)As + off) = u;
                }
            } else if (gi >= jb) {
                #pragma unroll
                for (int q = 0; q < 4; q++) {
                    float v[8];
                    #pragma unroll
                    for (int r = 0; r < 8; r++) {
                        int j = jb + q * 8 + r;
                        float a = 0.f;
                        if (j <= gi)
                            a = __half2float(g_Sh[((size_t)bc * CHUNK + gi) * CHUNK + j]) *
                                __expf(ci - g_cum[cb + j]) *
                                g_dt[(size_t)(row0 + j) * NHEADS + h];
                        v[r] = a;
                    }
                    uint4 u;
                    u.x = pack2(v[0], v[1]); u.y = pack2(v[2], v[3]);
                    u.z = pack2(v[4], v[5]); u.w = pack2(v[6], v[7]);
                    uint32_t cbyte = (uint32_t)(sj * 2 + q * 16);
                    uint32_t off = (uint32_t)si * 128 + (cbyte ^ (((uint32_t)si & 7) << 4));
                    *(uint4*)((char*)As + off) = u;
                }
            } else {
                #pragma unroll
                for (int q = 0; q < 4; q++) {
                    uint32_t cbyte = (uint32_t)(sj * 2 + q * 16);
                    uint32_t off = (uint32_t)si * 128 + (cbyte ^ (((uint32_t)si & 7) << 4));
                    *(uint4*)((char*)As + off) = make_uint4(0, 0, 0, 0);
                }
            }
            #pragma unroll
            for (int jp = 0; jp < 4; jp++) {
                int pair = wid + 8 * jp;
                int j = j0 + 2 * pair;
                const __half* x0 = g_xBCh + (size_t)(row0 + j) * CONVDIM + h * HEADDIM;
                const __half* x1 = x0 + CONVDIM;
                #pragma unroll
                for (int r = 0; r < 4; r++) {
                    int p = lane + 32 * r;
                    uint32_t cbyte = (uint32_t)pair * 4;
                    uint32_t off = (uint32_t)p * 128 + (cbyte ^ (((uint32_t)p & 7) << 4));
                    *(uint32_t*)((char*)Bs + off) = pack2h(x0[p], x1[p]);
                }
            }
        } else {
            // state tile: A = Ce[i][n], B = P[p][n] (both fp16 copies)
            const __half2* crow = (const __half2*)(g_xBCh + (size_t)(row0 + gi) * CONVDIM
                                                   + D_INNER + D_STATE + sj);
            #pragma unroll
            for (int q = 0; q < 4; q++) {
                uint4 hv = *(const uint4*)(crow + q * 4);
                float2 f0 = __half22float2(*(__half2*)&hv.x);
                float2 f1 = __half22float2(*(__half2*)&hv.y);
                float2 f2 = __half22float2(*(__half2*)&hv.z);
                float2 f3 = __half22float2(*(__half2*)&hv.w);
                uint4 u;
                u.x = pack2(f0.x * ei, f0.y * ei);
                u.y = pack2(f1.x * ei, f1.y * ei);
                u.z = pack2(f2.x * ei, f2.y * ei);
                u.w = pack2(f3.x * ei, f3.y * ei);
                uint32_t cbyte = (uint32_t)(sj * 2 + q * 16);
                uint32_t off = (uint32_t)si * 128 + (cbyte ^ (((uint32_t)si & 7) << 4));
                *(uint4*)((char*)As + off) = u;
            }
            int pr = tid >> 1;
            int nc = (tid & 1) * 32;
            const __half* prow = g_psh + psb + (size_t)pr * D_STATE + nc;
            #pragma unroll
            for (int q = 0; q < 2; q++) {
                uint4 u = *(const uint4*)(prow + q * 16);   // 16 halves
                uint32_t cbyte = (uint32_t)(nc * 2 + q * 32);
                uint32_t off = (uint32_t)pr * 128 + (cbyte ^ (((uint32_t)pr & 7) << 4));
                *(uint4*)((char*)Bs + off) = u;
                uint4 u2 = *(const uint4*)(prow + q * 16 + 8);
                // second 16B of the 32B chunk shares the same swizzle row
                uint32_t off2 = (uint32_t)pr * 128 + (((uint32_t)(nc * 2 + q * 32 + 16)) ^ (((uint32_t)pr & 7) << 4));
                *(uint4*)((char*)Bs + off2) = u2;
            }
        }
        __syncthreads();
        #pragma unroll
        for (int ks = 0; ks < 4; ks++) {
            uint32_t afr[2][4];
            #pragma unroll
            for (int mt = 0; mt < 2; mt++) {
                uint32_t row = (uint32_t)(a_row + mt * 16);
                uint32_t c = (uint32_t)ks * 32 + a_kb;
                ldsm_x4(afr[mt], as_base + row * 128 + (c ^ ((row & 7) << 4)));
            }
            uint32_t bfr[4][4];
            #pragma unroll
            for (int nh = 0; nh < 4; nh++) {
                uint32_t row = (uint32_t)(b_row + nh * 16);
                uint32_t c = (uint32_t)ks * 32 + b_kb;
                ldsm_x4(bfr[nh], bs_base + row * 128 + (c ^ ((row & 7) << 4)));
            }
            #pragma unroll
            for (int mt = 0; mt < 2; mt++)
                #pragma unroll
                for (int nt = 0; nt < 8; nt++)
                    mma_fp16(acc[mt][nt], afr[mt], &bfr[nt >> 1][(nt & 1) * 2]);
        }
    }

    int g = lane >> 2, tg = lane & 3;
    #pragma unroll
    for (int mt = 0; mt < 2; mt++) {
        int orow = row0 + i_base + wm + mt * 16 + g;
        #pragma unroll
        for (int nt = 0; nt < 8; nt++) {
            int col = h * HEADDIM + wn + nt * 8 + tg * 2;
            *(uint32_t*)(g_yh + (size_t)orow * D_INNER + col) =
                pack2(acc[mt][nt][0], acc[mt][nt][1]);
            *(uint32_t*)(g_yh + (size_t)(orow + 8) * D_INNER + col) =
                pack2(acc[mt][nt][2], acc[mt][nt][3]);
        }
    }
}

// ---------------- reductions ----------------
__device__ __forceinline__ float blockReduceSum256(float v) {
    __shared__ float red[8];
    __shared__ float tot;
    int lane = threadIdx.x & 31, wid = threadIdx.x >> 5;
    #pragma unroll
    for (int o = 16; o; o >>= 1) v += __shfl_down_sync(0xffffffffu, v, o);
    if (lane == 0) red[wid] = v;
    __syncthreads();
    if (wid == 0) {
        float w = (lane < 8) ? red[lane] : 0.f;
        #pragma unroll
        for (int o = 4; o; o >>= 1) w += __shfl_down_sync(0xffffffffu, w, o);
        if (lane == 0) tot = w;
    }
    __syncthreads();
    return tot;
}

// ---------------- K1: l2-normalize weight rows ----------------
__global__ __launch_bounds__(256) void k_normw(const float* __restrict__ W,
                                               __half* __restrict__ Wo, int K, float extra) {
    int r = blockIdx.x;
    const float* wr = W + (size_t)r * K;
    float s2 = 0.f;
    for (int i = threadIdx.x; i < K; i += 256) { float v = wr[i]; s2 += v * v; }
    float totv = blockReduceSum256(s2);
    float sc = extra / fmaxf(sqrtf(totv), 1e-6f);
    for (int i = threadIdx.x; i < K; i += 256)
        Wo[(size_t)r * K + i] = __float2half_rn(wr[i] * sc);
}

// ---------------- K2: layernorm ----------------
__global__ __launch_bounds__(256) void k_layernorm(const float* __restrict__ u,
                                                   const float* __restrict__ w,
                                                   const float* __restrict__ b) {
    int row = blockIdx.x;
    const float* ur = u + (size_t)row * XDIM;
    float v[4]; float s = 0.f, s2 = 0.f;
    #pragma unroll
    for (int k = 0; k < 4; k++) {
        v[k] = ur[threadIdx.x + 256 * k];
        s += v[k]; s2 += v[k] * v[k];
    }
    float sum = blockReduceSum256(s);
    float sumsq = blockReduceSum256(s2);
    float mu = sum * (1.f / XDIM);
    float var = sumsq * (1.f / XDIM) - mu * mu;
    float inv = rsqrtf(var + 1e-5f);
    #pragma unroll
    for (int k = 0; k < 4; k++) {
        int d = threadIdx.x + 256 * k;
        g_lnh[(size_t)row * XDIM + d] = __float2half_rn((v[k] - mu) * inv * w[d] + b[d]);
    }
}

// ---------------- K4: depthwise causal conv + bias + silu (fp16 in/out) ----------------
__global__ __launch_bounds__(128) void k_conv(const float* __restrict__ cw,
                                              const float* __restrict__ cb) {
    int ch = blockIdx.x * 128 + threadIdx.x;
    if (ch >= CONVDIM) return;
    int row0 = blockIdx.y * 8;
    int l0 = row0 & (SEQLEN - 1);
    float w0 = cw[ch * 4 + 0], w1 = cw[ch * 4 + 1];
    float w2 = cw[ch * 4 + 2], w3 = cw[ch * 4 + 3];
    float bias = cb[ch];
    float v[11];
    #pragma unroll
    for (int k = 0; k < 11; k++) {
        int l = l0 - 3 + k;
        v[k] = (l >= 0)
            ? __half2float(g_zxh[(size_t)(row0 - 3 + k) * DPROJP + D_INNER + ch]) : 0.f;
    }
    #pragma unroll
    for (int r = 0; r < 8; r++) {
        float acc = bias + w0 * v[r] + w1 * v[r + 1] + w2 * v[r + 2] + w3 * v[r + 3];
        float s = acc / (1.f + __expf(-acc));
        g_xBCh[(size_t)(row0 + r) * CONVDIM + ch] = __float2half_rn(s);
    }
}

// ---------------- K5: dt softplus + per-chunk cumulative dA (fp32 dt_raw) ----------------
__global__ __launch_bounds__(256) void k_dtcum(const float* __restrict__ dt_bias,
                                               const float* __restrict__ A_log) {
    int bch = blockIdx.x;
    int h = bch & 15, bc = bch >> 4;
    int t = threadIdx.x;
    int row = bc * CHUNK + t;
    float x = g_dtraw[(size_t)row * NHEADS + h] + dt_bias[h];
    float dtv = (x > 20.f) ? x : log1pf(expf(x));
    g_dt[(size_t)row * NHEADS + h] = dtv;
    float dA = dtv * (-expf(A_log[h]));
    __shared__ float s[256];
    s[t] = dA;
    __syncthreads();
    #pragma unroll
    for (int off = 1; off < 256; off <<= 1) {
        float pv = (t >= off) ? s[t - off] : 0.f;
        __syncthreads();
        s[t] += pv;
        __syncthreads();
    }
    g_cum[(size_t)bch * CHUNK + t] = s[t];
    if (t == 255) g_cdec[bch] = __expf(s[255]);
}

// ---------------- K8: inter-chunk scan (fp32 carry, fp16 ps out) ----------------
__global__ __launch_bounds__(256) void k_scan() {
    int b = blockIdx.x, h = blockIdx.y, z = blockIdx.z;
    int tid = threadIdx.x;
    int e0 = z * 1024 + tid * 4;
    float4 carry = make_float4(0.f, 0.f, 0.f, 0.f);
    for (int c = 0; c < NCPB; c++) {
        int bch = (b * NCPB + c) * NHEADS + h;
        float dec = g_cdec[bch];
        size_t base = (size_t)bch * HEADDIM * D_STATE + e0;
        uint2 pk;
        pk.x = pack2(carry.x, carry.y);
        pk.y = pack2(carry.z, carry.w);
        *(uint2*)(g_psh + base) = pk;
        float4 st = *(const float4*)(g_st + base);
        carry.x = carry.x * dec + st.x;
        carry.y = carry.y * dec + st.y;
        carry.z = carry.z * dec + st.z;
        carry.w = carry.w * dec + st.w;
    }
}

// ---------------- K10: y += D*x, gate, RMS norm (fp16 in/out) ----------------
__global__ __launch_bounds__(256) void k_gate(const float* __restrict__ Dp,
                                              const float* __restrict__ rms_w) {
    int row = blockIdx.x;
    int tid = threadIdx.x;
    float gg[8];
    float s2 = 0.f;
    #pragma unroll
    for (int k = 0; k < 8; k++) {
        int d = tid + 256 * k;
        float xv = __half2float(g_xBCh[(size_t)row * CONVDIM + d]);
        float yv = __half2float(g_yh[(size_t)row * D_INNER + d]);
        float v = yv + Dp[d >> 7] * xv;
        float z = __half2float(g_zxh[(size_t)row * DPROJP + d]);
        float sil = z / (1.f + __expf(-z));
        float g = v * sil;
        gg[k] = g;
        s2 += g * g;
    }
    float tot = blockReduceSum256(s2);
    float sc = rsqrtf(tot * (1.f / D_INNER) + 1e-5f);
    #pragma unroll
    for (int k = 0; k < 8; k++) {
        int d = tid + 256 * k;
        g_gh[(size_t)row * D_INNER + d] = __float2half_rn(gg[k] * sc * rms_w[d]);
    }
}

// ---------------- host launcher ----------------
extern "C" void kernel_launch(void* const* d_in, const int* in_sizes, int n_in,
                              void* d_out, int out_size) {
    const float* u          = (const float*)d_in[0];
    const float* in_proj_w  = (const float*)d_in[1];
    const float* conv_w     = (const float*)d_in[2];
    const float* conv_b     = (const float*)d_in[3];
    const float* dt_bias    = (const float*)d_in[4];
    const float* A_log      = (const float*)d_in[5];
    const float* Dp         = (const float*)d_in[6];
    const float* xnw        = (const float*)d_in[7];
    const float* xnb        = (const float*)d_in[8];
    const float* rms_w      = (const float*)d_in[9];
    const float* out_proj_w = (const float*)d_in[10];
    float* out = (float*)d_out;

    __half *pWinH, *pWoutH, *pLnH, *pGH, *pZxH;
    cudaGetSymbolAddress((void**)&pWinH,  g_Winh);
    cudaGetSymbolAddress((void**)&pWoutH, g_Wouth);
    cudaGetSymbolAddress((void**)&pLnH,   g_lnh);
    cudaGetSymbolAddress((void**)&pGH,    g_gh);
    cudaGetSymbolAddress((void**)&pZxH,   g_zxh);

    static int smem_set = 0;
    if (!smem_set) {
        cudaFuncSetAttribute(gemm_hc, cudaFuncAttributeMaxDynamicSharedMemorySize, GEMM_SMEM);
        cudaFuncSetAttribute(gemm_hc_h, cudaFuncAttributeMaxDynamicSharedMemorySize, GEMM_SMEM);
        smem_set = 1;
    }

    k_normw<<<DPROJ, 256>>>(in_proj_w, pWinH, XDIM, 0.03125f);
    k_normw<<<XDIM, 256>>>(out_proj_w, pWoutH, D_INNER, 1.0f);

    k_layernorm<<<R_TOT, 256>>>(u, xnw, xnb);

    // in_proj GEMM: fp16 output + fp32 dt side-channel
    gemm_hc_h<<<dim3(DPROJP / GBN, R_TOT / GBM), 128, GEMM_SMEM>>>(pLnH, pWinH, pZxH, XDIM, DPROJP);

    k_conv<<<dim3((CONVDIM + 127) / 128, R_TOT / 8), 128>>>(conv_w, conv_b);
    k_dtcum<<<NBC * NHEADS, 256>>>(dt_bias, A_log);

    k_scores_h<<<dim3(NBC, 3), 256>>>();
    k_states_h<<<dim3(NBC, NHEADS), 256>>>();
    k_scan<<<dim3(NBATCH, NHEADS, 8), 256>>>();
    k_yfused<<<dim3(NBC, NHEADS, 2), 256>>>();

    k_gate<<<R_TOT, 256>>>(Dp, rms_w);

    gemm_hc<<<dim3(XDIM / GBN, R_TOT / GBM), 128, GEMM_SMEM>>>(pGH, pWoutH, out, D_INNER, XDIM);
}

// round 13
// speedup vs baseline: 6.6721x; 1.0190x over previous
#include <cuda_runtime.h>
#include <cuda_fp16.h>
#include <math.h>
#include <stdint.h>

// ---------------- problem constants ----------------
#define XDIM    1024
#define D_STATE 64
#define HEADDIM 128
#define D_INNER 2048
#define NHEADS  16
#define CONVDIM 2176              // D_INNER + 2*64
#define DPROJ   4240              // 2*2048 + 2*64 + 16
#define DPROJP  4352              // padded to 128-multiple for GEMM tiles
#define DT_BASE 4224              // D_INNER + CONVDIM
#define CHUNK   256
#define NBATCH  2
#define SEQLEN  4096
#define NCPB    16
#define NBC     32
#define R_TOT   8192

// ---------------- device scratch ----------------
__device__ __half g_lnh [(size_t)R_TOT * XDIM];
__device__ __half g_Winh[(size_t)DPROJP * XDIM];     // rows >= DPROJ stay zero (.bss)
__device__ __half g_Wouth[(size_t)XDIM * D_INNER];
__device__ __half g_gh  [(size_t)R_TOT * D_INNER];
__device__ __half g_zxh [(size_t)R_TOT * DPROJP];    // fp16 in_proj output
__device__ __half g_xBCh[(size_t)R_TOT * CONVDIM];   // fp16 conv output
__device__ __half g_yh  [(size_t)R_TOT * D_INNER];   // fp16 y
__device__ __half g_Sh  [(size_t)NBC * CHUNK * CHUNK];  // fp16 scores
__device__ __half g_psh [(size_t)NBC * NHEADS * HEADDIM * D_STATE];  // fp16 prev states
__device__ float g_dtraw[(size_t)R_TOT * NHEADS];    // fp32 dt_raw side-channel
__device__ float g_dt  [(size_t)R_TOT * NHEADS];
__device__ float g_cum [(size_t)NBC * NHEADS * CHUNK];
__device__ float g_cdec[(size_t)NBC * NHEADS];
__device__ float g_st  [(size_t)NBC * NHEADS * HEADDIM * D_STATE];

// ---------------- PTX helpers (baseline PTX only) ----------------
__device__ __forceinline__ uint32_t smem_u32(const void* p) {
    uint32_t a;
    asm("{ .reg .u64 t; cvta.to.shared.u64 t, %1; cvt.u32.u64 %0, t; }" : "=r"(a) : "l"(p));
    return a;
}
__device__ __forceinline__ uint32_t pack2(float a, float b) {
    __half2 h = __floats2half2_rn(a, b);
    return *(uint32_t*)&h;
}
__device__ __forceinline__ uint32_t pack2h(__half a, __half b) {
    __half2 h = __halves2half2(a, b);
    return *(uint32_t*)&h;
}
#define CP_ASYNC16(s, g) \
    asm volatile("cp.async.cg.shared.global [%0], [%1], 16;" :: "r"(s), "l"(g))
#define CP_COMMIT() asm volatile("cp.async.commit_group;" ::: "memory")
#define CP_WAIT(n)  asm volatile("cp.async.wait_group %0;" :: "n"(n) : "memory")

__device__ __forceinline__ void ldsm_x4(uint32_t* r, uint32_t addr) {
    asm volatile("ldmatrix.sync.aligned.m8n8.x4.shared.b16 {%0,%1,%2,%3}, [%4];"
        : "=r"(r[0]), "=r"(r[1]), "=r"(r[2]), "=r"(r[3]) : "r"(addr));
}
__device__ __forceinline__ void mma_fp16(float* d, const uint32_t* a, const uint32_t* b) {
    asm volatile("mma.sync.aligned.m16n8k16.row.col.f32.f16.f16.f32 "
        "{%0,%1,%2,%3},{%4,%5,%6,%7},{%8,%9},{%0,%1,%2,%3};"
        : "+f"(d[0]), "+f"(d[1]), "+f"(d[2]), "+f"(d[3])
        : "r"(a[0]), "r"(a[1]), "r"(a[2]), "r"(a[3]), "r"(b[0]), "r"(b[1]));
}

// ================= fp16 tensor-core GEMM =================
#define GBM 128
#define GBN 128
#define GBK 64
#define GSTG 3
#define TB_A (GBM * GBK * 2)
#define TB_B (GBN * GBK * 2)
#define STAGE_B (TB_A + TB_B)
#define GEMM_SMEM (GSTG * STAGE_B)

__device__ __forceinline__ void gemm_load_tile_h(const __half* Ab, const __half* Bb,
                                                 int K, int t, uint32_t sb, int tid) {
    const __half* Ap = Ab + (size_t)t * GBK;
    const __half* Bp = Bb + (size_t)t * GBK;
    #pragma unroll
    for (int j = 0; j < 8; j++) {
        int c = tid + 128 * j;
        int row = c >> 3;
        uint32_t cc = (uint32_t)(c & 7) * 16;
        uint32_t off = (uint32_t)row * 128 + (cc ^ (((uint32_t)row & 7) << 4));
        CP_ASYNC16(sb + off, Ap + (size_t)row * K + (cc >> 1));
    }
    uint32_t sb2 = sb + TB_A;
    #pragma unroll
    for (int j = 0; j < 8; j++) {
        int c = tid + 128 * j;
        int row = c >> 3;
        uint32_t cc = (uint32_t)(c & 7) * 16;
        uint32_t off = (uint32_t)row * 128 + (cc ^ (((uint32_t)row & 7) << 4));
        CP_ASYNC16(sb2 + off, Bp + (size_t)row * K + (cc >> 1));
    }
    CP_COMMIT();
}

#define GEMM_MAIN(acc, A, B, K)                                                     \
    int T = (K) / GBK;                                                              \
    gemm_load_tile_h(A, B, K, 0, sbase, tid);                                       \
    gemm_load_tile_h(A, B, K, 1, sbase + STAGE_B, tid);                             \
    for (int t = 0; t < T; t++) {                                                   \
        CP_WAIT(1);                                                                 \
        __syncthreads();                                                            \
        if (t + 2 < T)                                                              \
            gemm_load_tile_h(A, B, K, t + 2, sbase + ((t + 2) % GSTG) * STAGE_B, tid); \
        uint32_t sa = sbase + (t % GSTG) * STAGE_B;                                 \
        uint32_t sb = sa + TB_A;                                                    \
        _Pragma("unroll")                                                           \
        for (int ks = 0; ks < 4; ks++) {                                            \
            uint32_t afr[4][4];                                                     \
            _Pragma("unroll")                                                       \
            for (int mt = 0; mt < 4; mt++) {                                        \
                uint32_t row = (uint32_t)(a_row + mt * 16);                         \
                uint32_t c = (uint32_t)ks * 32 + a_kb;                              \
                ldsm_x4(afr[mt], sa + row * 128 + (c ^ ((row & 7) << 4)));          \
            }                                                                       \
            uint32_t bfr[4][4];                                                     \
            _Pragma("unroll")                                                       \
            for (int nh = 0; nh < 4; nh++) {                                        \
                uint32_t row = (uint32_t)(b_row + nh * 16);                         \
                uint32_t c = (uint32_t)ks * 32 + b_kb;                              \
                ldsm_x4(bfr[nh], sb + row * 128 + (c ^ ((row & 7) << 4)));          \
            }                                                                       \
            _Pragma("unroll")                                                       \
            for (int mt = 0; mt < 4; mt++)                                          \
                _Pragma("unroll")                                                   \
                for (int nt = 0; nt < 8; nt++)                                      \
                    mma_fp16(acc[mt][nt], afr[mt], &bfr[nt >> 1][(nt & 1) * 2]);    \
        }                                                                           \
    }

// fp32-output GEMM (out_proj)
__global__ __launch_bounds__(128, 2) void gemm_hc(const __half* __restrict__ A,
                                                  const __half* __restrict__ B,
                                                  float* __restrict__ C,
                                                  int K, int ldc) {
    extern __shared__ char sm[];
    uint32_t sbase = smem_u32(sm);
    int tid = threadIdx.x, lane = tid & 31, wid = tid >> 5;
    int wm = (wid & 1) * 64, wn = (wid >> 1) * 64;
    int m0 = blockIdx.y * GBM, n0 = blockIdx.x * GBN;
    const __half* Ab = A + (size_t)m0 * K;
    const __half* Bb = B + (size_t)n0 * K;
    int a_row = wm + (lane & 15);
    uint32_t a_kb = (uint32_t)(lane >> 4) * 16;
    int b_row = wn + (lane & 7) + ((lane & 16) ? 8 : 0);
    uint32_t b_kb = (lane & 8) ? 16u : 0u;

    float acc[4][8][4];
    #pragma unroll
    for (int mt = 0; mt < 4; mt++)
        #pragma unroll
        for (int nt = 0; nt < 8; nt++)
            #pragma unroll
            for (int q = 0; q < 4; q++) acc[mt][nt][q] = 0.f;

    GEMM_MAIN(acc, Ab, Bb, K)

    int g = lane >> 2, tg = lane & 3;
    #pragma unroll
    for (int mt = 0; mt < 4; mt++) {
        int rowa = m0 + wm + mt * 16 + g;
        #pragma unroll
        for (int nt = 0; nt < 8; nt++) {
            int col = n0 + wn + nt * 8 + tg * 2;
            *(float2*)(C + (size_t)rowa * ldc + col) =
                make_float2(acc[mt][nt][0], acc[mt][nt][1]);
            *(float2*)(C + (size_t)(rowa + 8) * ldc + col) =
                make_float2(acc[mt][nt][2], acc[mt][nt][3]);
        }
    }
}

// fp16-output GEMM (in_proj) with fp32 dt side-channel
__global__ __launch_bounds__(128, 2) void gemm_hc_h(const __half* __restrict__ A,
                                                    const __half* __restrict__ B,
                                                    __half* __restrict__ C,
                                                    int K, int ldc) {
    extern __shared__ char sm[];
    uint32_t sbase = smem_u32(sm);
    int tid = threadIdx.x, lane = tid & 31, wid = tid >> 5;
    int wm = (wid & 1) * 64, wn = (wid >> 1) * 64;
    int m0 = blockIdx.y * GBM, n0 = blockIdx.x * GBN;
    const __half* Ab = A + (size_t)m0 * K;
    const __half* Bb = B + (size_t)n0 * K;
    int a_row = wm + (lane & 15);
    uint32_t a_kb = (uint32_t)(lane >> 4) * 16;
    int b_row = wn + (lane & 7) + ((lane & 16) ? 8 : 0);
    uint32_t b_kb = (lane & 8) ? 16u : 0u;

    float acc[4][8][4];
    #pragma unroll
    for (int mt = 0; mt < 4; mt++)
        #pragma unroll
        for (int nt = 0; nt < 8; nt++)
            #pragma unroll
            for (int q = 0; q < 4; q++) acc[mt][nt][q] = 0.f;

    GEMM_MAIN(acc, Ab, Bb, K)

    int g = lane >> 2, tg = lane & 3;
    #pragma unroll
    for (int mt = 0; mt < 4; mt++) {
        int rowa = m0 + wm + mt * 16 + g;
        #pragma unroll
        for (int nt = 0; nt < 8; nt++) {
            int col = n0 + wn + nt * 8 + tg * 2;
            *(uint32_t*)(C + (size_t)rowa * ldc + col) =
                pack2(acc[mt][nt][0], acc[mt][nt][1]);
            *(uint32_t*)(C + (size_t)(rowa + 8) * ldc + col) =
                pack2(acc[mt][nt][2], acc[mt][nt][3]);
            if (col >= DT_BASE && col < DPROJ) {
                int d = col - DT_BASE;
                g_dtraw[(size_t)rowa * NHEADS + d]     = acc[mt][nt][0];
                g_dtraw[(size_t)rowa * NHEADS + d + 1] = acc[mt][nt][1];
                g_dtraw[(size_t)(rowa + 8) * NHEADS + d]     = acc[mt][nt][2];
                g_dtraw[(size_t)(rowa + 8) * NHEADS + d + 1] = acc[mt][nt][3];
            }
        }
    }
}

// ============ K6a (fp16 MMA): S tile = C @ B^T, K=64 (fp16 S out) ============
__global__ __launch_bounds__(256, 2) void k_scores_h() {
    __shared__ __align__(16) __half As[128 * 64];
    __shared__ __align__(16) __half Bs[128 * 64];
    int bc = blockIdx.x;
    int tile = blockIdx.y;
    int i0 = (tile != 0) ? 128 : 0;
    int j0 = (tile == 2) ? 128 : 0;
    int row0 = bc * CHUNK;
    int tid = threadIdx.x, lane = tid & 31, wid = tid >> 5;

    uint32_t as_base = smem_u32(As);
    uint32_t bs_base = smem_u32(Bs);
    const __half* Cb = g_xBCh + (size_t)(row0 + i0) * CONVDIM + D_INNER + D_STATE;
    const __half* Bb = g_xBCh + (size_t)(row0 + j0) * CONVDIM + D_INNER;
    #pragma unroll
    for (int j = 0; j < 4; j++) {
        int c = tid + 256 * j;
        int row = c >> 3;
        uint32_t cc = (uint32_t)(c & 7) * 16;
        uint32_t off = (uint32_t)row * 128 + (cc ^ (((uint32_t)row & 7) << 4));
        CP_ASYNC16(as_base + off, Cb + (size_t)row * CONVDIM + (cc >> 1));
        CP_ASYNC16(bs_base + off, Bb + (size_t)row * CONVDIM + (cc >> 1));
    }
    CP_COMMIT();
    CP_WAIT(0);
    __syncthreads();

    int wm = (wid & 3) * 32;
    int wn = (wid >> 2) * 64;
    int a_row = wm + (lane & 15);
    uint32_t a_kb = (uint32_t)(lane >> 4) * 16;
    int b_row = wn + (lane & 7) + ((lane & 16) ? 8 : 0);
    uint32_t b_kb = (lane & 8) ? 16u : 0u;

    float acc[2][8][4];
    #pragma unroll
    for (int mt = 0; mt < 2; mt++)
        #pragma unroll
        for (int nt = 0; nt < 8; nt++)
            #pragma unroll
            for (int q = 0; q < 4; q++) acc[mt][nt][q] = 0.f;

    #pragma unroll
    for (int ks = 0; ks < 4; ks++) {
        uint32_t afr[2][4];
        #pragma unroll
        for (int mt = 0; mt < 2; mt++) {
            uint32_t row = (uint32_t)(a_row + mt * 16);
            uint32_t c = (uint32_t)ks * 32 + a_kb;
            ldsm_x4(afr[mt], as_base + row * 128 + (c ^ ((row & 7) << 4)));
        }
        uint32_t bfr[4][4];
        #pragma unroll
        for (int nh = 0; nh < 4; nh++) {
            uint32_t row = (uint32_t)(b_row + nh * 16);
            uint32_t c = (uint32_t)ks * 32 + b_kb;
            ldsm_x4(bfr[nh], bs_base + row * 128 + (c ^ ((row & 7) << 4)));
        }
        #pragma unroll
        for (int mt = 0; mt < 2; mt++)
            #pragma unroll
            for (int nt = 0; nt < 8; nt++)
                mma_fp16(acc[mt][nt], afr[mt], &bfr[nt >> 1][(nt & 1) * 2]);
    }

    int g = lane >> 2, tg = lane & 3;
    #pragma unroll
    for (int mt = 0; mt < 2; mt++) {
        int irow = i0 + wm + mt * 16 + g;
        #pragma unroll
        for (int nt = 0; nt < 8; nt++) {
            int col = j0 + wn + nt * 8 + tg * 2;
            *(uint32_t*)(g_Sh + ((size_t)bc * CHUNK + irow) * CHUNK + col) =
                pack2(acc[mt][nt][0], acc[mt][nt][1]);
            *(uint32_t*)(g_Sh + ((size_t)bc * CHUNK + irow + 8) * CHUNK + col) =
                pack2(acc[mt][nt][2], acc[mt][nt][3]);
        }
    }
}

// ============ K7 (fp16 MMA): states[p][n] = sum_t (x[t][p]*w_t) * B[t][n] ============
__global__ __launch_bounds__(256, 2) void k_states_h() {
    __shared__ __align__(16) __half As[128 * 64];
    __shared__ __align__(16) __half Bs[64 * 64];
    __shared__ float wsh[256];
    int bc = blockIdx.x, h = blockIdx.y;
    int row0 = bc * CHUNK;
    int cb = (bc * NHEADS + h) * CHUNK;
    int tid = threadIdx.x, lane = tid & 31, wid = tid >> 5;

    float cum_last = g_cum[cb + 255];
    wsh[tid] = g_dt[(size_t)(row0 + tid) * NHEADS + h] *
               __expf(cum_last - g_cum[cb + tid]);

    uint32_t as_base = smem_u32(As);
    uint32_t bs_base = smem_u32(Bs);

    int wm = (wid & 3) * 32;
    int wn = (wid >> 2) * 32;
    int a_row = wm + (lane & 15);
    uint32_t a_kb = (uint32_t)(lane >> 4) * 16;
    int b_row = wn + (lane & 7) + ((lane & 16) ? 8 : 0);
    uint32_t b_kb = (lane & 8) ? 16u : 0u;

    float acc[2][4][4];
    #pragma unroll
    for (int mt = 0; mt < 2; mt++)
        #pragma unroll
        for (int nt = 0; nt < 4; nt++)
            #pragma unroll
            for (int q = 0; q < 4; q++) acc[mt][nt][q] = 0.f;

    for (int kt = 0; kt < 4; kt++) {
        int t0 = kt * 64;
        __syncthreads();
        #pragma unroll
        for (int jp = 0; jp < 4; jp++) {
            int pair = wid + 8 * jp;
            int t = t0 + 2 * pair;
            const __half* x0 = g_xBCh + (size_t)(row0 + t) * CONVDIM + h * HEADDIM;
            const __half* x1 = x0 + CONVDIM;
            float w0 = wsh[t], w1 = wsh[t + 1];
            #pragma unroll
            for (int r = 0; r < 4; r++) {
                int p = lane + 32 * r;
                uint32_t cbyte = (uint32_t)pair * 4;
                uint32_t off = (uint32_t)p * 128 + (cbyte ^ (((uint32_t)p & 7) << 4));
                *(uint32_t*)((char*)As + off) =
                    pack2(__half2float(x0[p]) * w0, __half2float(x1[p]) * w1);
            }
        }
        #pragma unroll
        for (int q = 0; q < 8; q++) {
            int idx = tid + 256 * q;
            int n = idx >> 5, pair = idx & 31;
            int t = t0 + 2 * pair;
            const __half* b0 = g_xBCh + (size_t)(row0 + t) * CONVDIM + D_INNER;
            uint32_t cbyte = (uint32_t)pair * 4;
            uint32_t off = (uint32_t)n * 128 + (cbyte ^ (((uint32_t)n & 7) << 4));
            *(uint32_t*)((char*)Bs + off) = pack2h(b0[n], b0[CONVDIM + n]);
        }
        __syncthreads();
        #pragma unroll
        for (int ks = 0; ks < 4; ks++) {
            uint32_t afr[2][4];
            #pragma unroll
            for (int mt = 0; mt < 2; mt++) {
                uint32_t row = (uint32_t)(a_row + mt * 16);
                uint32_t c = (uint32_t)ks * 32 + a_kb;
                ldsm_x4(afr[mt], as_base + row * 128 + (c ^ ((row & 7) << 4)));
            }
            uint32_t bfr[2][4];
            #pragma unroll
            for (int nh = 0; nh < 2; nh++) {
                uint32_t row = (uint32_t)(b_row + nh * 16);
                uint32_t c = (uint32_t)ks * 32 + b_kb;
                ldsm_x4(bfr[nh], bs_base + row * 128 + (c ^ ((row & 7) << 4)));
            }
            #pragma unroll
            for (int mt = 0; mt < 2; mt++)
                #pragma unroll
                for (int nt = 0; nt < 4; nt++)
                    mma_fp16(acc[mt][nt], afr[mt], &bfr[nt >> 1][(nt & 1) * 2]);
        }
    }

    size_t base = (size_t)(bc * NHEADS + h) * HEADDIM * D_STATE;
    int g = lane >> 2, tg = lane & 3;
    #pragma unroll
    for (int mt = 0; mt < 2; mt++) {
        int prow = wm + mt * 16 + g;
        #pragma unroll
        for (int nt = 0; nt < 4; nt++) {
            int col = wn + nt * 8 + tg * 2;
            *(float2*)(g_st + base + (size_t)prow * D_STATE + col) =
                make_float2(acc[mt][nt][0], acc[mt][nt][1]);
            *(float2*)(g_st + base + (size_t)(prow + 8) * D_STATE + col) =
                make_float2(acc[mt][nt][2], acc[mt][nt][3]);
        }
    }
}

// ============ fused SSD y-kernel (fp16 fragments, fp32 accumulate, fp16 y out) ============
__global__ __launch_bounds__(256, 2) void k_yfused() {
    __shared__ __align__(16) __half As[128 * 64];
    __shared__ __align__(16) __half Bs[128 * 64];
    __shared__ float gj_all[256];
    __shared__ float cas[8];
    int bc = blockIdx.x, h = blockIdx.y, ih = blockIdx.z;
    int i_base = ih * 128;
    int row0 = bc * CHUNK;
    int cb = (bc * NHEADS + h) * CHUNK;
    size_t psb = (size_t)(bc * NHEADS + h) * HEADDIM * D_STATE;

    int tid = threadIdx.x, lane = tid & 31, wid = tid >> 5;
    int wm = (wid & 3) * 32;
    int wn = (wid >> 2) * 64;

    int si = tid >> 1;
    int sj = (tid & 1) * 32;
    int gi = i_base + si;
    float ci = g_cum[cb + gi];
    float ei = __expf(ci);

    uint32_t as_base = smem_u32(As);
    uint32_t bs_base = smem_u32(Bs);

    int a_row = wm + (lane & 15);
    uint32_t a_kb = (uint32_t)(lane >> 4) * 16;
    int b_row = wn + (lane & 7) + ((lane & 16) ? 8 : 0);
    uint32_t b_kb = (lane & 8) ? 16u : 0u;

    int natt64 = (ih + 1) * 2;
    int nattj = natt64 * 64;

    if (tid < nattj) {
        int j = tid;
        float ca = g_cum[cb + (j & ~31) + 31];
        gj_all[j] = __expf(ca - g_cum[cb + j]) *
                    g_dt[(size_t)(row0 + j) * NHEADS + h];
    }
    if (tid < natt64 * 2) cas[tid] = g_cum[cb + tid * 32 + 31];

    float acc[2][8][4];
    #pragma unroll
    for (int mt = 0; mt < 2; mt++)
        #pragma unroll
        for (int nt = 0; nt < 8; nt++)
            #pragma unroll
            for (int q = 0; q < 4; q++) acc[mt][nt][q] = 0.f;

    int ntiles = natt64 + 1;
    for (int kt = 0; kt < ntiles; kt++) {
        __syncthreads();
        if (kt < natt64) {
            int j0 = kt * 64;
            int jb = j0 + sj;
            if (gi >= jb + 31) {
                float fi = __expf(ci - cas[jb >> 5]);
                const __half* Srow = g_Sh + ((size_t)bc * CHUNK + gi) * CHUNK + jb;
                const float* gjp = gj_all + jb;
                #pragma unroll
                for (int q = 0; q < 4; q++) {
                    uint4 sv = *(const uint4*)(Srow + q * 8);
                    float2 f0 = __half22float2(*(__half2*)&sv.x);
                    float2 f1 = __half22float2(*(__half2*)&sv.y);
                    float2 f2 = __half22float2(*(__half2*)&sv.z);
                    float2 f3 = __half22float2(*(__half2*)&sv.w);
                    uint4 u;
                    u.x = pack2(f0.x * fi * gjp[q*8+0], f0.y * fi * gjp[q*8+1]);
                    u.y = pack2(f1.x * fi * gjp[q*8+2], f1.y * fi * gjp[q*8+3]);
                    u.z = pack2(f2.x * fi * gjp[q*8+4], f2.y * fi * gjp[q*8+5]);
                    u.w = pack2(f3.x * fi * gjp[q*8+6], f3.y * fi * gjp[q*8+7]);
                    uint32_t cbyte = (uint32_t)(sj * 2 + q * 16);
                    uint32_t off = (uint32_t)si * 128 + (cbyte ^ (((uint32_t)si & 7) << 4));
                    *(uint4*)((char*)As + off) = u;
                }
            } else if (gi >= jb) {
                #pragma unroll
                for (int q = 0; q < 4; q++) {
                    float v[8];
                    #pragma unroll
                    for (int r = 0; r < 8; r++) {
                        int j = jb + q * 8 + r;
                        float a = 0.f;
                        if (j <= gi)
                            a = __half2float(g_Sh[((size_t)bc * CHUNK + gi) * CHUNK + j]) *
                                __expf(ci - g_cum[cb + j]) *
                                g_dt[(size_t)(row0 + j) * NHEADS + h];
                        v[r] = a;
                    }
                    uint4 u;
                    u.x = pack2(v[0], v[1]); u.y = pack2(v[2], v[3]);
                    u.z = pack2(v[4], v[5]); u.w = pack2(v[6], v[7]);
                    uint32_t cbyte = (uint32_t)(sj * 2 + q * 16);
                    uint32_t off = (uint32_t)si * 128 + (cbyte ^ (((uint32_t)si & 7) << 4));
                    *(uint4*)((char*)As + off) = u;
                }
            } else {
                #pragma unroll
                for (int q = 0; q < 4; q++) {
                    uint32_t cbyte = (uint32_t)(sj * 2 + q * 16);
                    uint32_t off = (uint32_t)si * 128 + (cbyte ^ (((uint32_t)si & 7) << 4));
                    *(uint4*)((char*)As + off) = make_uint4(0, 0, 0, 0);
                }
            }
            #pragma unroll
            for (int jp = 0; jp < 4; jp++) {
                int pair = wid + 8 * jp;
                int j = j0 + 2 * pair;
                const __half* x0 = g_xBCh + (size_t)(row0 + j) * CONVDIM + h * HEADDIM;
                const __half* x1 = x0 + CONVDIM;
                #pragma unroll
                for (int r = 0; r < 4; r++) {
                    int p = lane + 32 * r;
                    uint32_t cbyte = (uint32_t)pair * 4;
                    uint32_t off = (uint32_t)p * 128 + (cbyte ^ (((uint32_t)p & 7) << 4));
                    *(uint32_t*)((char*)Bs + off) = pack2h(x0[p], x1[p]);
                }
            }
        } else {
            const __half2* crow = (const __half2*)(g_xBCh + (size_t)(row0 + gi) * CONVDIM
                                                   + D_INNER + D_STATE + sj);
            #pragma unroll
            for (int q = 0; q < 4; q++) {
                uint4 hv = *(const uint4*)(crow + q * 4);
                float2 f0 = __half22float2(*(__half2*)&hv.x);
                float2 f1 = __half22float2(*(__half2*)&hv.y);
                float2 f2 = __half22float2(*(__half2*)&hv.z);
                float2 f3 = __half22float2(*(__half2*)&hv.w);
                uint4 u;
                u.x = pack2(f0.x * ei, f0.y * ei);
                u.y = pack2(f1.x * ei, f1.y * ei);
                u.z = pack2(f2.x * ei, f2.y * ei);
                u.w = pack2(f3.x * ei, f3.y * ei);
                uint32_t cbyte = (uint32_t)(sj * 2 + q * 16);
                uint32_t off = (uint32_t)si * 128 + (cbyte ^ (((uint32_t)si & 7) << 4));
                *(uint4*)((char*)As + off) = u;
            }
            int pr = tid >> 1;
            int nc = (tid & 1) * 32;
            const __half* prow = g_psh + psb + (size_t)pr * D_STATE + nc;
            #pragma unroll
            for (int q = 0; q < 2; q++) {
                uint4 u = *(const uint4*)(prow + q * 16);
                uint32_t off = (uint32_t)pr * 128 +
                    (((uint32_t)(nc * 2 + q * 32)) ^ (((uint32_t)pr & 7) << 4));
                *(uint4*)((char*)Bs + off) = u;
                uint4 u2 = *(const uint4*)(prow + q * 16 + 8);
                uint32_t off2 = (uint32_t)pr * 128 +
                    (((uint32_t)(nc * 2 + q * 32 + 16)) ^ (((uint32_t)pr & 7) << 4));
                *(uint4*)((char*)Bs + off2) = u2;
            }
        }
        __syncthreads();
        #pragma unroll
        for (int ks = 0; ks < 4; ks++) {
            uint32_t afr[2][4];
            #pragma unroll
            for (int mt = 0; mt < 2; mt++) {
                uint32_t row = (uint32_t)(a_row + mt * 16);
                uint32_t c = (uint32_t)ks * 32 + a_kb;
                ldsm_x4(afr[mt], as_base + row * 128 + (c ^ ((row & 7) << 4)));
            }
            uint32_t bfr[4][4];
            #pragma unroll
            for (int nh = 0; nh < 4; nh++) {
                uint32_t row = (uint32_t)(b_row + nh * 16);
                uint32_t c = (uint32_t)ks * 32 + b_kb;
                ldsm_x4(bfr[nh], bs_base + row * 128 + (c ^ ((row & 7) << 4)));
            }
            #pragma unroll
            for (int mt = 0; mt < 2; mt++)
                #pragma unroll
                for (int nt = 0; nt < 8; nt++)
                    mma_fp16(acc[mt][nt], afr[mt], &bfr[nt >> 1][(nt & 1) * 2]);
        }
    }

    int g = lane >> 2, tg = lane & 3;
    #pragma unroll
    for (int mt = 0; mt < 2; mt++) {
        int orow = row0 + i_base + wm + mt * 16 + g;
        #pragma unroll
        for (int nt = 0; nt < 8; nt++) {
            int col = h * HEADDIM + wn + nt * 8 + tg * 2;
            *(uint32_t*)(g_yh + (size_t)orow * D_INNER + col) =
                pack2(acc[mt][nt][0], acc[mt][nt][1]);
            *(uint32_t*)(g_yh + (size_t)(orow + 8) * D_INNER + col) =
                pack2(acc[mt][nt][2], acc[mt][nt][3]);
        }
    }
}

// ---------------- reductions ----------------
__device__ __forceinline__ float blockReduceSum256(float v) {
    __shared__ float red[8];
    __shared__ float tot;
    int lane = threadIdx.x & 31, wid = threadIdx.x >> 5;
    #pragma unroll
    for (int o = 16; o; o >>= 1) v += __shfl_down_sync(0xffffffffu, v, o);
    if (lane == 0) red[wid] = v;
    __syncthreads();
    if (wid == 0) {
        float w = (lane < 8) ? red[lane] : 0.f;
        #pragma unroll
        for (int o = 4; o; o >>= 1) w += __shfl_down_sync(0xffffffffu, w, o);
        if (lane == 0) tot = w;
    }
    __syncthreads();
    return tot;
}

// ---------------- K1: l2-normalize weight rows ----------------
__global__ __launch_bounds__(256) void k_normw(const float* __restrict__ W,
                                               __half* __restrict__ Wo, int K, float extra) {
    int r = blockIdx.x;
    const float* wr = W + (size_t)r * K;
    float s2 = 0.f;
    for (int i = threadIdx.x; i < K; i += 256) { float v = wr[i]; s2 += v * v; }
    float totv = blockReduceSum256(s2);
    float sc = extra / fmaxf(sqrtf(totv), 1e-6f);
    for (int i = threadIdx.x; i < K; i += 256)
        Wo[(size_t)r * K + i] = __float2half_rn(wr[i] * sc);
}

// ---------------- K2: layernorm ----------------
__global__ __launch_bounds__(256) void k_layernorm(const float* __restrict__ u,
                                                   const float* __restrict__ w,
                                                   const float* __restrict__ b) {
    int row = blockIdx.x;
    const float* ur = u + (size_t)row * XDIM;
    float v[4]; float s = 0.f, s2 = 0.f;
    #pragma unroll
    for (int k = 0; k < 4; k++) {
        v[k] = ur[threadIdx.x + 256 * k];
        s += v[k]; s2 += v[k] * v[k];
    }
    float sum = blockReduceSum256(s);
    float sumsq = blockReduceSum256(s2);
    float mu = sum * (1.f / XDIM);
    float var = sumsq * (1.f / XDIM) - mu * mu;
    float inv = rsqrtf(var + 1e-5f);
    #pragma unroll
    for (int k = 0; k < 4; k++) {
        int d = threadIdx.x + 256 * k;
        g_lnh[(size_t)row * XDIM + d] = __float2half_rn((v[k] - mu) * inv * w[d] + b[d]);
    }
}

// ---------------- K4: depthwise causal conv + bias + silu ----------------
__global__ __launch_bounds__(128) void k_conv(const float* __restrict__ cw,
                                              const float* __restrict__ cb) {
    int ch = blockIdx.x * 128 + threadIdx.x;
    if (ch >= CONVDIM) return;
    int row0 = blockIdx.y * 8;
    int l0 = row0 & (SEQLEN - 1);
    float w0 = cw[ch * 4 + 0], w1 = cw[ch * 4 + 1];
    float w2 = cw[ch * 4 + 2], w3 = cw[ch * 4 + 3];
    float bias = cb[ch];
    float v[11];
    #pragma unroll
    for (int k = 0; k < 11; k++) {
        int l = l0 - 3 + k;
        v[k] = (l >= 0)
            ? __half2float(g_zxh[(size_t)(row0 - 3 + k) * DPROJP + D_INNER + ch]) : 0.f;
    }
    #pragma unroll
    for (int r = 0; r < 8; r++) {
        float acc = bias + w0 * v[r] + w1 * v[r + 1] + w2 * v[r + 2] + w3 * v[r + 3];
        float s = acc / (1.f + __expf(-acc));
        g_xBCh[(size_t)(row0 + r) * CONVDIM + ch] = __float2half_rn(s);
    }
}

// ---------------- K5: dt softplus + per-chunk cumulative dA ----------------
__global__ __launch_bounds__(256) void k_dtcum(const float* __restrict__ dt_bias,
                                               const float* __restrict__ A_log) {
    int bch = blockIdx.x;
    int h = bch & 15, bc = bch >> 4;
    int t = threadIdx.x;
    int row = bc * CHUNK + t;
    float x = g_dtraw[(size_t)row * NHEADS + h] + dt_bias[h];
    float dtv = (x > 20.f) ? x : log1pf(expf(x));
    g_dt[(size_t)row * NHEADS + h] = dtv;
    float dA = dtv * (-expf(A_log[h]));
    __shared__ float s[256];
    s[t] = dA;
    __syncthreads();
    #pragma unroll
    for (int off = 1; off < 256; off <<= 1) {
        float pv = (t >= off) ? s[t - off] : 0.f;
        __syncthreads();
        s[t] += pv;
        __syncthreads();
    }
    g_cum[(size_t)bch * CHUNK + t] = s[t];
    if (t == 255) g_cdec[bch] = __expf(s[255]);
}

// ---------------- K8: inter-chunk scan (fp32 carry, fp16 ps out) ----------------
__global__ __launch_bounds__(256) void k_scan() {
    int b = blockIdx.x, h = blockIdx.y, z = blockIdx.z;
    int tid = threadIdx.x;
    int e0 = z * 1024 + tid * 4;
    float4 carry = make_float4(0.f, 0.f, 0.f, 0.f);
    for (int c = 0; c < NCPB; c++) {
        int bch = (b * NCPB + c) * NHEADS + h;
        float dec = g_cdec[bch];
        size_t base = (size_t)bch * HEADDIM * D_STATE + e0;
        uint2 pk;
        pk.x = pack2(carry.x, carry.y);
        pk.y = pack2(carry.z, carry.w);
        *(uint2*)(g_psh + base) = pk;
        float4 st = *(const float4*)(g_st + base);
        carry.x = carry.x * dec + st.x;
        carry.y = carry.y * dec + st.y;
        carry.z = carry.z * dec + st.z;
        carry.w = carry.w * dec + st.w;
    }
}

// ---------------- K10: y += D*x, gate, RMS norm ----------------
__global__ __launch_bounds__(256) void k_gate(const float* __restrict__ Dp,
                                              const float* __restrict__ rms_w) {
    int row = blockIdx.x;
    int tid = threadIdx.x;
    float gg[8];
    float s2 = 0.f;
    #pragma unroll
    for (int k = 0; k < 8; k++) {
        int d = tid + 256 * k;
        float xv = __half2float(g_xBCh[(size_t)row * CONVDIM + d]);
        float yv = __half2float(g_yh[(size_t)row * D_INNER + d]);
        float v = yv + Dp[d >> 7] * xv;
        float z = __half2float(g_zxh[(size_t)row * DPROJP + d]);
        float sil = z / (1.f + __expf(-z));
        float g = v * sil;
        gg[k] = g;
        s2 += g * g;
    }
    float tot = blockReduceSum256(s2);
    float sc = rsqrtf(tot * (1.f / D_INNER) + 1e-5f);
    #pragma unroll
    for (int k = 0; k < 8; k++) {
        int d = tid + 256 * k;
        g_gh[(size_t)row * D_INNER + d] = __float2half_rn(gg[k] * sc * rms_w[d]);
    }
}

// ---------------- host launcher ----------------
extern "C" void kernel_launch(void* const* d_in, const int* in_sizes, int n_in,
                              void* d_out, int out_size) {
    const float* u          = (const float*)d_in[0];
    const float* in_proj_w  = (const float*)d_in[1];
    const float* conv_w     = (const float*)d_in[2];
    const float* conv_b     = (const float*)d_in[3];
    const float* dt_bias    = (const float*)d_in[4];
    const float* A_log      = (const float*)d_in[5];
    const float* Dp         = (const float*)d_in[6];
    const float* xnw        = (const float*)d_in[7];
    const float* xnb        = (const float*)d_in[8];
    const float* rms_w      = (const float*)d_in[9];
    const float* out_proj_w = (const float*)d_in[10];
    float* out = (float*)d_out;

    __half *pWinH, *pWoutH, *pLnH, *pGH, *pZxH;
    cudaGetSymbolAddress((void**)&pWinH,  g_Winh);
    cudaGetSymbolAddress((void**)&pWoutH, g_Wouth);
    cudaGetSymbolAddress((void**)&pLnH,   g_lnh);
    cudaGetSymbolAddress((void**)&pGH,    g_gh);
    cudaGetSymbolAddress((void**)&pZxH,   g_zxh);

    static int smem_set = 0;
    if (!smem_set) {
        cudaFuncSetAttribute(gemm_hc, cudaFuncAttributeMaxDynamicSharedMemorySize, GEMM_SMEM);
        cudaFuncSetAttribute(gemm_hc_h, cudaFuncAttributeMaxDynamicSharedMemorySize, GEMM_SMEM);
        smem_set = 1;
    }

    k_normw<<<DPROJ, 256>>>(in_proj_w, pWinH, XDIM, 0.03125f);
    k_normw<<<XDIM, 256>>>(out_proj_w, pWoutH, D_INNER, 1.0f);

    k_layernorm<<<R_TOT, 256>>>(u, xnw, xnb);

    gemm_hc_h<<<dim3(DPROJP / GBN, R_TOT / GBM), 128, GEMM_SMEM>>>(pLnH, pWinH, pZxH, XDIM, DPROJP);

    k_conv<<<dim3((CONVDIM + 127) / 128, R_TOT / 8), 128>>>(conv_w, conv_b);
    k_dtcum<<<NBC * NHEADS, 256>>>(dt_bias, A_log);

    k_scores_h<<<dim3(NBC, 3), 256>>>();
    k_states_h<<<dim3(NBC, NHEADS), 256>>>();
    k_scan<<<dim3(NBATCH, NHEADS, 8), 256>>>();
    k_yfused<<<dim3(NBC, NHEADS, 2), 256>>>();

    k_gate<<<R_TOT, 256>>>(Dp, rms_w);

    gemm_hc<<<dim3(XDIM / GBN, R_TOT / GBM), 128, GEMM_SMEM>>>(pGH, pWoutH, out, D_INNER, XDIM);
}